// round 9
// baseline (speedup 1.0000x reference)
#include <cuda_runtime.h>
#include <cstdint>
#include <cstddef>

#define NA 20000
#define PE 320000
#define FD 128
#define RD 64
#define MD 32

enum { FLAG_SILU = 1, FLAG_RES = 2, FLAG_CUT = 4, FLAG_TF32 = 8 };

// ---------------- scratch (device globals; no runtime alloc) ----------------
__device__ float g_u[PE * 3];
__device__ float g_s[NA * FD];
__device__ float g_vA[NA * 3 * MD];
__device__ float g_vB[NA * 3 * MD];
__device__ int   g_start[NA + 1];
__device__ float g_xinv[(size_t)PE * 192];
__device__ float g_gbuf[(size_t)PE * 64];
__device__ float g_m[(size_t)PE * FD];
__device__ float g_Pei[NA * MD];
__device__ float g_Pej[NA * MD];
__device__ float g_Peqi[NA * FD];
__device__ float g_Peqj[NA * FD];
__device__ float g_Pinvi[NA * FD];
__device__ float g_Pinvj[NA * FD];
__device__ float g_weff[FD * FD];
__device__ float g_hu[NA * FD];
__device__ float g_cew1[192 * 128];
__device__ float g_cew2[128 * 64];
__device__ float g_cw1[192 * 128];
__device__ float g_cw2[128 * 128];

__device__ __forceinline__ float silu_f(float x) { return x / (1.0f + expf(-x)); }

__device__ __forceinline__ float f2tf(float f) {
    uint32_t u;
    asm("cvt.rna.tf32.f32 %0, %1;" : "=r"(u) : "f"(f));
    return __uint_as_float(u);
}

__device__ __forceinline__ void mma_tf32(float c[4], const uint32_t a[4], const uint32_t b[2]) {
    asm volatile(
        "mma.sync.aligned.m16n8k8.row.col.f32.tf32.tf32.f32 "
        "{%0,%1,%2,%3}, {%4,%5,%6,%7}, {%8,%9}, {%0,%1,%2,%3};\n"
        : "+f"(c[0]), "+f"(c[1]), "+f"(c[2]), "+f"(c[3])
        : "r"(a[0]), "r"(a[1]), "r"(a[2]), "r"(a[3]), "r"(b[0]), "r"(b[1]));
}

__device__ __forceinline__ uint32_t smem_u32(const void* p) {
    uint32_t a;
    asm("{ .reg .u64 t; cvta.to.shared.u64 t, %1; cvt.u32.u64 %0, t; }" : "=r"(a) : "l"(p));
    return a;
}

#define CPA16(dst, src) \
    asm volatile("cp.async.cg.shared.global [%0], [%1], 16;" :: "r"(dst), "l"(src))
#define CPA_COMMIT() asm volatile("cp.async.commit_group;" ::: "memory")
#define CPA_WAIT0()  asm volatile("cp.async.wait_group 0;" ::: "memory")

// ================= pipelined tf32 legacy GEMM (node-side, unchanged) =========
template <int BM, int BN>
__device__ __forceinline__ void gemm_body(
    const float* __restrict__ A, int lda,
    const float* __restrict__ W, int ldw,
    float* __restrict__ C, int ldc,
    int Mrows, int K,
    const float* __restrict__ bias,
    const float* __restrict__ Pi,
    const float* __restrict__ Pj, int ldp,
    const int* __restrict__ ii,
    const int* __restrict__ jj,
    const float* __restrict__ cut,
    int flags)
{
    constexpr int BK = 16;
    constexpr int MW = (BN >= 128) ? 2 : (BN == 64 ? 4 : (BM >= 128 ? 8 : 4));
    constexpr int NW = 8 / MW;
    constexpr int WM = BM / MW, WN = BN / NW;
    constexpr int MT = WM / 16, NT = WN / 8;
    constexpr int SAS = BM + 8, SBS = BN + 8;
    constexpr int A4 = (BM * 4) / 256;
    constexpr int B4N = BN / 4;
    constexpr int B4 = (BN * 4 + 255) / 256;
    constexpr bool BG = ((BN * 4) % 256) != 0;

    __shared__ float sA[2][BK][SAS];
    __shared__ float sB[2][BK][SBS];

    const int tid  = threadIdx.x;
    const int lane = tid & 31;
    const int wid  = tid >> 5;
    const int wm   = wid % MW;
    const int wn   = wid / MW;
    const int brow = blockIdx.x * BM;
    const int ar = lane >> 2, ac = lane & 3;

    float acc[MT][NT][4];
#pragma unroll
    for (int i = 0; i < MT; i++)
#pragma unroll
        for (int j = 0; j < NT; j++)
#pragma unroll
            for (int r = 0; r < 4; r++) acc[i][j][r] = 0.0f;

    float4 ra[A4], rb[B4];
    const int nIter = K / BK;

#pragma unroll
    for (int i = 0; i < A4; i++) {
        int q = tid + i * 256, m = q >> 2, kq = q & 3;
        int row = brow + m;
        ra[i] = (row < Mrows) ? *(const float4*)&A[(size_t)row * lda + 4 * kq]
                              : make_float4(0.f, 0.f, 0.f, 0.f);
    }
#pragma unroll
    for (int i = 0; i < B4; i++) {
        int q = tid + i * 256;
        if (!BG || q < BN * 4) {
            int kk = q / B4N, c4 = (q % B4N) * 4;
            rb[i] = *(const float4*)&W[(size_t)kk * ldw + c4];
        }
    }

    for (int it = 0; it < nIter; ++it) {
        int buf = it & 1;
#pragma unroll
        for (int i = 0; i < A4; i++) {
            int q = tid + i * 256, m = q >> 2, kq = q & 3;
            sA[buf][4 * kq + 0][m] = f2tf(ra[i].x);
            sA[buf][4 * kq + 1][m] = f2tf(ra[i].y);
            sA[buf][4 * kq + 2][m] = f2tf(ra[i].z);
            sA[buf][4 * kq + 3][m] = f2tf(ra[i].w);
        }
#pragma unroll
        for (int i = 0; i < B4; i++) {
            int q = tid + i * 256;
            if (!BG || q < BN * 4) {
                int kk = q / B4N, c4 = (q % B4N) * 4;
                float4 v;
                v.x = f2tf(rb[i].x); v.y = f2tf(rb[i].y);
                v.z = f2tf(rb[i].z); v.w = f2tf(rb[i].w);
                *(float4*)&sB[buf][kk][c4] = v;
            }
        }
        __syncthreads();
        if (it + 1 < nIter) {
            int k0 = (it + 1) * BK;
#pragma unroll
            for (int i = 0; i < A4; i++) {
                int q = tid + i * 256, m = q >> 2, kq = q & 3;
                int row = brow + m;
                ra[i] = (row < Mrows) ? *(const float4*)&A[(size_t)row * lda + k0 + 4 * kq]
                                      : make_float4(0.f, 0.f, 0.f, 0.f);
            }
#pragma unroll
            for (int i = 0; i < B4; i++) {
                int q = tid + i * 256;
                if (!BG || q < BN * 4) {
                    int kk = q / B4N, c4 = (q % B4N) * 4;
                    rb[i] = *(const float4*)&W[(size_t)(k0 + kk) * ldw + c4];
                }
            }
        }
#pragma unroll
        for (int kk = 0; kk < BK; kk += 8) {
            uint32_t afr[MT][4], bfr[NT][2];
#pragma unroll
            for (int mt = 0; mt < MT; mt++) {
                int bm = wm * WM + mt * 16;
                afr[mt][0] = __float_as_uint(sA[buf][kk + ac][bm + ar]);
                afr[mt][1] = __float_as_uint(sA[buf][kk + ac][bm + ar + 8]);
                afr[mt][2] = __float_as_uint(sA[buf][kk + ac + 4][bm + ar]);
                afr[mt][3] = __float_as_uint(sA[buf][kk + ac + 4][bm + ar + 8]);
            }
#pragma unroll
            for (int nt = 0; nt < NT; nt++) {
                int bn = wn * WN + nt * 8;
                bfr[nt][0] = __float_as_uint(sB[buf][kk + ac][bn + ar]);
                bfr[nt][1] = __float_as_uint(sB[buf][kk + ac + 4][bn + ar]);
            }
#pragma unroll
            for (int mt = 0; mt < MT; mt++)
#pragma unroll
                for (int nt = 0; nt < NT; nt++)
                    mma_tf32(acc[mt][nt], afr[mt], bfr[nt]);
        }
    }

#pragma unroll
    for (int mt = 0; mt < MT; mt++) {
#pragma unroll
        for (int h = 0; h < 2; h++) {
            int r = wm * WM + mt * 16 + ar + 8 * h;
            int row = brow + r;
            if (row >= Mrows) continue;
            int pii = 0, pjj = 0;
            if (Pi) { pii = ii[row]; pjj = jj[row]; }
            float cv = (flags & FLAG_CUT) ? cut[row] : 1.0f;
#pragma unroll
            for (int nt = 0; nt < NT; nt++) {
                int col = wn * WN + nt * 8 + ac * 2;
#pragma unroll
                for (int e = 0; e < 2; e++) {
                    int c = col + e;
                    float v = acc[mt][nt][2 * h + e];
                    if (bias) v += bias[c];
                    if (Pi) v += Pi[(size_t)pii * ldp + c] + Pj[(size_t)pjj * ldp + c];
                    if (flags & FLAG_SILU) v = silu_f(v);
                    v *= cv;
                    if (flags & FLAG_TF32) v = f2tf(v);
                    float* cp = &C[(size_t)row * ldc + c];
                    if (flags & FLAG_RES) *cp += v; else *cp = v;
                }
            }
        }
    }
}

template <int BM, int BN>
__global__ void __launch_bounds__(256) gemm_single(
    const float* __restrict__ A, int lda, const float* __restrict__ W, int ldw,
    float* __restrict__ C, int ldc, int Mrows, int K,
    const float* __restrict__ bias, const float* __restrict__ Pi,
    const float* __restrict__ Pj, int ldp, const int* __restrict__ ii,
    const int* __restrict__ jj, const float* __restrict__ cut, int flags)
{
    gemm_body<BM, BN>(A, lda, W, ldw, C, ldc, Mrows, K, bias, Pi, Pj, ldp, ii, jj, cut, flags);
}

struct PB4 { const float* W[4]; float* C[4]; };

template <int BM, int BN>
__global__ void __launch_bounds__(256) gemm_batch(
    const float* __restrict__ A, int lda, PB4 p, int ldw, int ldc, int Mrows, int K)
{
    gemm_body<BM, BN>(A, lda, p.W[blockIdx.y], ldw, p.C[blockIdx.y], ldc,
                      Mrows, K, 0, 0, 0, 0, 0, 0, 0, 0);
}

// ================= merged fused edge MLPs (eq + inv share X), 512 threads ====
// One pass over X computes BOTH phase-1 GEMMs (BN=256 = eqW1|invW1 concat),
// then two phase-2 GEMMs. All inputs tf32-pre-rounded -> cp.async staging.
// smem floats: sA 2*2560, sB 2*4224, sHe 16896, sHi 16896 = 47360 -> 185 KB.
#define SMEM_MLP2 ((2 * 2560 + 2 * 4224 + 2 * 128 * 132) * 4)

template <int K1>
__global__ void __launch_bounds__(512, 1) mlp2_fused(
    const float* __restrict__ X, int ldx,
    const int* __restrict__ ii, const int* __restrict__ jj,
    const float* __restrict__ eW1, const float* __restrict__ eb1,
    const float* __restrict__ ePi, const float* __restrict__ ePj,
    const float* __restrict__ eW2, float* __restrict__ eOut,
    const float* __restrict__ iW1, const float* __restrict__ ib1,
    const float* __restrict__ iPi, const float* __restrict__ iPj,
    const float* __restrict__ iW2, const float* __restrict__ ib2,
    const float* __restrict__ cut, float* __restrict__ iOut)
{
    constexpr int SHS = 132;
    extern __shared__ float dsm[];
    float* sA0 = dsm;               // [2][128*20]  row-major A, pad 20
    float* sB0 = dsm + 5120;        // [2][16*264]  phase-1 B (256 cols + 8 pad)
    float* sHe = dsm + 13568;       // [128*132]
    float* sHi = dsm + 30464;       // [128*132]

    const int tid = threadIdx.x, lane = tid & 31, wid = tid >> 5;
    const int brow = blockIdx.x * 128;
    const int ar = lane >> 2, ac = lane & 3;
    const uint32_t sAu = smem_u32(sA0);
    const uint32_t sBu = smem_u32(sB0);

    constexpr int nIt = K1 / 16;

    // ---- stage 0: A chunk 0 + both W1 chunk 0 ----
    {
        int row = tid >> 2, kq = tid & 3;
        CPA16(sAu + (uint32_t)(row * 20 + kq * 4) * 4u,
              &X[(size_t)(brow + row) * ldx + kq * 4]);
#pragma unroll
        for (int i = 0; i < 2; i++) {
            int q = tid + i * 512, kk = q >> 6, c4 = (q & 63) * 4;
            const float* src = (c4 < 128) ? &eW1[(size_t)kk * 128 + c4]
                                          : &iW1[(size_t)kk * 128 + (c4 - 128)];
            CPA16(sBu + (uint32_t)(kk * 264 + c4) * 4u, src);
        }
        CPA_COMMIT();
    }

    // ---- pre-gather both bias planes (covers stage-0 load latency) ----
    for (int q = tid; q < 128 * 32; q += 512) {
        int r = q >> 5, c4 = (q & 31) << 2;
        int row = brow + r;
        int pii = ii[row], pjj = jj[row];
        {
            float4 a = *(const float4*)&ePi[(size_t)pii * 128 + c4];
            float4 b = *(const float4*)&ePj[(size_t)pjj * 128 + c4];
            float4 bb = *(const float4*)&eb1[c4];
            sHe[r * SHS + c4 + 0] = a.x + b.x + bb.x;
            sHe[r * SHS + c4 + 1] = a.y + b.y + bb.y;
            sHe[r * SHS + c4 + 2] = a.z + b.z + bb.z;
            sHe[r * SHS + c4 + 3] = a.w + b.w + bb.w;
        }
        {
            float4 a = *(const float4*)&iPi[(size_t)pii * 128 + c4];
            float4 b = *(const float4*)&iPj[(size_t)pjj * 128 + c4];
            float4 bb = *(const float4*)&ib1[c4];
            sHi[r * SHS + c4 + 0] = a.x + b.x + bb.x;
            sHi[r * SHS + c4 + 1] = a.y + b.y + bb.y;
            sHi[r * SHS + c4 + 2] = a.z + b.z + bb.z;
            sHi[r * SHS + c4 + 3] = a.w + b.w + bb.w;
        }
    }

    // ---- phase 1: both hiddens; 16 warps as 2x8, 64x32 tiles, BN=256 ----
    {
        const int wm = wid & 1, wn = wid >> 1;   // wn 0..7
        float acc[4][4][4];
#pragma unroll
        for (int i = 0; i < 4; i++)
#pragma unroll
            for (int j = 0; j < 4; j++)
#pragma unroll
                for (int r = 0; r < 4; r++) acc[i][j][r] = 0.0f;

        for (int it = 0; it < nIt; ++it) {
            CPA_WAIT0();
            __syncthreads();
            if (it + 1 < nIt) {
                int k0 = (it + 1) * 16;
                uint32_t nb = (uint32_t)((it + 1) & 1);
                int row = tid >> 2, kq = tid & 3;
                CPA16(sAu + (nb * 2560u + (uint32_t)(row * 20 + kq * 4)) * 4u,
                      &X[(size_t)(brow + row) * ldx + k0 + kq * 4]);
#pragma unroll
                for (int i = 0; i < 2; i++) {
                    int q = tid + i * 512, kk = q >> 6, c4 = (q & 63) * 4;
                    const float* src = (c4 < 128)
                        ? &eW1[(size_t)(k0 + kk) * 128 + c4]
                        : &iW1[(size_t)(k0 + kk) * 128 + (c4 - 128)];
                    CPA16(sBu + (nb * 4224u + (uint32_t)(kk * 264 + c4)) * 4u, src);
                }
                CPA_COMMIT();
            }
            const float* cA = sA0 + (it & 1) * 2560;
            const float* cB = sB0 + (it & 1) * 4224;
#pragma unroll
            for (int kk = 0; kk < 16; kk += 8) {
                uint32_t afr[4][4], bfr[4][2];
#pragma unroll
                for (int mt = 0; mt < 4; mt++) {
                    int bm = wm * 64 + mt * 16;
                    afr[mt][0] = __float_as_uint(cA[(bm + ar) * 20 + kk + ac]);
                    afr[mt][1] = __float_as_uint(cA[(bm + ar + 8) * 20 + kk + ac]);
                    afr[mt][2] = __float_as_uint(cA[(bm + ar) * 20 + kk + ac + 4]);
                    afr[mt][3] = __float_as_uint(cA[(bm + ar + 8) * 20 + kk + ac + 4]);
                }
#pragma unroll
                for (int nt = 0; nt < 4; nt++) {
                    int bn = wn * 32 + nt * 8;
                    bfr[nt][0] = __float_as_uint(cB[(kk + ac) * 264 + bn + ar]);
                    bfr[nt][1] = __float_as_uint(cB[(kk + ac + 4) * 264 + bn + ar]);
                }
#pragma unroll
                for (int mt = 0; mt < 4; mt++)
#pragma unroll
                    for (int nt = 0; nt < 4; nt++)
                        mma_tf32(acc[mt][nt], afr[mt], bfr[nt]);
            }
        }
        // epilogue 1: cols 0..127 -> sHe, cols 128..255 -> sHi (uniform per warp)
        float* sH = (wn < 4) ? sHe : sHi;
        const int cbase = (wn < 4) ? wn * 32 : (wn - 4) * 32;
#pragma unroll
        for (int mt = 0; mt < 4; mt++)
#pragma unroll
            for (int h = 0; h < 2; h++) {
                int r = wm * 64 + mt * 16 + ar + 8 * h;
#pragma unroll
                for (int nt = 0; nt < 4; nt++)
#pragma unroll
                    for (int e = 0; e < 2; e++) {
                        int c = cbase + nt * 8 + ac * 2 + e;
                        float v = acc[mt][nt][2 * h + e] + sH[r * SHS + c];
                        sH[r * SHS + c] = f2tf(silu_f(v));
                    }
            }
    }

    // ---- phase 2a: eOut = sHe @ eW2 (N2=64); 16 warps as 4x4 ----
    {
        const int wm2 = wid & 3, wn2 = wid >> 2;   // wn2 0..3
        // stage 0 W2eq into buf 0 (stride 136)
        if (tid < 256) {
            int kk = tid >> 4, c4 = (tid & 15) * 4;
            CPA16(sBu + (uint32_t)(kk * 136 + c4) * 4u, &eW2[(size_t)kk * 64 + c4]);
        }
        CPA_COMMIT();

        float acc2[2][2][4];
#pragma unroll
        for (int i = 0; i < 2; i++)
#pragma unroll
            for (int j = 0; j < 2; j++)
#pragma unroll
                for (int r = 0; r < 4; r++) acc2[i][j][r] = 0.0f;

        for (int it = 0; it < 8; ++it) {
            CPA_WAIT0();
            __syncthreads();   // first pass also publishes epilogue-1 sH writes
            if (it < 7) {
                int k0 = (it + 1) * 16;
                uint32_t nb = (uint32_t)((it + 1) & 1);
                if (tid < 256) {
                    int kk = tid >> 4, c4 = (tid & 15) * 4;
                    CPA16(sBu + (nb * 4224u + (uint32_t)(kk * 136 + c4)) * 4u,
                          &eW2[(size_t)(k0 + kk) * 64 + c4]);
                }
                CPA_COMMIT();
            }
            const float* cB = sB0 + (it & 1) * 4224;
#pragma unroll
            for (int kk = 0; kk < 16; kk += 8) {
                int k = it * 16 + kk;
                uint32_t afr[2][4], bfr[2][2];
#pragma unroll
                for (int mt = 0; mt < 2; mt++) {
                    int bm = wm2 * 32 + mt * 16;
                    afr[mt][0] = __float_as_uint(sHe[(bm + ar) * SHS + k + ac]);
                    afr[mt][1] = __float_as_uint(sHe[(bm + ar + 8) * SHS + k + ac]);
                    afr[mt][2] = __float_as_uint(sHe[(bm + ar) * SHS + k + ac + 4]);
                    afr[mt][3] = __float_as_uint(sHe[(bm + ar + 8) * SHS + k + ac + 4]);
                }
#pragma unroll
                for (int nt = 0; nt < 2; nt++) {
                    int bn = wn2 * 16 + nt * 8;
                    bfr[nt][0] = __float_as_uint(cB[(kk + ac) * 136 + bn + ar]);
                    bfr[nt][1] = __float_as_uint(cB[(kk + ac + 4) * 136 + bn + ar]);
                }
#pragma unroll
                for (int mt = 0; mt < 2; mt++)
#pragma unroll
                    for (int nt = 0; nt < 2; nt++)
                        mma_tf32(acc2[mt][nt], afr[mt], bfr[nt]);
            }
        }
#pragma unroll
        for (int mt = 0; mt < 2; mt++)
#pragma unroll
            for (int h = 0; h < 2; h++) {
                int r = wm2 * 32 + mt * 16 + ar + 8 * h;
                int row = brow + r;
#pragma unroll
                for (int nt = 0; nt < 2; nt++)
#pragma unroll
                    for (int e = 0; e < 2; e++) {
                        int c = wn2 * 16 + nt * 8 + ac * 2 + e;
                        eOut[(size_t)row * 64 + c] = acc2[mt][nt][2 * h + e];
                    }
            }
    }

    // ---- phase 2b: iOut = silu(sHi @ iW2 + b2) * cut (N2=128); warps 2x8 ----
    {
        const int wm2 = wid & 1, wn2 = wid >> 1;   // wn2 0..7
        // stage 0 W2inv into buf 0 (eq's last compute used buf 1)
        {
            int kk = tid >> 5, c4 = (tid & 31) * 4;
            CPA16(sBu + (uint32_t)(kk * 136 + c4) * 4u, &iW2[(size_t)kk * 128 + c4]);
            CPA_COMMIT();
        }

        float acc2[4][2][4];
#pragma unroll
        for (int i = 0; i < 4; i++)
#pragma unroll
            for (int j = 0; j < 2; j++)
#pragma unroll
                for (int r = 0; r < 4; r++) acc2[i][j][r] = 0.0f;

        for (int it = 0; it < 8; ++it) {
            CPA_WAIT0();
            __syncthreads();
            if (it < 7) {
                int k0 = (it + 1) * 16;
                uint32_t nb = (uint32_t)((it + 1) & 1);
                int kk = tid >> 5, c4 = (tid & 31) * 4;
                CPA16(sBu + (nb * 4224u + (uint32_t)(kk * 136 + c4)) * 4u,
                      &iW2[(size_t)(k0 + kk) * 128 + c4]);
                CPA_COMMIT();
            }
            const float* cB = sB0 + (it & 1) * 4224;
#pragma unroll
            for (int kk = 0; kk < 16; kk += 8) {
                int k = it * 16 + kk;
                uint32_t afr[4][4], bfr[2][2];
#pragma unroll
                for (int mt = 0; mt < 4; mt++) {
                    int bm = wm2 * 64 + mt * 16;
                    afr[mt][0] = __float_as_uint(sHi[(bm + ar) * SHS + k + ac]);
                    afr[mt][1] = __float_as_uint(sHi[(bm + ar + 8) * SHS + k + ac]);
                    afr[mt][2] = __float_as_uint(sHi[(bm + ar) * SHS + k + ac + 4]);
                    afr[mt][3] = __float_as_uint(sHi[(bm + ar + 8) * SHS + k + ac + 4]);
                }
#pragma unroll
                for (int nt = 0; nt < 2; nt++) {
                    int bn = wn2 * 16 + nt * 8;
                    bfr[nt][0] = __float_as_uint(cB[(kk + ac) * 136 + bn + ar]);
                    bfr[nt][1] = __float_as_uint(cB[(kk + ac + 4) * 136 + bn + ar]);
                }
#pragma unroll
                for (int mt = 0; mt < 4; mt++)
#pragma unroll
                    for (int nt = 0; nt < 2; nt++)
                        mma_tf32(acc2[mt][nt], afr[mt], bfr[nt]);
            }
        }
#pragma unroll
        for (int mt = 0; mt < 4; mt++)
#pragma unroll
            for (int h = 0; h < 2; h++) {
                int r = wm2 * 64 + mt * 16 + ar + 8 * h;
                int row = brow + r;
                float cv = cut[row];
#pragma unroll
                for (int nt = 0; nt < 2; nt++)
#pragma unroll
                    for (int e = 0; e < 2; e++) {
                        int c = wn2 * 16 + nt * 8 + ac * 2 + e;
                        float v = acc2[mt][nt][2 * h + e] + ib2[c];
                        iOut[(size_t)row * 128 + c] = silu_f(v) * cv;
                    }
            }
    }
}

// ---------------- small kernels ----------------
__global__ void cvt_kernel(const float* __restrict__ src, float* __restrict__ dst, int n) {
    int t = blockIdx.x * blockDim.x + threadIdx.x;
    if (t < n) dst[t] = f2tf(src[t]);
}

__global__ void copy_s_kernel(const float* __restrict__ features) {
    int t = blockIdx.x * blockDim.x + threadIdx.x;
    if (t < NA * FD) g_s[t] = features[t];
}

__global__ void compute_u_kernel(const float* __restrict__ vectors,
                                 const float* __restrict__ distances) {
    int t = blockIdx.x * blockDim.x + threadIdx.x;
    if (t >= PE * 3) return;
    int p = t / 3;
    g_u[t] = vectors[t] / (distances[p] + 0.001f);
}

__global__ void offsets_kernel(const int* __restrict__ idx_i) {
    int n = blockIdx.x * blockDim.x + threadIdx.x;
    if (n > NA) return;
    int lo = 0, hi = PE;
    while (lo < hi) {
        int mid = (lo + hi) >> 1;
        if (idx_i[mid] < n) lo = mid + 1; else hi = mid;
    }
    g_start[n] = lo;
}

__global__ void afeat_kernel(const int* __restrict__ idx_i,
                             const int* __restrict__ idx_j) {
    int t = blockIdx.x * blockDim.x + threadIdx.x;
    if (t >= PE * MD) return;
    int p = t / MD, mm = t % MD;
    const float* vi = g_vA + (size_t)idx_i[p] * 96;
    const float* vj = g_vA + (size_t)idx_j[p] * 96;
    float u0 = g_u[p * 3 + 0], u1 = g_u[p * 3 + 1], u2 = g_u[p * 3 + 2];
    float vi0 = vi[mm], vi1 = vi[32 + mm], vi2 = vi[64 + mm];
    float vj0 = vj[mm], vj1 = vj[32 + mm], vj2 = vj[64 + mm];
    float* x = g_xinv + (size_t)p * 192 + 32;
    x[mm]       = f2tf(u0 * vi0 + u1 * vi1 + u2 * vi2);
    x[32 + mm]  = f2tf(u0 * vj0 + u1 * vj1 + u2 * vj2);
    x[64 + mm]  = f2tf(vi0 * vj0 + vi1 * vj1 + vi2 * vj2);
    x[96 + mm]  = f2tf(vi0 * vi0 + vi1 * vi1 + vi2 * vi2);
    x[128 + mm] = f2tf(vj0 * vj0 + vj1 * vj1 + vj2 * vj2);
}

__global__ void segsum_s_kernel() {
    int n = blockIdx.x, f = threadIdx.x;
    int p0 = g_start[n], p1 = g_start[n + 1];
    float acc = 0.0f;
    for (int p = p0; p < p1; p++) acc += g_m[(size_t)p * FD + f];
    g_s[n * FD + f] += acc;
}

__global__ void segsum_v0_kernel(const float* __restrict__ cut) {
    int n = blockIdx.x, t = threadIdx.x;
    int d = t / 32, mm = t % 32;
    int p0 = g_start[n], p1 = g_start[n + 1];
    float acc = 0.0f;
    for (int p = p0; p < p1; p++)
        acc += g_gbuf[(size_t)p * 64 + mm] * g_u[p * 3 + d] * cut[p];
    g_vA[n * 96 + t] = acc;
}

__global__ void segsum_v1_kernel(const float* __restrict__ cut,
                                 const int* __restrict__ idx_j) {
    int n = blockIdx.x, t = threadIdx.x;
    int d = t / 32, mm = t % 32;
    int p0 = g_start[n], p1 = g_start[n + 1];
    float acc = 0.0f;
    for (int p = p0; p < p1; p++) {
        float vjv = g_vA[(size_t)idx_j[p] * 96 + t];
        acc += (g_gbuf[(size_t)p * 64 + mm] * g_u[p * 3 + d]
              + g_gbuf[(size_t)p * 64 + 32 + mm] * vjv) * cut[p];
    }
    g_vB[n * 96 + t] = g_vA[n * 96 + t] + acc;
}

__global__ void copy_weff_kernel(const float* __restrict__ uW1) {
    int t = blockIdx.x * blockDim.x + threadIdx.x;
    if (t < FD * FD) g_weff[t] = uW1[t];
}

__global__ void copy_out_kernel(float* __restrict__ out) {
    int t = blockIdx.x * blockDim.x + threadIdx.x;
    const int SN = NA * FD, VN = NA * 3 * MD;
    if (t < SN) out[t] = g_s[t];
    else if (t < SN + VN) out[t] = g_vB[t - SN];
}

// ---------------- host ----------------
extern "C" void kernel_launch(void* const* d_in, const int* in_sizes, int n_in,
                              void* d_out, int out_size)
{
    const float* features  = (const float*)d_in[0];
    const float* distances = (const float*)d_in[1];
    const float* vectors   = (const float*)d_in[2];
    const float* cutoffs   = (const float*)d_in[3];
    const float* rbfs      = (const float*)d_in[4];
    const int*   idx_i     = (const int*)d_in[5];
    const int*   idx_j     = (const int*)d_in[6];
    const float* Wrbf      = (const float*)d_in[7];
    const float* Wemb      = (const float*)d_in[8];
    const float* eq0_W1    = (const float*)d_in[9];
    const float* eq0_b1    = (const float*)d_in[10];
    const float* eq0_W2    = (const float*)d_in[11];
    const float* eq1_W1    = (const float*)d_in[12];
    const float* eq1_b1    = (const float*)d_in[13];
    const float* eq1_W2    = (const float*)d_in[14];
    const float* inv_W1    = (const float*)d_in[15];
    const float* inv_b1    = (const float*)d_in[16];
    const float* inv_W2    = (const float*)d_in[17];
    const float* inv_b2    = (const float*)d_in[18];
    const float* upd_W1    = (const float*)d_in[19];
    const float* upd_b1    = (const float*)d_in[20];
    const float* upd_W2    = (const float*)d_in[21];
    const float* upd_b2    = (const float*)d_in[22];
    float* out = (float*)d_out;

    static bool attr_done = false;
    if (!attr_done) {
        cudaFuncSetAttribute(mlp2_fused<32>,
                             cudaFuncAttributeMaxDynamicSharedMemorySize, SMEM_MLP2);
        cudaFuncSetAttribute(mlp2_fused<192>,
                             cudaFuncAttributeMaxDynamicSharedMemorySize, SMEM_MLP2);
        attr_done = true;
    }

    void* tp;
    float *s, *xinv, *gb, *m, *Pei, *Pej, *Peqi, *Peqj, *Pinvi, *Pinvj;
    float *weff, *hu, *cew1, *cew2, *cw1, *cw2;
    cudaGetSymbolAddress(&tp, g_s);      s      = (float*)tp;
    cudaGetSymbolAddress(&tp, g_xinv);   xinv   = (float*)tp;
    cudaGetSymbolAddress(&tp, g_gbuf);   gb     = (float*)tp;
    cudaGetSymbolAddress(&tp, g_m);      m      = (float*)tp;
    cudaGetSymbolAddress(&tp, g_Pei);    Pei    = (float*)tp;
    cudaGetSymbolAddress(&tp, g_Pej);    Pej    = (float*)tp;
    cudaGetSymbolAddress(&tp, g_Peqi);   Peqi   = (float*)tp;
    cudaGetSymbolAddress(&tp, g_Peqj);   Peqj   = (float*)tp;
    cudaGetSymbolAddress(&tp, g_Pinvi);  Pinvi  = (float*)tp;
    cudaGetSymbolAddress(&tp, g_Pinvj);  Pinvj  = (float*)tp;
    cudaGetSymbolAddress(&tp, g_weff);   weff   = (float*)tp;
    cudaGetSymbolAddress(&tp, g_hu);     hu     = (float*)tp;
    cudaGetSymbolAddress(&tp, g_cew1);   cew1   = (float*)tp;
    cudaGetSymbolAddress(&tp, g_cew2);   cew2   = (float*)tp;
    cudaGetSymbolAddress(&tp, g_cw1);    cw1    = (float*)tp;
    cudaGetSymbolAddress(&tp, g_cw2);    cw2    = (float*)tp;

    copy_s_kernel<<<(NA * FD + 255) / 256, 256>>>(features);
    compute_u_kernel<<<(PE * 3 + 255) / 256, 256>>>(vectors, distances);
    offsets_kernel<<<(NA + 1 + 255) / 256, 256>>>(idx_i);

    const int gridN = (NA + 63) / 64;
    const int gridE = PE / 128;

    for (int b = 0; b < 2; b++) {
        const float* eqW1 = b ? eq1_W1 : eq0_W1;
        const float* eqb1 = b ? eq1_b1 : eq0_b1;
        const float* eqW2 = b ? eq1_W2 : eq0_W2;
        const int eq_si = b ? 192 : 32;
        const int eq_sj = b ? 320 : 160;
        const float* iW1 = inv_W1 + (size_t)b * 448 * 128;
        const float* ib1 = inv_b1 + b * 128;
        const float* iW2 = inv_W2 + (size_t)b * 128 * 128;
        const float* ib2 = inv_b2 + b * 128;
        const float* uW1 = upd_W1 + (size_t)b * 256 * 128;
        const float* ub1 = upd_b1 + b * 128;
        const float* uW2 = upd_W2 + (size_t)b * 128 * 128;
        const float* ub2 = upd_b2 + b * 128;
        const int Ke = b ? 192 : 32;   // block 0: a-features are exactly 0

        // node projections, batched
        {
            PB4 p2; p2.W[0] = Wrbf + 64 * 32; p2.W[1] = Wrbf + 192 * 32;
            p2.C[0] = Pei; p2.C[1] = Pej;
            gemm_batch<64, 32><<<dim3(gridN, 2), 256>>>(s, FD, p2, 32, 32, NA, FD);

            PB4 p4;
            p4.W[0] = eqW1 + (size_t)eq_si * 128;
            p4.W[1] = eqW1 + (size_t)eq_sj * 128;
            p4.W[2] = iW1 + 192 * 128;
            p4.W[3] = iW1 + 320 * 128;
            p4.C[0] = Peqi; p4.C[1] = Peqj; p4.C[2] = Pinvi; p4.C[3] = Pinvj;
            gemm_batch<64, 128><<<dim3(gridN, 4), 256>>>(s, FD, p4, 128, 128, NA, FD);
        }

        // pre-round edge-MLP weights to tf32 (enables cp.async pure-copy staging)
        cvt_kernel<<<(Ke * 128 + 255) / 256, 256>>>(eqW1, cew1, Ke * 128);
        cvt_kernel<<<(128 * 64 + 255) / 256, 256>>>(eqW2, cew2, 128 * 64);
        cvt_kernel<<<(Ke * 128 + 255) / 256, 256>>>(iW1, cw1, Ke * 128);
        cvt_kernel<<<(128 * 128 + 255) / 256, 256>>>(iW2, cw2, 128 * 128);

        // e = rbfs @ Wrbf[0:64] + Pei[i] + Pej[j]  -> xinv cols 0..31 (tf32-rounded)
        gemm_single<128, 32><<<gridE, 256>>>(rbfs, RD, Wrbf, 32, xinv, 192, PE, RD,
                                             0, Pei, Pej, 32, idx_i, idx_j, 0, FLAG_TF32);

        if (b == 1)
            afeat_kernel<<<(PE * MD + 255) / 256, 256>>>(idx_i, idx_j);

        // merged fused edge MLPs (one pass over X)
        if (b == 0)
            mlp2_fused<32><<<gridE, 512, SMEM_MLP2>>>(
                xinv, 192, idx_i, idx_j,
                cew1, eqb1, Peqi, Peqj, cew2, gb,
                cw1, ib1, Pinvi, Pinvj, cw2, ib2, cutoffs, m);
        else
            mlp2_fused<192><<<gridE, 512, SMEM_MLP2>>>(
                xinv, 192, idx_i, idx_j,
                cew1, eqb1, Peqi, Peqj, cew2, gb,
                cw1, ib1, Pinvi, Pinvj, cw2, ib2, cutoffs, m);

        if (b == 0) segsum_v0_kernel<<<NA, 96>>>(cutoffs);
        else        segsum_v1_kernel<<<NA, 96>>>(cutoffs, idx_j);
        segsum_s_kernel<<<NA, FD>>>();

        // node update: Weff = uW1a + Wemb @ uW1b ; s += silu(silu(s@Weff+b1)@uW2+b2)
        copy_weff_kernel<<<(FD * FD + 255) / 256, 256>>>(uW1);
        gemm_single<64, 128><<<2, 256>>>(Wemb, 128, uW1 + 128 * 128, 128, weff, 128,
                                         128, 128, 0, 0, 0, 0, 0, 0, 0, FLAG_RES);
        gemm_single<64, 128><<<gridN, 256>>>(s, FD, weff, 128, hu, 128, NA, FD,
                                             ub1, 0, 0, 0, 0, 0, 0, FLAG_SILU);
        gemm_single<64, 128><<<gridN, 256>>>(hu, FD, uW2, 128, s, 128, NA, FD,
                                             ub2, 0, 0, 0, 0, 0, 0, FLAG_SILU | FLAG_RES);
    }

    int total = NA * FD + NA * 3 * MD;
    copy_out_kernel<<<(total + 255) / 256, 256>>>(out);
}

// round 14
// speedup vs baseline: 1.0691x; 1.0691x over previous
#include <cuda_runtime.h>
#include <cuda_fp16.h>
#include <cstdint>
#include <cstddef>

#define NA 20000
#define PE 320000
#define FD 128
#define RD 64
#define MD 32

enum { FLAG_SILU = 1, FLAG_RES = 2, FLAG_CUT = 4, FLAG_TF32 = 8 };

// ---------------- scratch (device globals; no runtime alloc) ----------------
__device__ float g_u[PE * 3];
__device__ float g_s[NA * FD];
__device__ float g_vA[NA * 3 * MD];
__device__ float g_vB[NA * 3 * MD];
__device__ int   g_start[NA + 1];
__device__ float g_xinv[(size_t)PE * 192];
__device__ float g_gbuf[(size_t)PE * 64];
__device__ float g_m[(size_t)PE * FD];
__device__ float g_Pei[NA * MD];
__device__ float g_Pej[NA * MD];
__device__ float g_Peqi[NA * FD];
__device__ float g_Peqj[NA * FD];
__device__ float g_Pinvi[NA * FD];
__device__ float g_Pinvj[NA * FD];
__device__ float g_weff[FD * FD];
__device__ float g_hu[NA * FD];
// block-1 tf32 pre-rounded weights
__device__ float g_cew1[192 * 128];
__device__ float g_cew2[128 * 64];
__device__ float g_cw1[192 * 128];
__device__ float g_cw2[128 * 128];
// block-0 fp16 data (16B-aligned; e-range is bounded -> fp16 safe)
__device__ __align__(16) __half g_xh[(size_t)PE * 32];
__device__ __align__(16) __half g_tew1[128 * 32];
__device__ __align__(16) __half g_tew2[64 * 128];
__device__ __align__(16) __half g_tiw1[128 * 32];
__device__ __align__(16) __half g_tiw2[128 * 128];

__device__ __forceinline__ float silu_f(float x) { return x / (1.0f + expf(-x)); }

__device__ __forceinline__ float f2tf(float f) {
    uint32_t u;
    asm("cvt.rna.tf32.f32 %0, %1;" : "=r"(u) : "f"(f));
    return __uint_as_float(u);
}

union U32H2 { uint32_t u; __half2 h; };
__device__ __forceinline__ uint32_t hld(const __half* p) {
    U32H2 x; x.h = *(const __half2*)p; return x.u;
}

__device__ __forceinline__ void mma_tf32(float c[4], const uint32_t a[4], const uint32_t b[2]) {
    asm volatile(
        "mma.sync.aligned.m16n8k8.row.col.f32.tf32.tf32.f32 "
        "{%0,%1,%2,%3}, {%4,%5,%6,%7}, {%8,%9}, {%0,%1,%2,%3};\n"
        : "+f"(c[0]), "+f"(c[1]), "+f"(c[2]), "+f"(c[3])
        : "r"(a[0]), "r"(a[1]), "r"(a[2]), "r"(a[3]), "r"(b[0]), "r"(b[1]));
}

__device__ __forceinline__ void mma_f16(float c[4], const uint32_t a[4], const uint32_t b[2]) {
    asm volatile(
        "mma.sync.aligned.m16n8k16.row.col.f32.f16.f16.f32 "
        "{%0,%1,%2,%3}, {%4,%5,%6,%7}, {%8,%9}, {%0,%1,%2,%3};\n"
        : "+f"(c[0]), "+f"(c[1]), "+f"(c[2]), "+f"(c[3])
        : "r"(a[0]), "r"(a[1]), "r"(a[2]), "r"(a[3]), "r"(b[0]), "r"(b[1]));
}

__device__ __forceinline__ uint32_t smem_u32(const void* p) {
    uint32_t a;
    asm("{ .reg .u64 t; cvta.to.shared.u64 t, %1; cvt.u32.u64 %0, t; }" : "=r"(a) : "l"(p));
    return a;
}

#define CPA16(dst, src) \
    asm volatile("cp.async.cg.shared.global [%0], [%1], 16;" :: "r"(dst), "l"(src))
#define CPA_COMMIT() asm volatile("cp.async.commit_group;" ::: "memory")
#define CPA_WAIT0()  asm volatile("cp.async.wait_group 0;" ::: "memory")

// ================= pipelined tf32 legacy GEMM (round 8, unchanged) ===========
template <int BM, int BN>
__device__ __forceinline__ void gemm_body(
    const float* __restrict__ A, int lda,
    const float* __restrict__ W, int ldw,
    float* __restrict__ C, int ldc,
    int Mrows, int K,
    const float* __restrict__ bias,
    const float* __restrict__ Pi,
    const float* __restrict__ Pj, int ldp,
    const int* __restrict__ ii,
    const int* __restrict__ jj,
    const float* __restrict__ cut,
    int flags)
{
    constexpr int BK = 16;
    constexpr int MW = (BN >= 128) ? 2 : (BN == 64 ? 4 : (BM >= 128 ? 8 : 4));
    constexpr int NW = 8 / MW;
    constexpr int WM = BM / MW, WN = BN / NW;
    constexpr int MT = WM / 16, NT = WN / 8;
    constexpr int SAS = BM + 8, SBS = BN + 8;
    constexpr int A4 = (BM * 4) / 256;
    constexpr int B4N = BN / 4;
    constexpr int B4 = (BN * 4 + 255) / 256;
    constexpr bool BG = ((BN * 4) % 256) != 0;

    __shared__ float sA[2][BK][SAS];
    __shared__ float sB[2][BK][SBS];

    const int tid  = threadIdx.x;
    const int lane = tid & 31;
    const int wid  = tid >> 5;
    const int wm   = wid % MW;
    const int wn   = wid / MW;
    const int brow = blockIdx.x * BM;
    const int ar = lane >> 2, ac = lane & 3;

    float acc[MT][NT][4];
#pragma unroll
    for (int i = 0; i < MT; i++)
#pragma unroll
        for (int j = 0; j < NT; j++)
#pragma unroll
            for (int r = 0; r < 4; r++) acc[i][j][r] = 0.0f;

    float4 ra[A4], rb[B4];
    const int nIter = K / BK;

#pragma unroll
    for (int i = 0; i < A4; i++) {
        int q = tid + i * 256, m = q >> 2, kq = q & 3;
        int row = brow + m;
        ra[i] = (row < Mrows) ? *(const float4*)&A[(size_t)row * lda + 4 * kq]
                              : make_float4(0.f, 0.f, 0.f, 0.f);
    }
#pragma unroll
    for (int i = 0; i < B4; i++) {
        int q = tid + i * 256;
        if (!BG || q < BN * 4) {
            int kk = q / B4N, c4 = (q % B4N) * 4;
            rb[i] = *(const float4*)&W[(size_t)kk * ldw + c4];
        }
    }

    for (int it = 0; it < nIter; ++it) {
        int buf = it & 1;
#pragma unroll
        for (int i = 0; i < A4; i++) {
            int q = tid + i * 256, m = q >> 2, kq = q & 3;
            sA[buf][4 * kq + 0][m] = f2tf(ra[i].x);
            sA[buf][4 * kq + 1][m] = f2tf(ra[i].y);
            sA[buf][4 * kq + 2][m] = f2tf(ra[i].z);
            sA[buf][4 * kq + 3][m] = f2tf(ra[i].w);
        }
#pragma unroll
        for (int i = 0; i < B4; i++) {
            int q = tid + i * 256;
            if (!BG || q < BN * 4) {
                int kk = q / B4N, c4 = (q % B4N) * 4;
                float4 v;
                v.x = f2tf(rb[i].x); v.y = f2tf(rb[i].y);
                v.z = f2tf(rb[i].z); v.w = f2tf(rb[i].w);
                *(float4*)&sB[buf][kk][c4] = v;
            }
        }
        __syncthreads();
        if (it + 1 < nIter) {
            int k0 = (it + 1) * BK;
#pragma unroll
            for (int i = 0; i < A4; i++) {
                int q = tid + i * 256, m = q >> 2, kq = q & 3;
                int row = brow + m;
                ra[i] = (row < Mrows) ? *(const float4*)&A[(size_t)row * lda + k0 + 4 * kq]
                                      : make_float4(0.f, 0.f, 0.f, 0.f);
            }
#pragma unroll
            for (int i = 0; i < B4; i++) {
                int q = tid + i * 256;
                if (!BG || q < BN * 4) {
                    int kk = q / B4N, c4 = (q % B4N) * 4;
                    rb[i] = *(const float4*)&W[(size_t)(k0 + kk) * ldw + c4];
                }
            }
        }
#pragma unroll
        for (int kk = 0; kk < BK; kk += 8) {
            uint32_t afr[MT][4], bfr[NT][2];
#pragma unroll
            for (int mt = 0; mt < MT; mt++) {
                int bm = wm * WM + mt * 16;
                afr[mt][0] = __float_as_uint(sA[buf][kk + ac][bm + ar]);
                afr[mt][1] = __float_as_uint(sA[buf][kk + ac][bm + ar + 8]);
                afr[mt][2] = __float_as_uint(sA[buf][kk + ac + 4][bm + ar]);
                afr[mt][3] = __float_as_uint(sA[buf][kk + ac + 4][bm + ar + 8]);
            }
#pragma unroll
            for (int nt = 0; nt < NT; nt++) {
                int bn = wn * WN + nt * 8;
                bfr[nt][0] = __float_as_uint(sB[buf][kk + ac][bn + ar]);
                bfr[nt][1] = __float_as_uint(sB[buf][kk + ac + 4][bn + ar]);
            }
#pragma unroll
            for (int mt = 0; mt < MT; mt++)
#pragma unroll
                for (int nt = 0; nt < NT; nt++)
                    mma_tf32(acc[mt][nt], afr[mt], bfr[nt]);
        }
    }

#pragma unroll
    for (int mt = 0; mt < MT; mt++) {
#pragma unroll
        for (int h = 0; h < 2; h++) {
            int r = wm * WM + mt * 16 + ar + 8 * h;
            int row = brow + r;
            if (row >= Mrows) continue;
            int pii = 0, pjj = 0;
            if (Pi) { pii = ii[row]; pjj = jj[row]; }
            float cv = (flags & FLAG_CUT) ? cut[row] : 1.0f;
#pragma unroll
            for (int nt = 0; nt < NT; nt++) {
                int col = wn * WN + nt * 8 + ac * 2;
#pragma unroll
                for (int e = 0; e < 2; e++) {
                    int c = col + e;
                    float v = acc[mt][nt][2 * h + e];
                    if (bias) v += bias[c];
                    if (Pi) v += Pi[(size_t)pii * ldp + c] + Pj[(size_t)pjj * ldp + c];
                    if (flags & FLAG_SILU) v = silu_f(v);
                    v *= cv;
                    if (flags & FLAG_TF32) v = f2tf(v);
                    float* cp = &C[(size_t)row * ldc + c];
                    if (flags & FLAG_RES) *cp += v; else *cp = v;
                }
            }
        }
    }
}

template <int BM, int BN>
__global__ void __launch_bounds__(256) gemm_single(
    const float* __restrict__ A, int lda, const float* __restrict__ W, int ldw,
    float* __restrict__ C, int ldc, int Mrows, int K,
    const float* __restrict__ bias, const float* __restrict__ Pi,
    const float* __restrict__ Pj, int ldp, const int* __restrict__ ii,
    const int* __restrict__ jj, const float* __restrict__ cut, int flags)
{
    gemm_body<BM, BN>(A, lda, W, ldw, C, ldc, Mrows, K, bias, Pi, Pj, ldp, ii, jj, cut, flags);
}

struct PB4 { const float* W[4]; float* C[4]; };

template <int BM, int BN>
__global__ void __launch_bounds__(256) gemm_batch(
    const float* __restrict__ A, int lda, PB4 p, int ldw, int ldc, int Mrows, int K)
{
    gemm_body<BM, BN>(A, lda, p.W[blockIdx.y], ldw, p.C[blockIdx.y], ldc,
                      Mrows, K, 0, 0, 0, 0, 0, 0, 0, 0);
}

// ================= block-1 MLPs: round-8 tf32 fused kernel ===================
#define SMEM_MLP ((2 * 2560 + 2 * 2176 + 128 * 132) * 4)

template <int N2, int FLAGS2>
__global__ void __launch_bounds__(256, 2) mlp_fused(
    const float* __restrict__ X, int ldx, int K1,
    const float* __restrict__ W1,
    const float* __restrict__ b1v,
    const float* __restrict__ Pi, const float* __restrict__ Pj,
    const int* __restrict__ ii, const int* __restrict__ jj,
    const float* __restrict__ W2,
    const float* __restrict__ b2v,
    const float* __restrict__ cut,
    float* __restrict__ C, int ldc)
{
    constexpr int SHS = 132;
    extern __shared__ float dsm[];
    float* sA0 = dsm;
    float* sB0 = dsm + 5120;
    float* sH  = dsm + 9472;

    const int tid = threadIdx.x, lane = tid & 31, wid = tid >> 5;
    const int brow = blockIdx.x * 128;
    const int ar = lane >> 2, ac = lane & 3;
    const uint32_t sAu = smem_u32(sA0);
    const uint32_t sBu = smem_u32(sB0);

    const int nIt = K1 / 16;

#pragma unroll
    for (int i = 0; i < 2; i++) {
        int q = tid + i * 256, row = q >> 2, kq = q & 3;
        CPA16(sAu + (uint32_t)(row * 20 + kq * 4) * 4u,
              &X[(size_t)(brow + row) * ldx + kq * 4]);
    }
#pragma unroll
    for (int i = 0; i < 2; i++) {
        int q = tid + i * 256, kk = q >> 5, c4 = (q & 31) * 4;
        CPA16(sBu + (uint32_t)(kk * 136 + c4) * 4u,
              &W1[(size_t)kk * 128 + c4]);
    }
    CPA_COMMIT();

    for (int q = tid; q < 128 * 32; q += 256) {
        int r = q >> 5, c4 = (q & 31) << 2;
        int row = brow + r;
        int pii = ii[row], pjj = jj[row];
        float4 a = *(const float4*)&Pi[(size_t)pii * 128 + c4];
        float4 b = *(const float4*)&Pj[(size_t)pjj * 128 + c4];
        float4 bb = *(const float4*)&b1v[c4];
        sH[r * SHS + c4 + 0] = a.x + b.x + bb.x;
        sH[r * SHS + c4 + 1] = a.y + b.y + bb.y;
        sH[r * SHS + c4 + 2] = a.z + b.z + bb.z;
        sH[r * SHS + c4 + 3] = a.w + b.w + bb.w;
    }

    const int wm = wid & 1, wn = wid >> 1;
    {
        float acc[4][4][4];
#pragma unroll
        for (int i = 0; i < 4; i++)
#pragma unroll
            for (int j = 0; j < 4; j++)
#pragma unroll
                for (int r = 0; r < 4; r++) acc[i][j][r] = 0.0f;

        for (int it = 0; it < nIt; ++it) {
            CPA_WAIT0();
            __syncthreads();
            if (it + 1 < nIt) {
                int k0 = (it + 1) * 16;
                uint32_t nb = (uint32_t)((it + 1) & 1);
#pragma unroll
                for (int i = 0; i < 2; i++) {
                    int q = tid + i * 256, row = q >> 2, kq = q & 3;
                    CPA16(sAu + (nb * 2560u + (uint32_t)(row * 20 + kq * 4)) * 4u,
                          &X[(size_t)(brow + row) * ldx + k0 + kq * 4]);
                }
#pragma unroll
                for (int i = 0; i < 2; i++) {
                    int q = tid + i * 256, kk = q >> 5, c4 = (q & 31) * 4;
                    CPA16(sBu + (nb * 2176u + (uint32_t)(kk * 136 + c4)) * 4u,
                          &W1[(size_t)(k0 + kk) * 128 + c4]);
                }
                CPA_COMMIT();
            }
            const float* cA = sA0 + (it & 1) * 2560;
            const float* cB = sB0 + (it & 1) * 2176;
#pragma unroll
            for (int kk = 0; kk < 16; kk += 8) {
                uint32_t afr[4][4], bfr[4][2];
#pragma unroll
                for (int mt = 0; mt < 4; mt++) {
                    int bm = wm * 64 + mt * 16;
                    afr[mt][0] = __float_as_uint(cA[(bm + ar) * 20 + kk + ac]);
                    afr[mt][1] = __float_as_uint(cA[(bm + ar + 8) * 20 + kk + ac]);
                    afr[mt][2] = __float_as_uint(cA[(bm + ar) * 20 + kk + ac + 4]);
                    afr[mt][3] = __float_as_uint(cA[(bm + ar + 8) * 20 + kk + ac + 4]);
                }
#pragma unroll
                for (int nt = 0; nt < 4; nt++) {
                    int bn = wn * 32 + nt * 8;
                    bfr[nt][0] = __float_as_uint(cB[(kk + ac) * 136 + bn + ar]);
                    bfr[nt][1] = __float_as_uint(cB[(kk + ac + 4) * 136 + bn + ar]);
                }
#pragma unroll
                for (int mt = 0; mt < 4; mt++)
#pragma unroll
                    for (int nt = 0; nt < 4; nt++)
                        mma_tf32(acc[mt][nt], afr[mt], bfr[nt]);
            }
        }
#pragma unroll
        for (int mt = 0; mt < 4; mt++)
#pragma unroll
            for (int h = 0; h < 2; h++) {
                int r = wm * 64 + mt * 16 + ar + 8 * h;
#pragma unroll
                for (int nt = 0; nt < 4; nt++)
#pragma unroll
                    for (int e = 0; e < 2; e++) {
                        int c = wn * 32 + nt * 8 + ac * 2 + e;
                        float v = acc[mt][nt][2 * h + e] + sH[r * SHS + c];
                        sH[r * SHS + c] = f2tf(silu_f(v));
                    }
            }
    }

    {
        constexpr int MW2 = (N2 == 128) ? 2 : 4;
        constexpr int NW2 = 8 / MW2;
        constexpr int WM2 = 128 / MW2, WN2 = N2 / NW2;
        constexpr int MT2 = WM2 / 16, NT2 = WN2 / 8;
        constexpr int B4N = N2 / 4;
        constexpr int ITB = (16 * B4N) / 256;
        const int wm2 = wid % MW2, wn2 = wid / MW2;

#pragma unroll
        for (int i = 0; i < ITB; i++) {
            int q = tid + i * 256, kk = q / B4N, c4 = (q % B4N) * 4;
            CPA16(sBu + (uint32_t)(kk * 136 + c4) * 4u,
                  &W2[(size_t)kk * N2 + c4]);
        }
        CPA_COMMIT();

        float acc2[MT2][NT2][4];
#pragma unroll
        for (int i = 0; i < MT2; i++)
#pragma unroll
            for (int j = 0; j < NT2; j++)
#pragma unroll
                for (int r = 0; r < 4; r++) acc2[i][j][r] = 0.0f;

        for (int it = 0; it < 8; ++it) {
            CPA_WAIT0();
            __syncthreads();
            if (it < 7) {
                int k0 = (it + 1) * 16;
                uint32_t nb = (uint32_t)((it + 1) & 1);
#pragma unroll
                for (int i = 0; i < ITB; i++) {
                    int q = tid + i * 256, kk = q / B4N, c4 = (q % B4N) * 4;
                    CPA16(sBu + (nb * 2176u + (uint32_t)(kk * 136 + c4)) * 4u,
                          &W2[(size_t)(k0 + kk) * N2 + c4]);
                }
                CPA_COMMIT();
            }
            const float* cB = sB0 + (it & 1) * 2176;
#pragma unroll
            for (int kk = 0; kk < 16; kk += 8) {
                int k = it * 16 + kk;
                uint32_t afr[MT2][4], bfr[NT2][2];
#pragma unroll
                for (int mt = 0; mt < MT2; mt++) {
                    int bm = wm2 * WM2 + mt * 16;
                    afr[mt][0] = __float_as_uint(sH[(bm + ar) * SHS + k + ac]);
                    afr[mt][1] = __float_as_uint(sH[(bm + ar + 8) * SHS + k + ac]);
                    afr[mt][2] = __float_as_uint(sH[(bm + ar) * SHS + k + ac + 4]);
                    afr[mt][3] = __float_as_uint(sH[(bm + ar + 8) * SHS + k + ac + 4]);
                }
#pragma unroll
                for (int nt = 0; nt < NT2; nt++) {
                    int bn = wn2 * WN2 + nt * 8;
                    bfr[nt][0] = __float_as_uint(cB[(kk + ac) * 136 + bn + ar]);
                    bfr[nt][1] = __float_as_uint(cB[(kk + ac + 4) * 136 + bn + ar]);
                }
#pragma unroll
                for (int mt = 0; mt < MT2; mt++)
#pragma unroll
                    for (int nt = 0; nt < NT2; nt++)
                        mma_tf32(acc2[mt][nt], afr[mt], bfr[nt]);
            }
        }
#pragma unroll
        for (int mt = 0; mt < MT2; mt++)
#pragma unroll
            for (int h = 0; h < 2; h++) {
                int r = wm2 * WM2 + mt * 16 + ar + 8 * h;
                int row = brow + r;
                float cv = (FLAGS2 & FLAG_CUT) ? cut[row] : 1.0f;
#pragma unroll
                for (int nt = 0; nt < NT2; nt++)
#pragma unroll
                    for (int e = 0; e < 2; e++) {
                        int c = wn2 * WN2 + nt * 8 + ac * 2 + e;
                        float v = acc2[mt][nt][2 * h + e];
                        if (b2v) v += b2v[c];
                        if (FLAGS2 & FLAG_SILU) v = silu_f(v);
                        v *= cv;
                        C[(size_t)row * ldc + c] = v;
                    }
            }
    }
}

// ================= block-0 MLPs: fp16 tensor cores (K1=32, range-safe) =======
// X [PE][32] fp16 compact; W1T [128][32], W2T [N2][128] fp16 n-major.
#define SMEM_EQ (20480 + 20480 + 34816)

template <int N2, int FLAGS2>
__global__ void __launch_bounds__(256, 2) mlp_h0(
    const __half* __restrict__ X,
    const __half* __restrict__ W1T,
    const float* __restrict__ b1v,
    const float* __restrict__ Pi, const float* __restrict__ Pj,
    const int* __restrict__ ii, const int* __restrict__ jj,
    const __half* __restrict__ W2T,
    const float* __restrict__ b2v,
    const float* __restrict__ cut,
    float* __restrict__ C, int ldc)
{
    extern __shared__ char dsmc[];
    __half* sA0 = (__half*)dsmc;
    __half* sB0 = (__half*)(dsmc + 20480);
    __half* sHb = (__half*)(dsmc + 40960);

    const int tid = threadIdx.x, lane = tid & 31, wid = tid >> 5;
    const int brow = blockIdx.x * 128;
    const int ar = lane >> 2, ac = lane & 3;
    const uint32_t sBu = smem_u32(sB0);

    const int wm = wid & 1, wn = wid >> 1;

    // phase 1 (single K-chunk of 32): plain staged (validated round 12/13)
    {
        float acc[4][4][4];
#pragma unroll
        for (int i = 0; i < 4; i++)
#pragma unroll
            for (int j = 0; j < 4; j++)
#pragma unroll
                for (int r = 0; r < 4; r++) acc[i][j][r] = 0.0f;

        uint4 ra[2], rb[2];
#pragma unroll
        for (int i = 0; i < 2; i++) {
            int q = tid + i * 256, row = q >> 2, seg = q & 3;
            ra[i] = *(const uint4*)&X[(size_t)(brow + row) * 32 + seg * 8];
        }
#pragma unroll
        for (int i = 0; i < 2; i++) {
            int q = tid + i * 256, n = q >> 2, seg = q & 3;
            rb[i] = *(const uint4*)&W1T[(size_t)n * 32 + seg * 8];
        }
#pragma unroll
        for (int i = 0; i < 2; i++) {
            int q = tid + i * 256, row = q >> 2, seg = q & 3;
            *(uint4*)&sA0[row * 40 + seg * 8] = ra[i];
        }
#pragma unroll
        for (int i = 0; i < 2; i++) {
            int q = tid + i * 256, n = q >> 2, seg = q & 3;
            *(uint4*)&sB0[n * 40 + seg * 8] = rb[i];
        }
        __syncthreads();

#pragma unroll
        for (int kk = 0; kk < 32; kk += 16) {
            uint32_t afr[4][4], bfr[4][2];
#pragma unroll
            for (int mt = 0; mt < 4; mt++) {
                int bm = wm * 64 + mt * 16;
                afr[mt][0] = hld(&sA0[(bm + ar) * 40 + kk + ac * 2]);
                afr[mt][1] = hld(&sA0[(bm + ar + 8) * 40 + kk + ac * 2]);
                afr[mt][2] = hld(&sA0[(bm + ar) * 40 + kk + ac * 2 + 8]);
                afr[mt][3] = hld(&sA0[(bm + ar + 8) * 40 + kk + ac * 2 + 8]);
            }
#pragma unroll
            for (int nt = 0; nt < 4; nt++) {
                int bn = wn * 32 + nt * 8;
                bfr[nt][0] = hld(&sB0[(bn + ar) * 40 + kk + ac * 2]);
                bfr[nt][1] = hld(&sB0[(bn + ar) * 40 + kk + ac * 2 + 8]);
            }
#pragma unroll
            for (int mt = 0; mt < 4; mt++)
#pragma unroll
                for (int nt = 0; nt < 4; nt++)
                    mma_f16(acc[mt][nt], afr[mt], bfr[nt]);
        }

        // epilogue 1: sHb = half(silu(acc + Pi[ii] + Pj[jj] + b1))
#pragma unroll
        for (int mt = 0; mt < 4; mt++)
#pragma unroll
            for (int h = 0; h < 2; h++) {
                int r = wm * 64 + mt * 16 + ar + 8 * h;
                int row = brow + r;
                int pii = ii[row], pjj = jj[row];
                const float* pi = Pi + (size_t)pii * 128;
                const float* pj = Pj + (size_t)pjj * 128;
#pragma unroll
                for (int nt = 0; nt < 4; nt++) {
                    int c = wn * 32 + nt * 8 + ac * 2;
                    float2 a = *(const float2*)&pi[c];
                    float2 b = *(const float2*)&pj[c];
                    float2 bb = *(const float2*)&b1v[c];
                    float v0 = silu_f(acc[mt][nt][2 * h + 0] + a.x + b.x + bb.x);
                    float v1 = silu_f(acc[mt][nt][2 * h + 1] + a.y + b.y + bb.y);
                    *(__half2*)&sHb[r * 136 + c] = __floats2half2_rn(v0, v1);
                }
            }
    }
    __syncthreads();

    // phase 2: out = epi2(hidden @ W2), K=128, cp.async W2 pipeline (validated)
    {
        constexpr int MW2 = (N2 == 128) ? 2 : 4;
        constexpr int WM2 = 128 / MW2;
        constexpr int WN2 = (N2 == 128) ? 32 : 32;   // both: 8 warps cover N2
        constexpr int MT2 = WM2 / 16;
        constexpr int NT2 = WN2 / 8;                 // 4
        constexpr int NCH = N2 / 64;                 // 16B chunks per thread
        const int wm2 = wid % MW2, wn2 = wid / MW2;

#pragma unroll
        for (int i = 0; i < NCH; i++) {
            int q = tid + i * 256, n = q >> 2, seg = q & 3;
            CPA16(sBu + (uint32_t)(n * 80 + seg * 16),
                  &W2T[(size_t)n * 128 + seg * 8]);
        }
        CPA_COMMIT();

        float acc2[MT2][NT2][4];
#pragma unroll
        for (int i = 0; i < MT2; i++)
#pragma unroll
            for (int j = 0; j < NT2; j++)
#pragma unroll
                for (int r = 0; r < 4; r++) acc2[i][j][r] = 0.0f;

        for (int it = 0; it < 4; ++it) {
            CPA_WAIT0();
            __syncthreads();
            if (it < 3) {
                int k0 = (it + 1) * 32;
                uint32_t nb = (uint32_t)((it + 1) & 1);
#pragma unroll
                for (int i = 0; i < NCH; i++) {
                    int q = tid + i * 256, n = q >> 2, seg = q & 3;
                    CPA16(sBu + nb * 10240u + (uint32_t)(n * 80 + seg * 16),
                          &W2T[(size_t)n * 128 + k0 + seg * 8]);
                }
                CPA_COMMIT();
            }
            const __half* cB = sB0 + (it & 1) * 5120;
#pragma unroll
            for (int kk = 0; kk < 32; kk += 16) {
                int k = it * 32 + kk;
                uint32_t afr[MT2][4], bfr[NT2][2];
#pragma unroll
                for (int mt = 0; mt < MT2; mt++) {
                    int bm = wm2 * WM2 + mt * 16;
                    afr[mt][0] = hld(&sHb[(bm + ar) * 136 + k + ac * 2]);
                    afr[mt][1] = hld(&sHb[(bm + ar + 8) * 136 + k + ac * 2]);
                    afr[mt][2] = hld(&sHb[(bm + ar) * 136 + k + ac * 2 + 8]);
                    afr[mt][3] = hld(&sHb[(bm + ar + 8) * 136 + k + ac * 2 + 8]);
                }
#pragma unroll
                for (int nt = 0; nt < NT2; nt++) {
                    int bn = wn2 * WN2 + nt * 8;
                    bfr[nt][0] = hld(&cB[(bn + ar) * 40 + kk + ac * 2]);
                    bfr[nt][1] = hld(&cB[(bn + ar) * 40 + kk + ac * 2 + 8]);
                }
#pragma unroll
                for (int mt = 0; mt < MT2; mt++)
#pragma unroll
                    for (int nt = 0; nt < NT2; nt++)
                        mma_f16(acc2[mt][nt], afr[mt], bfr[nt]);
            }
        }
#pragma unroll
        for (int mt = 0; mt < MT2; mt++)
#pragma unroll
            for (int h = 0; h < 2; h++) {
                int r = wm2 * WM2 + mt * 16 + ar + 8 * h;
                int row = brow + r;
                float cv = (FLAGS2 & FLAG_CUT) ? cut[row] : 1.0f;
#pragma unroll
                for (int nt = 0; nt < NT2; nt++)
#pragma unroll
                    for (int e = 0; e < 2; e++) {
                        int c = wn2 * WN2 + nt * 8 + ac * 2 + e;
                        float v = acc2[mt][nt][2 * h + e];
                        if (b2v) v += b2v[c];
                        if (FLAGS2 & FLAG_SILU) v = silu_f(v);
                        v *= cv;
                        C[(size_t)row * ldc + c] = v;
                    }
            }
    }
}

// ---------------- small kernels ----------------
__global__ void cvt_kernel(const float* __restrict__ src, float* __restrict__ dst, int n) {
    int t = blockIdx.x * blockDim.x + threadIdx.x;
    if (t < n) dst[t] = f2tf(src[t]);
}

__global__ void tr_half_kernel(const float* __restrict__ W, __half* __restrict__ WT,
                               int K, int N) {
    int t = blockIdx.x * blockDim.x + threadIdx.x;
    if (t >= K * N) return;
    int k = t / N, n = t % N;
    WT[(size_t)n * K + k] = __float2half(W[t]);
}

// compact fp16 copy of xinv cols 0..31 -> xh[PE][32]
__global__ void e_to_half_kernel() {
    int t = blockIdx.x * blockDim.x + threadIdx.x;
    if (t >= PE * 32) return;
    int p = t >> 5, c = t & 31;
    g_xh[t] = __float2half(g_xinv[(size_t)p * 192 + c]);
}

__global__ void copy_s_kernel(const float* __restrict__ features) {
    int t = blockIdx.x * blockDim.x + threadIdx.x;
    if (t < NA * FD) g_s[t] = features[t];
}

__global__ void compute_u_kernel(const float* __restrict__ vectors,
                                 const float* __restrict__ distances) {
    int t = blockIdx.x * blockDim.x + threadIdx.x;
    if (t >= PE * 3) return;
    int p = t / 3;
    g_u[t] = vectors[t] / (distances[p] + 0.001f);
}

__global__ void offsets_kernel(const int* __restrict__ idx_i) {
    int n = blockIdx.x * blockDim.x + threadIdx.x;
    if (n > NA) return;
    int lo = 0, hi = PE;
    while (lo < hi) {
        int mid = (lo + hi) >> 1;
        if (idx_i[mid] < n) lo = mid + 1; else hi = mid;
    }
    g_start[n] = lo;
}

__global__ void afeat_kernel(const int* __restrict__ idx_i,
                             const int* __restrict__ idx_j) {
    int t = blockIdx.x * blockDim.x + threadIdx.x;
    if (t >= PE * MD) return;
    int p = t / MD, mm = t % MD;
    const float* vi = g_vA + (size_t)idx_i[p] * 96;
    const float* vj = g_vA + (size_t)idx_j[p] * 96;
    float u0 = g_u[p * 3 + 0], u1 = g_u[p * 3 + 1], u2 = g_u[p * 3 + 2];
    float vi0 = vi[mm], vi1 = vi[32 + mm], vi2 = vi[64 + mm];
    float vj0 = vj[mm], vj1 = vj[32 + mm], vj2 = vj[64 + mm];
    float* x = g_xinv + (size_t)p * 192 + 32;
    x[mm]       = f2tf(u0 * vi0 + u1 * vi1 + u2 * vi2);
    x[32 + mm]  = f2tf(u0 * vj0 + u1 * vj1 + u2 * vj2);
    x[64 + mm]  = f2tf(vi0 * vj0 + vi1 * vj1 + vi2 * vj2);
    x[96 + mm]  = f2tf(vi0 * vi0 + vi1 * vi1 + vi2 * vi2);
    x[128 + mm] = f2tf(vj0 * vj0 + vj1 * vj1 + vj2 * vj2);
}

__global__ void segsum_s_kernel() {
    int n = blockIdx.x, f = threadIdx.x;
    int p0 = g_start[n], p1 = g_start[n + 1];
    float acc = 0.0f;
    for (int p = p0; p < p1; p++) acc += g_m[(size_t)p * FD + f];
    g_s[n * FD + f] += acc;
}

__global__ void segsum_v0_kernel(const float* __restrict__ cut) {
    int n = blockIdx.x, t = threadIdx.x;
    int d = t / 32, mm = t % 32;
    int p0 = g_start[n], p1 = g_start[n + 1];
    float acc = 0.0f;
    for (int p = p0; p < p1; p++)
        acc += g_gbuf[(size_t)p * 64 + mm] * g_u[p * 3 + d] * cut[p];
    g_vA[n * 96 + t] = acc;
}

__global__ void segsum_v1_kernel(const float* __restrict__ cut,
                                 const int* __restrict__ idx_j) {
    int n = blockIdx.x, t = threadIdx.x;
    int d = t / 32, mm = t % 32;
    int p0 = g_start[n], p1 = g_start[n + 1];
    float acc = 0.0f;
    for (int p = p0; p < p1; p++) {
        float vjv = g_vA[(size_t)idx_j[p] * 96 + t];
        acc += (g_gbuf[(size_t)p * 64 + mm] * g_u[p * 3 + d]
              + g_gbuf[(size_t)p * 64 + 32 + mm] * vjv) * cut[p];
    }
    g_vB[n * 96 + t] = g_vA[n * 96 + t] + acc;
}

__global__ void copy_weff_kernel(const float* __restrict__ uW1) {
    int t = blockIdx.x * blockDim.x + threadIdx.x;
    if (t < FD * FD) g_weff[t] = uW1[t];
}

__global__ void copy_out_kernel(float* __restrict__ out) {
    int t = blockIdx.x * blockDim.x + threadIdx.x;
    const int SN = NA * FD, VN = NA * 3 * MD;
    if (t < SN) out[t] = g_s[t];
    else if (t < SN + VN) out[t] = g_vB[t - SN];
}

// ---------------- host ----------------
extern "C" void kernel_launch(void* const* d_in, const int* in_sizes, int n_in,
                              void* d_out, int out_size)
{
    const float* features  = (const float*)d_in[0];
    const float* distances = (const float*)d_in[1];
    const float* vectors   = (const float*)d_in[2];
    const float* cutoffs   = (const float*)d_in[3];
    const float* rbfs      = (const float*)d_in[4];
    const int*   idx_i     = (const int*)d_in[5];
    const int*   idx_j     = (const int*)d_in[6];
    const float* Wrbf      = (const float*)d_in[7];
    const float* Wemb      = (const float*)d_in[8];
    const float* eq0_W1    = (const float*)d_in[9];
    const float* eq0_b1    = (const float*)d_in[10];
    const float* eq0_W2    = (const float*)d_in[11];
    const float* eq1_W1    = (const float*)d_in[12];
    const float* eq1_b1    = (const float*)d_in[13];
    const float* eq1_W2    = (const float*)d_in[14];
    const float* inv_W1    = (const float*)d_in[15];
    const float* inv_b1    = (const float*)d_in[16];
    const float* inv_W2    = (const float*)d_in[17];
    const float* inv_b2    = (const float*)d_in[18];
    const float* upd_W1    = (const float*)d_in[19];
    const float* upd_b1    = (const float*)d_in[20];
    const float* upd_W2    = (const float*)d_in[21];
    const float* upd_b2    = (const float*)d_in[22];
    float* out = (float*)d_out;

    static bool attr_done = false;
    if (!attr_done) {
        cudaFuncSetAttribute(mlp_fused<64, 0>,
                             cudaFuncAttributeMaxDynamicSharedMemorySize, SMEM_MLP);
        cudaFuncSetAttribute(mlp_fused<128, FLAG_SILU | FLAG_CUT>,
                             cudaFuncAttributeMaxDynamicSharedMemorySize, SMEM_MLP);
        cudaFuncSetAttribute(mlp_h0<64, 0>,
                             cudaFuncAttributeMaxDynamicSharedMemorySize, SMEM_EQ);
        cudaFuncSetAttribute(mlp_h0<128, FLAG_SILU | FLAG_CUT>,
                             cudaFuncAttributeMaxDynamicSharedMemorySize, SMEM_EQ);
        attr_done = true;
    }

    void* tp;
    float *s, *xinv, *gb, *m, *Pei, *Pej, *Peqi, *Peqj, *Pinvi, *Pinvj;
    float *weff, *hu, *cew1, *cew2, *cw1, *cw2;
    __half *xh, *tew1, *tew2, *tiw1, *tiw2;
    cudaGetSymbolAddress(&tp, g_s);      s      = (float*)tp;
    cudaGetSymbolAddress(&tp, g_xinv);   xinv   = (float*)tp;
    cudaGetSymbolAddress(&tp, g_gbuf);   gb     = (float*)tp;
    cudaGetSymbolAddress(&tp, g_m);      m      = (float*)tp;
    cudaGetSymbolAddress(&tp, g_Pei);    Pei    = (float*)tp;
    cudaGetSymbolAddress(&tp, g_Pej);    Pej    = (float*)tp;
    cudaGetSymbolAddress(&tp, g_Peqi);   Peqi   = (float*)tp;
    cudaGetSymbolAddress(&tp, g_Peqj);   Peqj   = (float*)tp;
    cudaGetSymbolAddress(&tp, g_Pinvi);  Pinvi  = (float*)tp;
    cudaGetSymbolAddress(&tp, g_Pinvj);  Pinvj  = (float*)tp;
    cudaGetSymbolAddress(&tp, g_weff);   weff   = (float*)tp;
    cudaGetSymbolAddress(&tp, g_hu);     hu     = (float*)tp;
    cudaGetSymbolAddress(&tp, g_cew1);   cew1   = (float*)tp;
    cudaGetSymbolAddress(&tp, g_cew2);   cew2   = (float*)tp;
    cudaGetSymbolAddress(&tp, g_cw1);    cw1    = (float*)tp;
    cudaGetSymbolAddress(&tp, g_cw2);    cw2    = (float*)tp;
    cudaGetSymbolAddress(&tp, g_xh);     xh     = (__half*)tp;
    cudaGetSymbolAddress(&tp, g_tew1);   tew1   = (__half*)tp;
    cudaGetSymbolAddress(&tp, g_tew2);   tew2   = (__half*)tp;
    cudaGetSymbolAddress(&tp, g_tiw1);   tiw1   = (__half*)tp;
    cudaGetSymbolAddress(&tp, g_tiw2);   tiw2   = (__half*)tp;

    copy_s_kernel<<<(NA * FD + 255) / 256, 256>>>(features);
    compute_u_kernel<<<(PE * 3 + 255) / 256, 256>>>(vectors, distances);
    offsets_kernel<<<(NA + 1 + 255) / 256, 256>>>(idx_i);

    const int gridN = (NA + 63) / 64;
    const int gridE = PE / 128;

    for (int b = 0; b < 2; b++) {
        const float* eqW1 = b ? eq1_W1 : eq0_W1;
        const float* eqb1 = b ? eq1_b1 : eq0_b1;
        const float* eqW2 = b ? eq1_W2 : eq0_W2;
        const int eq_si = b ? 192 : 32;
        const int eq_sj = b ? 320 : 160;
        const float* iW1 = inv_W1 + (size_t)b * 448 * 128;
        const float* ib1 = inv_b1 + b * 128;
        const float* iW2 = inv_W2 + (size_t)b * 128 * 128;
        const float* ib2 = inv_b2 + b * 128;
        const float* uW1 = upd_W1 + (size_t)b * 256 * 128;
        const float* ub1 = upd_b1 + b * 128;
        const float* uW2 = upd_W2 + (size_t)b * 128 * 128;
        const float* ub2 = upd_b2 + b * 128;
        const int Ke = b ? 192 : 32;

        // node projections, batched
        {
            PB4 p2; p2.W[0] = Wrbf + 64 * 32; p2.W[1] = Wrbf + 192 * 32;
            p2.C[0] = Pei; p2.C[1] = Pej;
            gemm_batch<64, 32><<<dim3(gridN, 2), 256>>>(s, FD, p2, 32, 32, NA, FD);

            PB4 p4;
            p4.W[0] = eqW1 + (size_t)eq_si * 128;
            p4.W[1] = eqW1 + (size_t)eq_sj * 128;
            p4.W[2] = iW1 + 192 * 128;
            p4.W[3] = iW1 + 320 * 128;
            p4.C[0] = Peqi; p4.C[1] = Peqj; p4.C[2] = Pinvi; p4.C[3] = Pinvj;
            gemm_batch<64, 128><<<dim3(gridN, 4), 256>>>(s, FD, p4, 128, 128, NA, FD);
        }

        if (b == 0) {
            // fp16 weights for block-0 MLPs
            tr_half_kernel<<<(32 * 128 + 255) / 256, 256>>>(eqW1, tew1, 32, 128);
            tr_half_kernel<<<(128 * 64 + 255) / 256, 256>>>(eqW2, tew2, 128, 64);
            tr_half_kernel<<<(32 * 128 + 255) / 256, 256>>>(iW1, tiw1, 32, 128);
            tr_half_kernel<<<(128 * 128 + 255) / 256, 256>>>(iW2, tiw2, 128, 128);
        } else {
            // tf32 pre-rounded weights for block-1 MLPs
            cvt_kernel<<<(Ke * 128 + 255) / 256, 256>>>(eqW1, cew1, Ke * 128);
            cvt_kernel<<<(128 * 64 + 255) / 256, 256>>>(eqW2, cew2, 128 * 64);
            cvt_kernel<<<(Ke * 128 + 255) / 256, 256>>>(iW1, cw1, Ke * 128);
            cvt_kernel<<<(128 * 128 + 255) / 256, 256>>>(iW2, cw2, 128 * 128);
        }

        // e = rbfs @ Wrbf[0:64] + Pei[i] + Pej[j]  -> xinv cols 0..31 (tf32)
        gemm_single<128, 32><<<gridE, 256>>>(rbfs, RD, Wrbf, 32, xinv, 192, PE, RD,
                                             0, Pei, Pej, 32, idx_i, idx_j, 0, FLAG_TF32);

        if (b == 0) {
            // compact fp16 X and run fp16 MLPs (bounded range -> safe)
            e_to_half_kernel<<<(PE * 32 + 255) / 256, 256>>>();
            mlp_h0<64, 0><<<gridE, 256, SMEM_EQ>>>(
                xh, tew1, eqb1, Peqi, Peqj, idx_i, idx_j,
                tew2, (const float*)0, (const float*)0, gb, 64);
            mlp_h0<128, FLAG_SILU | FLAG_CUT><<<gridE, 256, SMEM_EQ>>>(
                xh, tiw1, ib1, Pinvi, Pinvj, idx_i, idx_j,
                tiw2, ib2, cutoffs, m, 128);
        } else {
            afeat_kernel<<<(PE * MD + 255) / 256, 256>>>(idx_i, idx_j);
            mlp_fused<64, 0><<<gridE, 256, SMEM_MLP>>>(
                xinv, 192, Ke, cew1, eqb1, Peqi, Peqj, idx_i, idx_j,
                cew2, (const float*)0, (const float*)0, gb, 64);
            mlp_fused<128, FLAG_SILU | FLAG_CUT><<<gridE, 256, SMEM_MLP>>>(
                xinv, 192, Ke, cw1, ib1, Pinvi, Pinvj, idx_i, idx_j,
                cw2, ib2, cutoffs, m, 128);
        }

        if (b == 0) segsum_v0_kernel<<<NA, 96>>>(cutoffs);
        else        segsum_v1_kernel<<<NA, 96>>>(cutoffs, idx_j);
        segsum_s_kernel<<<NA, FD>>>();

        // node update: Weff = uW1a + Wemb @ uW1b ; s += silu(silu(s@Weff+b1)@uW2+b2)
        copy_weff_kernel<<<(FD * FD + 255) / 256, 256>>>(uW1);
        gemm_single<64, 128><<<2, 256>>>(Wemb, 128, uW1 + 128 * 128, 128, weff, 128,
                                         128, 128, 0, 0, 0, 0, 0, 0, 0, FLAG_RES);
        gemm_single<64, 128><<<gridN, 256>>>(s, FD, weff, 128, hu, 128, NA, FD,
                                             ub1, 0, 0, 0, 0, 0, 0, FLAG_SILU);
        gemm_single<64, 128><<<gridN, 256>>>(hu, FD, uW2, 128, s, 128, NA, FD,
                                             ub2, 0, 0, 0, 0, 0, 0, FLAG_SILU | FLAG_RES);
    }

    int total = NA * FD + NA * 3 * MD;
    copy_out_kernel<<<(total + 255) / 256, 256>>>(out);
}

// round 15
// speedup vs baseline: 1.1160x; 1.0439x over previous
#include <cuda_runtime.h>
#include <cuda_fp16.h>
#include <cstdint>
#include <cstddef>

#define NA 20000
#define PE 320000
#define FD 128
#define RD 64
#define MD 32

enum { FLAG_SILU = 1, FLAG_RES = 2, FLAG_CUT = 4, FLAG_TF32 = 8 };

#define ASCL_DOWN (1.0f / 8192.0f)
#define ASCL_UP   8192.0f

// ---------------- scratch (device globals; no runtime alloc) ----------------
__device__ float g_u[PE * 3];
__device__ float g_s[NA * FD];
__device__ float g_vA[NA * 3 * MD];
__device__ float g_vB[NA * 3 * MD];
__device__ int   g_start[NA + 1];
__device__ float g_xinv[(size_t)PE * 192];
__device__ float g_gbuf[(size_t)PE * 64];
__device__ float g_m[(size_t)PE * FD];
__device__ float g_Pei[NA * MD];
__device__ float g_Pej[NA * MD];
__device__ float g_Peqi[NA * FD];
__device__ float g_Peqj[NA * FD];
__device__ float g_Pinvi[NA * FD];
__device__ float g_Pinvj[NA * FD];
__device__ float g_weff[FD * FD];
__device__ float g_hu[NA * FD];
// tf32 pre-rounded W2s (phase-2 of block-1)
__device__ float g_cew2[128 * 64];
__device__ float g_cw2[128 * 128];
// block-0 fp16 data (bounded range)
__device__ __align__(16) __half g_xh[(size_t)PE * 32];
__device__ __align__(16) __half g_tew1[128 * 32];
__device__ __align__(16) __half g_tew2[64 * 128];
__device__ __align__(16) __half g_tiw1[128 * 32];
__device__ __align__(16) __half g_tiw2[128 * 128];
// block-1 fp16 data (a-cols scaled by 2^-13; W1 rows>=32 scaled by 2^13)
__device__ __align__(16) __half g_xh1[(size_t)PE * 192];
__device__ __align__(16) __half g_tew1b[128 * 192];
__device__ __align__(16) __half g_tiw1b[128 * 192];

__device__ __forceinline__ float silu_f(float x) { return x / (1.0f + expf(-x)); }

__device__ __forceinline__ float f2tf(float f) {
    uint32_t u;
    asm("cvt.rna.tf32.f32 %0, %1;" : "=r"(u) : "f"(f));
    return __uint_as_float(u);
}

union U32H2 { uint32_t u; __half2 h; };
__device__ __forceinline__ uint32_t hld(const __half* p) {
    U32H2 x; x.h = *(const __half2*)p; return x.u;
}

__device__ __forceinline__ void mma_tf32(float c[4], const uint32_t a[4], const uint32_t b[2]) {
    asm volatile(
        "mma.sync.aligned.m16n8k8.row.col.f32.tf32.tf32.f32 "
        "{%0,%1,%2,%3}, {%4,%5,%6,%7}, {%8,%9}, {%0,%1,%2,%3};\n"
        : "+f"(c[0]), "+f"(c[1]), "+f"(c[2]), "+f"(c[3])
        : "r"(a[0]), "r"(a[1]), "r"(a[2]), "r"(a[3]), "r"(b[0]), "r"(b[1]));
}

__device__ __forceinline__ void mma_f16(float c[4], const uint32_t a[4], const uint32_t b[2]) {
    asm volatile(
        "mma.sync.aligned.m16n8k16.row.col.f32.f16.f16.f32 "
        "{%0,%1,%2,%3}, {%4,%5,%6,%7}, {%8,%9}, {%0,%1,%2,%3};\n"
        : "+f"(c[0]), "+f"(c[1]), "+f"(c[2]), "+f"(c[3])
        : "r"(a[0]), "r"(a[1]), "r"(a[2]), "r"(a[3]), "r"(b[0]), "r"(b[1]));
}

__device__ __forceinline__ uint32_t smem_u32(const void* p) {
    uint32_t a;
    asm("{ .reg .u64 t; cvta.to.shared.u64 t, %1; cvt.u32.u64 %0, t; }" : "=r"(a) : "l"(p));
    return a;
}

#define CPA16(dst, src) \
    asm volatile("cp.async.cg.shared.global [%0], [%1], 16;" :: "r"(dst), "l"(src))
#define CPA_COMMIT() asm volatile("cp.async.commit_group;" ::: "memory")
#define CPA_WAIT0()  asm volatile("cp.async.wait_group 0;" ::: "memory")

// ================= pipelined tf32 legacy GEMM (round 8, unchanged) ===========
template <int BM, int BN>
__device__ __forceinline__ void gemm_body(
    const float* __restrict__ A, int lda,
    const float* __restrict__ W, int ldw,
    float* __restrict__ C, int ldc,
    int Mrows, int K,
    const float* __restrict__ bias,
    const float* __restrict__ Pi,
    const float* __restrict__ Pj, int ldp,
    const int* __restrict__ ii,
    const int* __restrict__ jj,
    const float* __restrict__ cut,
    int flags)
{
    constexpr int BK = 16;
    constexpr int MW = (BN >= 128) ? 2 : (BN == 64 ? 4 : (BM >= 128 ? 8 : 4));
    constexpr int NW = 8 / MW;
    constexpr int WM = BM / MW, WN = BN / NW;
    constexpr int MT = WM / 16, NT = WN / 8;
    constexpr int SAS = BM + 8, SBS = BN + 8;
    constexpr int A4 = (BM * 4) / 256;
    constexpr int B4N = BN / 4;
    constexpr int B4 = (BN * 4 + 255) / 256;
    constexpr bool BG = ((BN * 4) % 256) != 0;

    __shared__ float sA[2][BK][SAS];
    __shared__ float sB[2][BK][SBS];

    const int tid  = threadIdx.x;
    const int lane = tid & 31;
    const int wid  = tid >> 5;
    const int wm   = wid % MW;
    const int wn   = wid / MW;
    const int brow = blockIdx.x * BM;
    const int ar = lane >> 2, ac = lane & 3;

    float acc[MT][NT][4];
#pragma unroll
    for (int i = 0; i < MT; i++)
#pragma unroll
        for (int j = 0; j < NT; j++)
#pragma unroll
            for (int r = 0; r < 4; r++) acc[i][j][r] = 0.0f;

    float4 ra[A4], rb[B4];
    const int nIter = K / BK;

#pragma unroll
    for (int i = 0; i < A4; i++) {
        int q = tid + i * 256, m = q >> 2, kq = q & 3;
        int row = brow + m;
        ra[i] = (row < Mrows) ? *(const float4*)&A[(size_t)row * lda + 4 * kq]
                              : make_float4(0.f, 0.f, 0.f, 0.f);
    }
#pragma unroll
    for (int i = 0; i < B4; i++) {
        int q = tid + i * 256;
        if (!BG || q < BN * 4) {
            int kk = q / B4N, c4 = (q % B4N) * 4;
            rb[i] = *(const float4*)&W[(size_t)kk * ldw + c4];
        }
    }

    for (int it = 0; it < nIter; ++it) {
        int buf = it & 1;
#pragma unroll
        for (int i = 0; i < A4; i++) {
            int q = tid + i * 256, m = q >> 2, kq = q & 3;
            sA[buf][4 * kq + 0][m] = f2tf(ra[i].x);
            sA[buf][4 * kq + 1][m] = f2tf(ra[i].y);
            sA[buf][4 * kq + 2][m] = f2tf(ra[i].z);
            sA[buf][4 * kq + 3][m] = f2tf(ra[i].w);
        }
#pragma unroll
        for (int i = 0; i < B4; i++) {
            int q = tid + i * 256;
            if (!BG || q < BN * 4) {
                int kk = q / B4N, c4 = (q % B4N) * 4;
                float4 v;
                v.x = f2tf(rb[i].x); v.y = f2tf(rb[i].y);
                v.z = f2tf(rb[i].z); v.w = f2tf(rb[i].w);
                *(float4*)&sB[buf][kk][c4] = v;
            }
        }
        __syncthreads();
        if (it + 1 < nIter) {
            int k0 = (it + 1) * BK;
#pragma unroll
            for (int i = 0; i < A4; i++) {
                int q = tid + i * 256, m = q >> 2, kq = q & 3;
                int row = brow + m;
                ra[i] = (row < Mrows) ? *(const float4*)&A[(size_t)row * lda + k0 + 4 * kq]
                                      : make_float4(0.f, 0.f, 0.f, 0.f);
            }
#pragma unroll
            for (int i = 0; i < B4; i++) {
                int q = tid + i * 256;
                if (!BG || q < BN * 4) {
                    int kk = q / B4N, c4 = (q % B4N) * 4;
                    rb[i] = *(const float4*)&W[(size_t)(k0 + kk) * ldw + c4];
                }
            }
        }
#pragma unroll
        for (int kk = 0; kk < BK; kk += 8) {
            uint32_t afr[MT][4], bfr[NT][2];
#pragma unroll
            for (int mt = 0; mt < MT; mt++) {
                int bm = wm * WM + mt * 16;
                afr[mt][0] = __float_as_uint(sA[buf][kk + ac][bm + ar]);
                afr[mt][1] = __float_as_uint(sA[buf][kk + ac][bm + ar + 8]);
                afr[mt][2] = __float_as_uint(sA[buf][kk + ac + 4][bm + ar]);
                afr[mt][3] = __float_as_uint(sA[buf][kk + ac + 4][bm + ar + 8]);
            }
#pragma unroll
            for (int nt = 0; nt < NT; nt++) {
                int bn = wn * WN + nt * 8;
                bfr[nt][0] = __float_as_uint(sB[buf][kk + ac][bn + ar]);
                bfr[nt][1] = __float_as_uint(sB[buf][kk + ac + 4][bn + ar]);
            }
#pragma unroll
            for (int mt = 0; mt < MT; mt++)
#pragma unroll
                for (int nt = 0; nt < NT; nt++)
                    mma_tf32(acc[mt][nt], afr[mt], bfr[nt]);
        }
    }

#pragma unroll
    for (int mt = 0; mt < MT; mt++) {
#pragma unroll
        for (int h = 0; h < 2; h++) {
            int r = wm * WM + mt * 16 + ar + 8 * h;
            int row = brow + r;
            if (row >= Mrows) continue;
            int pii = 0, pjj = 0;
            if (Pi) { pii = ii[row]; pjj = jj[row]; }
            float cv = (flags & FLAG_CUT) ? cut[row] : 1.0f;
#pragma unroll
            for (int nt = 0; nt < NT; nt++) {
                int col = wn * WN + nt * 8 + ac * 2;
#pragma unroll
                for (int e = 0; e < 2; e++) {
                    int c = col + e;
                    float v = acc[mt][nt][2 * h + e];
                    if (bias) v += bias[c];
                    if (Pi) v += Pi[(size_t)pii * ldp + c] + Pj[(size_t)pjj * ldp + c];
                    if (flags & FLAG_SILU) v = silu_f(v);
                    v *= cv;
                    if (flags & FLAG_TF32) v = f2tf(v);
                    float* cp = &C[(size_t)row * ldc + c];
                    if (flags & FLAG_RES) *cp += v; else *cp = v;
                }
            }
        }
    }
}

template <int BM, int BN>
__global__ void __launch_bounds__(256) gemm_single(
    const float* __restrict__ A, int lda, const float* __restrict__ W, int ldw,
    float* __restrict__ C, int ldc, int Mrows, int K,
    const float* __restrict__ bias, const float* __restrict__ Pi,
    const float* __restrict__ Pj, int ldp, const int* __restrict__ ii,
    const int* __restrict__ jj, const float* __restrict__ cut, int flags)
{
    gemm_body<BM, BN>(A, lda, W, ldw, C, ldc, Mrows, K, bias, Pi, Pj, ldp, ii, jj, cut, flags);
}

struct PB4 { const float* W[4]; float* C[4]; };

template <int BM, int BN>
__global__ void __launch_bounds__(256) gemm_batch(
    const float* __restrict__ A, int lda, PB4 p, int ldw, int ldc, int Mrows, int K)
{
    gemm_body<BM, BN>(A, lda, p.W[blockIdx.y], ldw, p.C[blockIdx.y], ldc,
                      Mrows, K, 0, 0, 0, 0, 0, 0, 0, 0);
}

// ================= block-0 MLPs: fp16 (K1=32, validated round 14) ============
#define SMEM_EQ (20480 + 20480 + 34816)

template <int N2, int FLAGS2>
__global__ void __launch_bounds__(256, 2) mlp_h0(
    const __half* __restrict__ X,
    const __half* __restrict__ W1T,
    const float* __restrict__ b1v,
    const float* __restrict__ Pi, const float* __restrict__ Pj,
    const int* __restrict__ ii, const int* __restrict__ jj,
    const __half* __restrict__ W2T,
    const float* __restrict__ b2v,
    const float* __restrict__ cut,
    float* __restrict__ C, int ldc)
{
    extern __shared__ char dsmc[];
    __half* sA0 = (__half*)dsmc;
    __half* sB0 = (__half*)(dsmc + 20480);
    __half* sHb = (__half*)(dsmc + 40960);

    const int tid = threadIdx.x, lane = tid & 31, wid = tid >> 5;
    const int brow = blockIdx.x * 128;
    const int ar = lane >> 2, ac = lane & 3;
    const uint32_t sBu = smem_u32(sB0);

    const int wm = wid & 1, wn = wid >> 1;

    {
        float acc[4][4][4];
#pragma unroll
        for (int i = 0; i < 4; i++)
#pragma unroll
            for (int j = 0; j < 4; j++)
#pragma unroll
                for (int r = 0; r < 4; r++) acc[i][j][r] = 0.0f;

        uint4 ra[2], rb[2];
#pragma unroll
        for (int i = 0; i < 2; i++) {
            int q = tid + i * 256, row = q >> 2, seg = q & 3;
            ra[i] = *(const uint4*)&X[(size_t)(brow + row) * 32 + seg * 8];
        }
#pragma unroll
        for (int i = 0; i < 2; i++) {
            int q = tid + i * 256, n = q >> 2, seg = q & 3;
            rb[i] = *(const uint4*)&W1T[(size_t)n * 32 + seg * 8];
        }
#pragma unroll
        for (int i = 0; i < 2; i++) {
            int q = tid + i * 256, row = q >> 2, seg = q & 3;
            *(uint4*)&sA0[row * 40 + seg * 8] = ra[i];
        }
#pragma unroll
        for (int i = 0; i < 2; i++) {
            int q = tid + i * 256, n = q >> 2, seg = q & 3;
            *(uint4*)&sB0[n * 40 + seg * 8] = rb[i];
        }
        __syncthreads();

#pragma unroll
        for (int kk = 0; kk < 32; kk += 16) {
            uint32_t afr[4][4], bfr[4][2];
#pragma unroll
            for (int mt = 0; mt < 4; mt++) {
                int bm = wm * 64 + mt * 16;
                afr[mt][0] = hld(&sA0[(bm + ar) * 40 + kk + ac * 2]);
                afr[mt][1] = hld(&sA0[(bm + ar + 8) * 40 + kk + ac * 2]);
                afr[mt][2] = hld(&sA0[(bm + ar) * 40 + kk + ac * 2 + 8]);
                afr[mt][3] = hld(&sA0[(bm + ar + 8) * 40 + kk + ac * 2 + 8]);
            }
#pragma unroll
            for (int nt = 0; nt < 4; nt++) {
                int bn = wn * 32 + nt * 8;
                bfr[nt][0] = hld(&sB0[(bn + ar) * 40 + kk + ac * 2]);
                bfr[nt][1] = hld(&sB0[(bn + ar) * 40 + kk + ac * 2 + 8]);
            }
#pragma unroll
            for (int mt = 0; mt < 4; mt++)
#pragma unroll
                for (int nt = 0; nt < 4; nt++)
                    mma_f16(acc[mt][nt], afr[mt], bfr[nt]);
        }

#pragma unroll
        for (int mt = 0; mt < 4; mt++)
#pragma unroll
            for (int h = 0; h < 2; h++) {
                int r = wm * 64 + mt * 16 + ar + 8 * h;
                int row = brow + r;
                int pii = ii[row], pjj = jj[row];
                const float* pi = Pi + (size_t)pii * 128;
                const float* pj = Pj + (size_t)pjj * 128;
#pragma unroll
                for (int nt = 0; nt < 4; nt++) {
                    int c = wn * 32 + nt * 8 + ac * 2;
                    float2 a = *(const float2*)&pi[c];
                    float2 b = *(const float2*)&pj[c];
                    float2 bb = *(const float2*)&b1v[c];
                    float v0 = silu_f(acc[mt][nt][2 * h + 0] + a.x + b.x + bb.x);
                    float v1 = silu_f(acc[mt][nt][2 * h + 1] + a.y + b.y + bb.y);
                    *(__half2*)&sHb[r * 136 + c] = __floats2half2_rn(v0, v1);
                }
            }
    }
    __syncthreads();

    {
        constexpr int MW2 = (N2 == 128) ? 2 : 4;
        constexpr int WM2 = 128 / MW2;
        constexpr int WN2 = 32;
        constexpr int MT2 = WM2 / 16;
        constexpr int NT2 = 4;
        constexpr int NCH = N2 / 64;
        const int wm2 = wid % MW2, wn2 = wid / MW2;

#pragma unroll
        for (int i = 0; i < NCH; i++) {
            int q = tid + i * 256, n = q >> 2, seg = q & 3;
            CPA16(sBu + (uint32_t)(n * 80 + seg * 16),
                  &W2T[(size_t)n * 128 + seg * 8]);
        }
        CPA_COMMIT();

        float acc2[MT2][NT2][4];
#pragma unroll
        for (int i = 0; i < MT2; i++)
#pragma unroll
            for (int j = 0; j < NT2; j++)
#pragma unroll
                for (int r = 0; r < 4; r++) acc2[i][j][r] = 0.0f;

        for (int it = 0; it < 4; ++it) {
            CPA_WAIT0();
            __syncthreads();
            if (it < 3) {
                int k0 = (it + 1) * 32;
                uint32_t nb = (uint32_t)((it + 1) & 1);
#pragma unroll
                for (int i = 0; i < NCH; i++) {
                    int q = tid + i * 256, n = q >> 2, seg = q & 3;
                    CPA16(sBu + nb * 10240u + (uint32_t)(n * 80 + seg * 16),
                          &W2T[(size_t)n * 128 + k0 + seg * 8]);
                }
                CPA_COMMIT();
            }
            const __half* cB = sB0 + (it & 1) * 5120;
#pragma unroll
            for (int kk = 0; kk < 32; kk += 16) {
                int k = it * 32 + kk;
                uint32_t afr[MT2][4], bfr[NT2][2];
#pragma unroll
                for (int mt = 0; mt < MT2; mt++) {
                    int bm = wm2 * WM2 + mt * 16;
                    afr[mt][0] = hld(&sHb[(bm + ar) * 136 + k + ac * 2]);
                    afr[mt][1] = hld(&sHb[(bm + ar + 8) * 136 + k + ac * 2]);
                    afr[mt][2] = hld(&sHb[(bm + ar) * 136 + k + ac * 2 + 8]);
                    afr[mt][3] = hld(&sHb[(bm + ar + 8) * 136 + k + ac * 2 + 8]);
                }
#pragma unroll
                for (int nt = 0; nt < NT2; nt++) {
                    int bn = wn2 * WN2 + nt * 8;
                    bfr[nt][0] = hld(&cB[(bn + ar) * 40 + kk + ac * 2]);
                    bfr[nt][1] = hld(&cB[(bn + ar) * 40 + kk + ac * 2 + 8]);
                }
#pragma unroll
                for (int mt = 0; mt < MT2; mt++)
#pragma unroll
                    for (int nt = 0; nt < NT2; nt++)
                        mma_f16(acc2[mt][nt], afr[mt], bfr[nt]);
            }
        }
#pragma unroll
        for (int mt = 0; mt < MT2; mt++)
#pragma unroll
            for (int h = 0; h < 2; h++) {
                int r = wm2 * WM2 + mt * 16 + ar + 8 * h;
                int row = brow + r;
                float cv = (FLAGS2 & FLAG_CUT) ? cut[row] : 1.0f;
#pragma unroll
                for (int nt = 0; nt < NT2; nt++)
#pragma unroll
                    for (int e = 0; e < 2; e++) {
                        int c = wn2 * WN2 + nt * 8 + ac * 2 + e;
                        float v = acc2[mt][nt][2 * h + e];
                        if (b2v) v += b2v[c];
                        if (FLAGS2 & FLAG_SILU) v = silu_f(v);
                        v *= cv;
                        C[(size_t)row * ldc + c] = v;
                    }
            }
    }
}

// ================= block-1 MLPs: fp16 phase-1 (scaled), tf32 phase-2 =========
// X [PE][192] fp16 (a-cols x 2^-13); W1T [128][192] fp16 (rows>=32 x 2^13);
// W2 [128][N2] float tf32-pre-rounded. Hidden in fp32 smem (no overflow).
#define SMEM_B1 (20480 + 20480 + 128 * 132 * 4)

template <int N2, int FLAGS2>
__global__ void __launch_bounds__(256, 2) mlp_b1(
    const __half* __restrict__ X,
    const __half* __restrict__ W1T,
    const float* __restrict__ b1v,
    const float* __restrict__ Pi, const float* __restrict__ Pj,
    const int* __restrict__ ii, const int* __restrict__ jj,
    const float* __restrict__ W2,
    const float* __restrict__ b2v,
    const float* __restrict__ cut,
    float* __restrict__ C, int ldc)
{
    extern __shared__ char dsmc[];
    __half* sAh = (__half*)dsmc;                   // 2 x [128][40] halves
    __half* sBh = (__half*)(dsmc + 20480);         // 2 x [128][40] halves
    float*  sHf = (float*)(dsmc + 40960);          // [128][132] floats
    float*  sBf = (float*)dsmc;                    // phase-2: 2 x [16][136] floats

    const int tid = threadIdx.x, lane = tid & 31, wid = tid >> 5;
    const int brow = blockIdx.x * 128;
    const int ar = lane >> 2, ac = lane & 3;
    const uint32_t sAu  = smem_u32(sAh);
    const uint32_t sBuh = smem_u32(sBh);
    const uint32_t sBuf = smem_u32(sBf);

    const int wm = wid & 1, wn = wid >> 1;

    // ---- phase 1: 6 iters of BK=32, fp16 mma, cp.async staging ----
    {
#pragma unroll
        for (int i = 0; i < 2; i++) {
            int q = tid + i * 256, row = q >> 2, seg = q & 3;
            CPA16(sAu + (uint32_t)(row * 80 + seg * 16),
                  &X[(size_t)(brow + row) * 192 + seg * 8]);
        }
#pragma unroll
        for (int i = 0; i < 2; i++) {
            int q = tid + i * 256, n = q >> 2, seg = q & 3;
            CPA16(sBuh + (uint32_t)(n * 80 + seg * 16),
                  &W1T[(size_t)n * 192 + seg * 8]);
        }
        CPA_COMMIT();

        float acc[4][4][4];
#pragma unroll
        for (int i = 0; i < 4; i++)
#pragma unroll
            for (int j = 0; j < 4; j++)
#pragma unroll
                for (int r = 0; r < 4; r++) acc[i][j][r] = 0.0f;

        for (int it = 0; it < 6; ++it) {
            CPA_WAIT0();
            __syncthreads();
            if (it < 5) {
                int k0 = (it + 1) * 32;
                uint32_t nb = (uint32_t)((it + 1) & 1);
#pragma unroll
                for (int i = 0; i < 2; i++) {
                    int q = tid + i * 256, row = q >> 2, seg = q & 3;
                    CPA16(sAu + nb * 10240u + (uint32_t)(row * 80 + seg * 16),
                          &X[(size_t)(brow + row) * 192 + k0 + seg * 8]);
                }
#pragma unroll
                for (int i = 0; i < 2; i++) {
                    int q = tid + i * 256, n = q >> 2, seg = q & 3;
                    CPA16(sBuh + nb * 10240u + (uint32_t)(n * 80 + seg * 16),
                          &W1T[(size_t)n * 192 + k0 + seg * 8]);
                }
                CPA_COMMIT();
            }
            const __half* cA = sAh + (it & 1) * 5120;
            const __half* cB = sBh + (it & 1) * 5120;
#pragma unroll
            for (int kk = 0; kk < 32; kk += 16) {
                uint32_t afr[4][4], bfr[4][2];
#pragma unroll
                for (int mt = 0; mt < 4; mt++) {
                    int bm = wm * 64 + mt * 16;
                    afr[mt][0] = hld(&cA[(bm + ar) * 40 + kk + ac * 2]);
                    afr[mt][1] = hld(&cA[(bm + ar + 8) * 40 + kk + ac * 2]);
                    afr[mt][2] = hld(&cA[(bm + ar) * 40 + kk + ac * 2 + 8]);
                    afr[mt][3] = hld(&cA[(bm + ar + 8) * 40 + kk + ac * 2 + 8]);
                }
#pragma unroll
                for (int nt = 0; nt < 4; nt++) {
                    int bn = wn * 32 + nt * 8;
                    bfr[nt][0] = hld(&cB[(bn + ar) * 40 + kk + ac * 2]);
                    bfr[nt][1] = hld(&cB[(bn + ar) * 40 + kk + ac * 2 + 8]);
                }
#pragma unroll
                for (int mt = 0; mt < 4; mt++)
#pragma unroll
                    for (int nt = 0; nt < 4; nt++)
                        mma_f16(acc[mt][nt], afr[mt], bfr[nt]);
            }
        }

        // epilogue 1: sHf = f2tf(silu(acc + Pi[ii] + Pj[jj] + b1)), fp32 smem
#pragma unroll
        for (int mt = 0; mt < 4; mt++)
#pragma unroll
            for (int h = 0; h < 2; h++) {
                int r = wm * 64 + mt * 16 + ar + 8 * h;
                int row = brow + r;
                int pii = ii[row], pjj = jj[row];
                const float* pi = Pi + (size_t)pii * 128;
                const float* pj = Pj + (size_t)pjj * 128;
#pragma unroll
                for (int nt = 0; nt < 4; nt++) {
                    int c = wn * 32 + nt * 8 + ac * 2;
                    float2 a = *(const float2*)&pi[c];
                    float2 b = *(const float2*)&pj[c];
                    float2 bb = *(const float2*)&b1v[c];
                    sHf[r * 132 + c]     = f2tf(silu_f(acc[mt][nt][2 * h + 0] + a.x + b.x + bb.x));
                    sHf[r * 132 + c + 1] = f2tf(silu_f(acc[mt][nt][2 * h + 1] + a.y + b.y + bb.y));
                }
            }
    }
    // NOTE: phase-2 stage-0 writes float buf0 (bytes [0,8704)) which phase-1's
    // last iteration (buf 1, bytes [10240,20480)) no longer reads -> safe
    // without an extra sync; the loop's first sync publishes sHf.

    // ---- phase 2: round-8 tf32, K=128, 8 iters of BK=16 ----
    {
        constexpr int MW2 = (N2 == 128) ? 2 : 4;
        constexpr int NW2 = 8 / MW2;
        constexpr int WM2 = 128 / MW2, WN2 = N2 / NW2;
        constexpr int MT2 = WM2 / 16, NT2 = WN2 / 8;
        constexpr int B4N = N2 / 4;
        constexpr int ITB = (16 * B4N) / 256;
        const int wm2 = wid % MW2, wn2 = wid / MW2;

#pragma unroll
        for (int i = 0; i < ITB; i++) {
            int q = tid + i * 256, kk = q / B4N, c4 = (q % B4N) * 4;
            CPA16(sBuf + (uint32_t)(kk * 136 + c4) * 4u,
                  &W2[(size_t)kk * N2 + c4]);
        }
        CPA_COMMIT();

        float acc2[MT2][NT2][4];
#pragma unroll
        for (int i = 0; i < MT2; i++)
#pragma unroll
            for (int j = 0; j < NT2; j++)
#pragma unroll
                for (int r = 0; r < 4; r++) acc2[i][j][r] = 0.0f;

        for (int it = 0; it < 8; ++it) {
            CPA_WAIT0();
            __syncthreads();
            if (it < 7) {
                int k0 = (it + 1) * 16;
                uint32_t nb = (uint32_t)((it + 1) & 1);
#pragma unroll
                for (int i = 0; i < ITB; i++) {
                    int q = tid + i * 256, kk = q / B4N, c4 = (q % B4N) * 4;
                    CPA16(sBuf + (nb * 2176u + (uint32_t)(kk * 136 + c4)) * 4u,
                          &W2[(size_t)(k0 + kk) * N2 + c4]);
                }
                CPA_COMMIT();
            }
            const float* cB = sBf + (it & 1) * 2176;
#pragma unroll
            for (int kk = 0; kk < 16; kk += 8) {
                int k = it * 16 + kk;
                uint32_t afr[MT2][4], bfr[NT2][2];
#pragma unroll
                for (int mt = 0; mt < MT2; mt++) {
                    int bm = wm2 * WM2 + mt * 16;
                    afr[mt][0] = __float_as_uint(sHf[(bm + ar) * 132 + k + ac]);
                    afr[mt][1] = __float_as_uint(sHf[(bm + ar + 8) * 132 + k + ac]);
                    afr[mt][2] = __float_as_uint(sHf[(bm + ar) * 132 + k + ac + 4]);
                    afr[mt][3] = __float_as_uint(sHf[(bm + ar + 8) * 132 + k + ac + 4]);
                }
#pragma unroll
                for (int nt = 0; nt < NT2; nt++) {
                    int bn = wn2 * WN2 + nt * 8;
                    bfr[nt][0] = __float_as_uint(cB[(kk + ac) * 136 + bn + ar]);
                    bfr[nt][1] = __float_as_uint(cB[(kk + ac + 4) * 136 + bn + ar]);
                }
#pragma unroll
                for (int mt = 0; mt < MT2; mt++)
#pragma unroll
                    for (int nt = 0; nt < NT2; nt++)
                        mma_tf32(acc2[mt][nt], afr[mt], bfr[nt]);
            }
        }
#pragma unroll
        for (int mt = 0; mt < MT2; mt++)
#pragma unroll
            for (int h = 0; h < 2; h++) {
                int r = wm2 * WM2 + mt * 16 + ar + 8 * h;
                int row = brow + r;
                float cv = (FLAGS2 & FLAG_CUT) ? cut[row] : 1.0f;
#pragma unroll
                for (int nt = 0; nt < NT2; nt++)
#pragma unroll
                    for (int e = 0; e < 2; e++) {
                        int c = wn2 * WN2 + nt * 8 + ac * 2 + e;
                        float v = acc2[mt][nt][2 * h + e];
                        if (b2v) v += b2v[c];
                        if (FLAGS2 & FLAG_SILU) v = silu_f(v);
                        v *= cv;
                        C[(size_t)row * ldc + c] = v;
                    }
            }
    }
}

// ---------------- small kernels ----------------
__global__ void cvt_kernel(const float* __restrict__ src, float* __restrict__ dst, int n) {
    int t = blockIdx.x * blockDim.x + threadIdx.x;
    if (t < n) dst[t] = f2tf(src[t]);
}

__global__ void tr_half_kernel(const float* __restrict__ W, __half* __restrict__ WT,
                               int K, int N) {
    int t = blockIdx.x * blockDim.x + threadIdx.x;
    if (t >= K * N) return;
    int k = t / N, n = t % N;
    WT[(size_t)n * K + k] = __float2half(W[t]);
}

// block-1 W1 transpose + fp16, rows k>=32 scaled by 2^13 (exact)
__global__ void tr_half192s_kernel(const float* __restrict__ W, __half* __restrict__ WT) {
    int t = blockIdx.x * blockDim.x + threadIdx.x;
    if (t >= 192 * 128) return;
    int k = t / 128, n = t % 128;
    float scl = (k >= 32) ? ASCL_UP : 1.0f;
    WT[(size_t)n * 192 + k] = __float2half(W[t] * scl);
}

// compact fp16 copy of xinv cols 0..31 -> g_xh[PE][32] (block 0)
__global__ void e_to_half_kernel() {
    int t = blockIdx.x * blockDim.x + threadIdx.x;
    if (t >= PE * 32) return;
    int p = t >> 5, c = t & 31;
    g_xh[t] = __float2half(g_xinv[(size_t)p * 192 + c]);
}

// e cols -> g_xh1[PE][192] cols 0..31 (block 1)
__global__ void e192_to_half_kernel() {
    int t = blockIdx.x * blockDim.x + threadIdx.x;
    if (t >= PE * 32) return;
    int p = t >> 5, c = t & 31;
    g_xh1[(size_t)p * 192 + c] = __float2half(g_xinv[(size_t)p * 192 + c]);
}

__global__ void copy_s_kernel(const float* __restrict__ features) {
    int t = blockIdx.x * blockDim.x + threadIdx.x;
    if (t < NA * FD) g_s[t] = features[t];
}

__global__ void compute_u_kernel(const float* __restrict__ vectors,
                                 const float* __restrict__ distances) {
    int t = blockIdx.x * blockDim.x + threadIdx.x;
    if (t >= PE * 3) return;
    int p = t / 3;
    g_u[t] = vectors[t] / (distances[p] + 0.001f);
}

__global__ void offsets_kernel(const int* __restrict__ idx_i) {
    int n = blockIdx.x * blockDim.x + threadIdx.x;
    if (n > NA) return;
    int lo = 0, hi = PE;
    while (lo < hi) {
        int mid = (lo + hi) >> 1;
        if (idx_i[mid] < n) lo = mid + 1; else hi = mid;
    }
    g_start[n] = lo;
}

// a-features -> g_xh1 cols 32..191 as fp16 scaled by 2^-13 (exact pow2)
__global__ void afeat_h_kernel(const int* __restrict__ idx_i,
                               const int* __restrict__ idx_j) {
    int t = blockIdx.x * blockDim.x + threadIdx.x;
    if (t >= PE * MD) return;
    int p = t / MD, mm = t % MD;
    const float* vi = g_vA + (size_t)idx_i[p] * 96;
    const float* vj = g_vA + (size_t)idx_j[p] * 96;
    float u0 = g_u[p * 3 + 0], u1 = g_u[p * 3 + 1], u2 = g_u[p * 3 + 2];
    float vi0 = vi[mm], vi1 = vi[32 + mm], vi2 = vi[64 + mm];
    float vj0 = vj[mm], vj1 = vj[32 + mm], vj2 = vj[64 + mm];
    __half* x = g_xh1 + (size_t)p * 192 + 32;
    x[mm]       = __float2half((u0 * vi0 + u1 * vi1 + u2 * vi2) * ASCL_DOWN);
    x[32 + mm]  = __float2half((u0 * vj0 + u1 * vj1 + u2 * vj2) * ASCL_DOWN);
    x[64 + mm]  = __float2half((vi0 * vj0 + vi1 * vj1 + vi2 * vj2) * ASCL_DOWN);
    x[96 + mm]  = __float2half((vi0 * vi0 + vi1 * vi1 + vi2 * vi2) * ASCL_DOWN);
    x[128 + mm] = __float2half((vj0 * vj0 + vj1 * vj1 + vj2 * vj2) * ASCL_DOWN);
}

__global__ void segsum_s_kernel() {
    int n = blockIdx.x, f = threadIdx.x;
    int p0 = g_start[n], p1 = g_start[n + 1];
    float acc = 0.0f;
    for (int p = p0; p < p1; p++) acc += g_m[(size_t)p * FD + f];
    g_s[n * FD + f] += acc;
}

__global__ void segsum_v0_kernel(const float* __restrict__ cut) {
    int n = blockIdx.x, t = threadIdx.x;
    int d = t / 32, mm = t % 32;
    int p0 = g_start[n], p1 = g_start[n + 1];
    float acc = 0.0f;
    for (int p = p0; p < p1; p++)
        acc += g_gbuf[(size_t)p * 64 + mm] * g_u[p * 3 + d] * cut[p];
    g_vA[n * 96 + t] = acc;
}

__global__ void segsum_v1_kernel(const float* __restrict__ cut,
                                 const int* __restrict__ idx_j) {
    int n = blockIdx.x, t = threadIdx.x;
    int d = t / 32, mm = t % 32;
    int p0 = g_start[n], p1 = g_start[n + 1];
    float acc = 0.0f;
    for (int p = p0; p < p1; p++) {
        float vjv = g_vA[(size_t)idx_j[p] * 96 + t];
        acc += (g_gbuf[(size_t)p * 64 + mm] * g_u[p * 3 + d]
              + g_gbuf[(size_t)p * 64 + 32 + mm] * vjv) * cut[p];
    }
    g_vB[n * 96 + t] = g_vA[n * 96 + t] + acc;
}

__global__ void copy_weff_kernel(const float* __restrict__ uW1) {
    int t = blockIdx.x * blockDim.x + threadIdx.x;
    if (t < FD * FD) g_weff[t] = uW1[t];
}

__global__ void copy_out_kernel(float* __restrict__ out) {
    int t = blockIdx.x * blockDim.x + threadIdx.x;
    const int SN = NA * FD, VN = NA * 3 * MD;
    if (t < SN) out[t] = g_s[t];
    else if (t < SN + VN) out[t] = g_vB[t - SN];
}

// ---------------- host ----------------
extern "C" void kernel_launch(void* const* d_in, const int* in_sizes, int n_in,
                              void* d_out, int out_size)
{
    const float* features  = (const float*)d_in[0];
    const float* distances = (const float*)d_in[1];
    const float* vectors   = (const float*)d_in[2];
    const float* cutoffs   = (const float*)d_in[3];
    const float* rbfs      = (const float*)d_in[4];
    const int*   idx_i     = (const int*)d_in[5];
    const int*   idx_j     = (const int*)d_in[6];
    const float* Wrbf      = (const float*)d_in[7];
    const float* Wemb      = (const float*)d_in[8];
    const float* eq0_W1    = (const float*)d_in[9];
    const float* eq0_b1    = (const float*)d_in[10];
    const float* eq0_W2    = (const float*)d_in[11];
    const float* eq1_W1    = (const float*)d_in[12];
    const float* eq1_b1    = (const float*)d_in[13];
    const float* eq1_W2    = (const float*)d_in[14];
    const float* inv_W1    = (const float*)d_in[15];
    const float* inv_b1    = (const float*)d_in[16];
    const float* inv_W2    = (const float*)d_in[17];
    const float* inv_b2    = (const float*)d_in[18];
    const float* upd_W1    = (const float*)d_in[19];
    const float* upd_b1    = (const float*)d_in[20];
    const float* upd_W2    = (const float*)d_in[21];
    const float* upd_b2    = (const float*)d_in[22];
    float* out = (float*)d_out;

    static bool attr_done = false;
    if (!attr_done) {
        cudaFuncSetAttribute(mlp_h0<64, 0>,
                             cudaFuncAttributeMaxDynamicSharedMemorySize, SMEM_EQ);
        cudaFuncSetAttribute(mlp_h0<128, FLAG_SILU | FLAG_CUT>,
                             cudaFuncAttributeMaxDynamicSharedMemorySize, SMEM_EQ);
        cudaFuncSetAttribute(mlp_b1<64, 0>,
                             cudaFuncAttributeMaxDynamicSharedMemorySize, SMEM_B1);
        cudaFuncSetAttribute(mlp_b1<128, FLAG_SILU | FLAG_CUT>,
                             cudaFuncAttributeMaxDynamicSharedMemorySize, SMEM_B1);
        attr_done = true;
    }

    void* tp;
    float *s, *xinv, *gb, *m, *Pei, *Pej, *Peqi, *Peqj, *Pinvi, *Pinvj;
    float *weff, *hu, *cew2, *cw2;
    __half *xh, *xh1, *tew1, *tew2, *tiw1, *tiw2, *tew1b, *tiw1b;
    cudaGetSymbolAddress(&tp, g_s);      s      = (float*)tp;
    cudaGetSymbolAddress(&tp, g_xinv);   xinv   = (float*)tp;
    cudaGetSymbolAddress(&tp, g_gbuf);   gb     = (float*)tp;
    cudaGetSymbolAddress(&tp, g_m);      m      = (float*)tp;
    cudaGetSymbolAddress(&tp, g_Pei);    Pei    = (float*)tp;
    cudaGetSymbolAddress(&tp, g_Pej);    Pej    = (float*)tp;
    cudaGetSymbolAddress(&tp, g_Peqi);   Peqi   = (float*)tp;
    cudaGetSymbolAddress(&tp, g_Peqj);   Peqj   = (float*)tp;
    cudaGetSymbolAddress(&tp, g_Pinvi);  Pinvi  = (float*)tp;
    cudaGetSymbolAddress(&tp, g_Pinvj);  Pinvj  = (float*)tp;
    cudaGetSymbolAddress(&tp, g_weff);   weff   = (float*)tp;
    cudaGetSymbolAddress(&tp, g_hu);     hu     = (float*)tp;
    cudaGetSymbolAddress(&tp, g_cew2);   cew2   = (float*)tp;
    cudaGetSymbolAddress(&tp, g_cw2);    cw2    = (float*)tp;
    cudaGetSymbolAddress(&tp, g_xh);     xh     = (__half*)tp;
    cudaGetSymbolAddress(&tp, g_xh1);    xh1    = (__half*)tp;
    cudaGetSymbolAddress(&tp, g_tew1);   tew1   = (__half*)tp;
    cudaGetSymbolAddress(&tp, g_tew2);   tew2   = (__half*)tp;
    cudaGetSymbolAddress(&tp, g_tiw1);   tiw1   = (__half*)tp;
    cudaGetSymbolAddress(&tp, g_tiw2);   tiw2   = (__half*)tp;
    cudaGetSymbolAddress(&tp, g_tew1b);  tew1b  = (__half*)tp;
    cudaGetSymbolAddress(&tp, g_tiw1b);  tiw1b  = (__half*)tp;

    copy_s_kernel<<<(NA * FD + 255) / 256, 256>>>(features);
    compute_u_kernel<<<(PE * 3 + 255) / 256, 256>>>(vectors, distances);
    offsets_kernel<<<(NA + 1 + 255) / 256, 256>>>(idx_i);

    const int gridN = (NA + 63) / 64;
    const int gridE = PE / 128;

    for (int b = 0; b < 2; b++) {
        const float* eqW1 = b ? eq1_W1 : eq0_W1;
        const float* eqb1 = b ? eq1_b1 : eq0_b1;
        const float* eqW2 = b ? eq1_W2 : eq0_W2;
        const int eq_si = b ? 192 : 32;
        const int eq_sj = b ? 320 : 160;
        const float* iW1 = inv_W1 + (size_t)b * 448 * 128;
        const float* ib1 = inv_b1 + b * 128;
        const float* iW2 = inv_W2 + (size_t)b * 128 * 128;
        const float* ib2 = inv_b2 + b * 128;
        const float* uW1 = upd_W1 + (size_t)b * 256 * 128;
        const float* ub1 = upd_b1 + b * 128;
        const float* uW2 = upd_W2 + (size_t)b * 128 * 128;
        const float* ub2 = upd_b2 + b * 128;

        // node projections, batched
        {
            PB4 p2; p2.W[0] = Wrbf + 64 * 32; p2.W[1] = Wrbf + 192 * 32;
            p2.C[0] = Pei; p2.C[1] = Pej;
            gemm_batch<64, 32><<<dim3(gridN, 2), 256>>>(s, FD, p2, 32, 32, NA, FD);

            PB4 p4;
            p4.W[0] = eqW1 + (size_t)eq_si * 128;
            p4.W[1] = eqW1 + (size_t)eq_sj * 128;
            p4.W[2] = iW1 + 192 * 128;
            p4.W[3] = iW1 + 320 * 128;
            p4.C[0] = Peqi; p4.C[1] = Peqj; p4.C[2] = Pinvi; p4.C[3] = Pinvj;
            gemm_batch<64, 128><<<dim3(gridN, 4), 256>>>(s, FD, p4, 128, 128, NA, FD);
        }

        if (b == 0) {
            tr_half_kernel<<<(32 * 128 + 255) / 256, 256>>>(eqW1, tew1, 32, 128);
            tr_half_kernel<<<(128 * 64 + 255) / 256, 256>>>(eqW2, tew2, 128, 64);
            tr_half_kernel<<<(32 * 128 + 255) / 256, 256>>>(iW1, tiw1, 32, 128);
            tr_half_kernel<<<(128 * 128 + 255) / 256, 256>>>(iW2, tiw2, 128, 128);
        } else {
            tr_half192s_kernel<<<(192 * 128 + 255) / 256, 256>>>(eqW1, tew1b);
            tr_half192s_kernel<<<(192 * 128 + 255) / 256, 256>>>(iW1, tiw1b);
            cvt_kernel<<<(128 * 64 + 255) / 256, 256>>>(eqW2, cew2, 128 * 64);
            cvt_kernel<<<(128 * 128 + 255) / 256, 256>>>(iW2, cw2, 128 * 128);
        }

        // e = rbfs @ Wrbf[0:64] + Pei[i] + Pej[j]  -> xinv cols 0..31 (tf32)
        gemm_single<128, 32><<<gridE, 256>>>(rbfs, RD, Wrbf, 32, xinv, 192, PE, RD,
                                             0, Pei, Pej, 32, idx_i, idx_j, 0, FLAG_TF32);

        if (b == 0) {
            e_to_half_kernel<<<(PE * 32 + 255) / 256, 256>>>();
            mlp_h0<64, 0><<<gridE, 256, SMEM_EQ>>>(
                xh, tew1, eqb1, Peqi, Peqj, idx_i, idx_j,
                tew2, (const float*)0, (const float*)0, gb, 64);
            mlp_h0<128, FLAG_SILU | FLAG_CUT><<<gridE, 256, SMEM_EQ>>>(
                xh, tiw1, ib1, Pinvi, Pinvj, idx_i, idx_j,
                tiw2, ib2, cutoffs, m, 128);
        } else {
            e192_to_half_kernel<<<(PE * 32 + 255) / 256, 256>>>();
            afeat_h_kernel<<<(PE * MD + 255) / 256, 256>>>(idx_i, idx_j);
            mlp_b1<64, 0><<<gridE, 256, SMEM_B1>>>(
                xh1, tew1b, eqb1, Peqi, Peqj, idx_i, idx_j,
                cew2, (const float*)0, (const float*)0, gb, 64);
            mlp_b1<128, FLAG_SILU | FLAG_CUT><<<gridE, 256, SMEM_B1>>>(
                xh1, tiw1b, ib1, Pinvi, Pinvj, idx_i, idx_j,
                cw2, ib2, cutoffs, m, 128);
        }

        if (b == 0) segsum_v0_kernel<<<NA, 96>>>(cutoffs);
        else        segsum_v1_kernel<<<NA, 96>>>(cutoffs, idx_j);
        segsum_s_kernel<<<NA, FD>>>();

        // node update: Weff = uW1a + Wemb @ uW1b ; s += silu(silu(s@Weff+b1)@uW2+b2)
        copy_weff_kernel<<<(FD * FD + 255) / 256, 256>>>(uW1);
        gemm_single<64, 128><<<2, 256>>>(Wemb, 128, uW1 + 128 * 128, 128, weff, 128,
                                         128, 128, 0, 0, 0, 0, 0, 0, 0, FLAG_RES);
        gemm_single<64, 128><<<gridN, 256>>>(s, FD, weff, 128, hu, 128, NA, FD,
                                             ub1, 0, 0, 0, 0, 0, 0, FLAG_SILU);
        gemm_single<64, 128><<<gridN, 256>>>(hu, FD, uW2, 128, s, 128, NA, FD,
                                             ub2, 0, 0, 0, 0, 0, 0, FLAG_SILU | FLAG_RES);
    }

    int total = NA * FD + NA * 3 * MD;
    copy_out_kernel<<<(total + 255) / 256, 256>>>(out);
}

// round 16
// speedup vs baseline: 1.1435x; 1.0247x over previous
#include <cuda_runtime.h>
#include <cuda_fp16.h>
#include <cstdint>
#include <cstddef>

#define NA 20000
#define PE 320000
#define FD 128
#define RD 64
#define MD 32

enum { FLAG_SILU = 1, FLAG_RES = 2, FLAG_CUT = 4, FLAG_TF32 = 8, FLAG_F16 = 16 };

#define ASCL_DOWN (1.0f / 8192.0f)   // a-feature scale 2^-13
#define ASCL_UP   8192.0f
#define HSCL_UP   128.0f             // hidden scale 2^7 (block-1 W2 pre-scale)

// ---------------- scratch (device globals; no runtime alloc) ----------------
__device__ float g_u[PE * 3];
__device__ float g_s[NA * FD];
__device__ float g_vA[NA * 3 * MD];
__device__ float g_vB[NA * 3 * MD];
__device__ int   g_start[NA + 1];
__device__ float g_gbuf[(size_t)PE * 64];
__device__ float g_m[(size_t)PE * FD];
__device__ float g_Pei[NA * MD];
__device__ float g_Pej[NA * MD];
__device__ float g_Peqi[NA * FD];
__device__ float g_Peqj[NA * FD];
__device__ float g_Pinvi[NA * FD];
__device__ float g_Pinvj[NA * FD];
__device__ float g_weff[FD * FD];
__device__ float g_hu[NA * FD];
// block-0 fp16 data (bounded range)
__device__ __align__(16) __half g_xh[(size_t)PE * 32];
__device__ __align__(16) __half g_tew1[128 * 32];
__device__ __align__(16) __half g_tew2[64 * 128];
__device__ __align__(16) __half g_tiw1[128 * 32];
__device__ __align__(16) __half g_tiw2[128 * 128];
// block-1 fp16 data (a-cols x 2^-13; W1 rows>=32 x 2^13; W2 x 2^7)
__device__ __align__(16) __half g_xh1[(size_t)PE * 192];
__device__ __align__(16) __half g_tew1b[128 * 192];
__device__ __align__(16) __half g_tew2b[64 * 128];
__device__ __align__(16) __half g_tiw1b[128 * 192];
__device__ __align__(16) __half g_tiw2b[128 * 128];

__device__ __forceinline__ float silu_f(float x) { return x / (1.0f + expf(-x)); }

__device__ __forceinline__ float f2tf(float f) {
    uint32_t u;
    asm("cvt.rna.tf32.f32 %0, %1;" : "=r"(u) : "f"(f));
    return __uint_as_float(u);
}

union U32H2 { uint32_t u; __half2 h; };
__device__ __forceinline__ uint32_t hld(const __half* p) {
    U32H2 x; x.h = *(const __half2*)p; return x.u;
}

__device__ __forceinline__ void mma_tf32(float c[4], const uint32_t a[4], const uint32_t b[2]) {
    asm volatile(
        "mma.sync.aligned.m16n8k8.row.col.f32.tf32.tf32.f32 "
        "{%0,%1,%2,%3}, {%4,%5,%6,%7}, {%8,%9}, {%0,%1,%2,%3};\n"
        : "+f"(c[0]), "+f"(c[1]), "+f"(c[2]), "+f"(c[3])
        : "r"(a[0]), "r"(a[1]), "r"(a[2]), "r"(a[3]), "r"(b[0]), "r"(b[1]));
}

__device__ __forceinline__ void mma_f16(float c[4], const uint32_t a[4], const uint32_t b[2]) {
    asm volatile(
        "mma.sync.aligned.m16n8k16.row.col.f32.f16.f16.f32 "
        "{%0,%1,%2,%3}, {%4,%5,%6,%7}, {%8,%9}, {%0,%1,%2,%3};\n"
        : "+f"(c[0]), "+f"(c[1]), "+f"(c[2]), "+f"(c[3])
        : "r"(a[0]), "r"(a[1]), "r"(a[2]), "r"(a[3]), "r"(b[0]), "r"(b[1]));
}

__device__ __forceinline__ uint32_t smem_u32(const void* p) {
    uint32_t a;
    asm("{ .reg .u64 t; cvta.to.shared.u64 t, %1; cvt.u32.u64 %0, t; }" : "=r"(a) : "l"(p));
    return a;
}

#define CPA16(dst, src) \
    asm volatile("cp.async.cg.shared.global [%0], [%1], 16;" :: "r"(dst), "l"(src))
#define CPA_COMMIT() asm volatile("cp.async.commit_group;" ::: "memory")
#define CPA_WAIT0()  asm volatile("cp.async.wait_group 0;" ::: "memory")

// ================= pipelined tf32 legacy GEMM (round 8 + F16 epilogue) =======
template <int BM, int BN>
__device__ __forceinline__ void gemm_body(
    const float* __restrict__ A, int lda,
    const float* __restrict__ W, int ldw,
    float* __restrict__ C, int ldc,
    int Mrows, int K,
    const float* __restrict__ bias,
    const float* __restrict__ Pi,
    const float* __restrict__ Pj, int ldp,
    const int* __restrict__ ii,
    const int* __restrict__ jj,
    const float* __restrict__ cut,
    int flags)
{
    constexpr int BK = 16;
    constexpr int MW = (BN >= 128) ? 2 : (BN == 64 ? 4 : (BM >= 128 ? 8 : 4));
    constexpr int NW = 8 / MW;
    constexpr int WM = BM / MW, WN = BN / NW;
    constexpr int MT = WM / 16, NT = WN / 8;
    constexpr int SAS = BM + 8, SBS = BN + 8;
    constexpr int A4 = (BM * 4) / 256;
    constexpr int B4N = BN / 4;
    constexpr int B4 = (BN * 4 + 255) / 256;
    constexpr bool BG = ((BN * 4) % 256) != 0;

    __shared__ float sA[2][BK][SAS];
    __shared__ float sB[2][BK][SBS];

    const int tid  = threadIdx.x;
    const int lane = tid & 31;
    const int wid  = tid >> 5;
    const int wm   = wid % MW;
    const int wn   = wid / MW;
    const int brow = blockIdx.x * BM;
    const int ar = lane >> 2, ac = lane & 3;

    float acc[MT][NT][4];
#pragma unroll
    for (int i = 0; i < MT; i++)
#pragma unroll
        for (int j = 0; j < NT; j++)
#pragma unroll
            for (int r = 0; r < 4; r++) acc[i][j][r] = 0.0f;

    float4 ra[A4], rb[B4];
    const int nIter = K / BK;

#pragma unroll
    for (int i = 0; i < A4; i++) {
        int q = tid + i * 256, m = q >> 2, kq = q & 3;
        int row = brow + m;
        ra[i] = (row < Mrows) ? *(const float4*)&A[(size_t)row * lda + 4 * kq]
                              : make_float4(0.f, 0.f, 0.f, 0.f);
    }
#pragma unroll
    for (int i = 0; i < B4; i++) {
        int q = tid + i * 256;
        if (!BG || q < BN * 4) {
            int kk = q / B4N, c4 = (q % B4N) * 4;
            rb[i] = *(const float4*)&W[(size_t)kk * ldw + c4];
        }
    }

    for (int it = 0; it < nIter; ++it) {
        int buf = it & 1;
#pragma unroll
        for (int i = 0; i < A4; i++) {
            int q = tid + i * 256, m = q >> 2, kq = q & 3;
            sA[buf][4 * kq + 0][m] = f2tf(ra[i].x);
            sA[buf][4 * kq + 1][m] = f2tf(ra[i].y);
            sA[buf][4 * kq + 2][m] = f2tf(ra[i].z);
            sA[buf][4 * kq + 3][m] = f2tf(ra[i].w);
        }
#pragma unroll
        for (int i = 0; i < B4; i++) {
            int q = tid + i * 256;
            if (!BG || q < BN * 4) {
                int kk = q / B4N, c4 = (q % B4N) * 4;
                float4 v;
                v.x = f2tf(rb[i].x); v.y = f2tf(rb[i].y);
                v.z = f2tf(rb[i].z); v.w = f2tf(rb[i].w);
                *(float4*)&sB[buf][kk][c4] = v;
            }
        }
        __syncthreads();
        if (it + 1 < nIter) {
            int k0 = (it + 1) * BK;
#pragma unroll
            for (int i = 0; i < A4; i++) {
                int q = tid + i * 256, m = q >> 2, kq = q & 3;
                int row = brow + m;
                ra[i] = (row < Mrows) ? *(const float4*)&A[(size_t)row * lda + k0 + 4 * kq]
                                      : make_float4(0.f, 0.f, 0.f, 0.f);
            }
#pragma unroll
            for (int i = 0; i < B4; i++) {
                int q = tid + i * 256;
                if (!BG || q < BN * 4) {
                    int kk = q / B4N, c4 = (q % B4N) * 4;
                    rb[i] = *(const float4*)&W[(size_t)(k0 + kk) * ldw + c4];
                }
            }
        }
#pragma unroll
        for (int kk = 0; kk < BK; kk += 8) {
            uint32_t afr[MT][4], bfr[NT][2];
#pragma unroll
            for (int mt = 0; mt < MT; mt++) {
                int bm = wm * WM + mt * 16;
                afr[mt][0] = __float_as_uint(sA[buf][kk + ac][bm + ar]);
                afr[mt][1] = __float_as_uint(sA[buf][kk + ac][bm + ar + 8]);
                afr[mt][2] = __float_as_uint(sA[buf][kk + ac + 4][bm + ar]);
                afr[mt][3] = __float_as_uint(sA[buf][kk + ac + 4][bm + ar + 8]);
            }
#pragma unroll
            for (int nt = 0; nt < NT; nt++) {
                int bn = wn * WN + nt * 8;
                bfr[nt][0] = __float_as_uint(sB[buf][kk + ac][bn + ar]);
                bfr[nt][1] = __float_as_uint(sB[buf][kk + ac + 4][bn + ar]);
            }
#pragma unroll
            for (int mt = 0; mt < MT; mt++)
#pragma unroll
                for (int nt = 0; nt < NT; nt++)
                    mma_tf32(acc[mt][nt], afr[mt], bfr[nt]);
        }
    }

#pragma unroll
    for (int mt = 0; mt < MT; mt++) {
#pragma unroll
        for (int h = 0; h < 2; h++) {
            int r = wm * WM + mt * 16 + ar + 8 * h;
            int row = brow + r;
            if (row >= Mrows) continue;
            int pii = 0, pjj = 0;
            if (Pi) { pii = ii[row]; pjj = jj[row]; }
            float cv = (flags & FLAG_CUT) ? cut[row] : 1.0f;
#pragma unroll
            for (int nt = 0; nt < NT; nt++) {
                int col = wn * WN + nt * 8 + ac * 2;
#pragma unroll
                for (int e = 0; e < 2; e++) {
                    int c = col + e;
                    float v = acc[mt][nt][2 * h + e];
                    if (bias) v += bias[c];
                    if (Pi) v += Pi[(size_t)pii * ldp + c] + Pj[(size_t)pjj * ldp + c];
                    if (flags & FLAG_SILU) v = silu_f(v);
                    v *= cv;
                    if (flags & FLAG_F16) {
                        ((__half*)C)[(size_t)row * ldc + c] = __float2half(v);
                    } else {
                        if (flags & FLAG_TF32) v = f2tf(v);
                        float* cp = &C[(size_t)row * ldc + c];
                        if (flags & FLAG_RES) *cp += v; else *cp = v;
                    }
                }
            }
        }
    }
}

template <int BM, int BN>
__global__ void __launch_bounds__(256) gemm_single(
    const float* __restrict__ A, int lda, const float* __restrict__ W, int ldw,
    float* __restrict__ C, int ldc, int Mrows, int K,
    const float* __restrict__ bias, const float* __restrict__ Pi,
    const float* __restrict__ Pj, int ldp, const int* __restrict__ ii,
    const int* __restrict__ jj, const float* __restrict__ cut, int flags)
{
    gemm_body<BM, BN>(A, lda, W, ldw, C, ldc, Mrows, K, bias, Pi, Pj, ldp, ii, jj, cut, flags);
}

struct PB4 { const float* W[4]; float* C[4]; };

template <int BM, int BN>
__global__ void __launch_bounds__(256) gemm_batch(
    const float* __restrict__ A, int lda, PB4 p, int ldw, int ldc, int Mrows, int K)
{
    gemm_body<BM, BN>(A, lda, p.W[blockIdx.y], ldw, p.C[blockIdx.y], ldc,
                      Mrows, K, 0, 0, 0, 0, 0, 0, 0, 0);
}

// ================= unified fp16 fused 2-layer edge MLP =======================
// X [PE][K1] fp16 (K1=32 compact, K1=192 full/scaled); W1T [128][K1] fp16;
// W2T [N2][128] fp16 (pre-scaled x 2^HSHIFT). Hidden stored x 2^-HSHIFT.
// smem: sA 2x[128][40]h, sB 2x[128][40]h, sHb [128][136]h  = 75776 B.
#define SMEM_H (20480 + 20480 + 34816)

template <int K1, int N2, int FLAGS2, int HSHIFT>
__global__ void __launch_bounds__(256, 2) mlp_h(
    const __half* __restrict__ X, int ldx,
    const __half* __restrict__ W1T,
    const float* __restrict__ b1v,
    const float* __restrict__ Pi, const float* __restrict__ Pj,
    const int* __restrict__ ii, const int* __restrict__ jj,
    const __half* __restrict__ W2T,
    const float* __restrict__ b2v,
    const float* __restrict__ cut,
    float* __restrict__ C, int ldc)
{
    extern __shared__ char dsmc[];
    __half* sA0 = (__half*)dsmc;
    __half* sB0 = (__half*)(dsmc + 20480);
    __half* sHb = (__half*)(dsmc + 40960);

    const int tid = threadIdx.x, lane = tid & 31, wid = tid >> 5;
    const int brow = blockIdx.x * 128;
    const int ar = lane >> 2, ac = lane & 3;
    const uint32_t sAu = smem_u32(sA0);
    const uint32_t sBu = smem_u32(sB0);
    constexpr float HS = 1.0f / (float)(1 << HSHIFT);

    const int wm = wid & 1, wn = wid >> 1;

    // ---- phase 1: hidden = silu(X@W1 + Pi+Pj+b1) ----
    {
        float acc[4][4][4];
#pragma unroll
        for (int i = 0; i < 4; i++)
#pragma unroll
            for (int j = 0; j < 4; j++)
#pragma unroll
                for (int r = 0; r < 4; r++) acc[i][j][r] = 0.0f;

        if (K1 == 32) {
            // single chunk, plain staging (validated round 14)
            uint4 ra[2], rb[2];
#pragma unroll
            for (int i = 0; i < 2; i++) {
                int q = tid + i * 256, row = q >> 2, seg = q & 3;
                ra[i] = *(const uint4*)&X[(size_t)(brow + row) * ldx + seg * 8];
            }
#pragma unroll
            for (int i = 0; i < 2; i++) {
                int q = tid + i * 256, n = q >> 2, seg = q & 3;
                rb[i] = *(const uint4*)&W1T[(size_t)n * K1 + seg * 8];
            }
#pragma unroll
            for (int i = 0; i < 2; i++) {
                int q = tid + i * 256, row = q >> 2, seg = q & 3;
                *(uint4*)&sA0[row * 40 + seg * 8] = ra[i];
            }
#pragma unroll
            for (int i = 0; i < 2; i++) {
                int q = tid + i * 256, n = q >> 2, seg = q & 3;
                *(uint4*)&sB0[n * 40 + seg * 8] = rb[i];
            }
            __syncthreads();
#pragma unroll
            for (int kk = 0; kk < 32; kk += 16) {
                uint32_t afr[4][4], bfr[4][2];
#pragma unroll
                for (int mt = 0; mt < 4; mt++) {
                    int bm = wm * 64 + mt * 16;
                    afr[mt][0] = hld(&sA0[(bm + ar) * 40 + kk + ac * 2]);
                    afr[mt][1] = hld(&sA0[(bm + ar + 8) * 40 + kk + ac * 2]);
                    afr[mt][2] = hld(&sA0[(bm + ar) * 40 + kk + ac * 2 + 8]);
                    afr[mt][3] = hld(&sA0[(bm + ar + 8) * 40 + kk + ac * 2 + 8]);
                }
#pragma unroll
                for (int nt = 0; nt < 4; nt++) {
                    int bn = wn * 32 + nt * 8;
                    bfr[nt][0] = hld(&sB0[(bn + ar) * 40 + kk + ac * 2]);
                    bfr[nt][1] = hld(&sB0[(bn + ar) * 40 + kk + ac * 2 + 8]);
                }
#pragma unroll
                for (int mt = 0; mt < 4; mt++)
#pragma unroll
                    for (int nt = 0; nt < 4; nt++)
                        mma_f16(acc[mt][nt], afr[mt], bfr[nt]);
            }
        } else {
            // multi-chunk cp.async pipeline (validated round 15)
#pragma unroll
            for (int i = 0; i < 2; i++) {
                int q = tid + i * 256, row = q >> 2, seg = q & 3;
                CPA16(sAu + (uint32_t)(row * 80 + seg * 16),
                      &X[(size_t)(brow + row) * ldx + seg * 8]);
            }
#pragma unroll
            for (int i = 0; i < 2; i++) {
                int q = tid + i * 256, n = q >> 2, seg = q & 3;
                CPA16(sBu + (uint32_t)(n * 80 + seg * 16),
                      &W1T[(size_t)n * K1 + seg * 8]);
            }
            CPA_COMMIT();

            constexpr int nIt1 = K1 / 32;
            for (int it = 0; it < nIt1; ++it) {
                CPA_WAIT0();
                __syncthreads();
                if (it + 1 < nIt1) {
                    int k0 = (it + 1) * 32;
                    uint32_t nb = (uint32_t)((it + 1) & 1);
#pragma unroll
                    for (int i = 0; i < 2; i++) {
                        int q = tid + i * 256, row = q >> 2, seg = q & 3;
                        CPA16(sAu + nb * 10240u + (uint32_t)(row * 80 + seg * 16),
                              &X[(size_t)(brow + row) * ldx + k0 + seg * 8]);
                    }
#pragma unroll
                    for (int i = 0; i < 2; i++) {
                        int q = tid + i * 256, n = q >> 2, seg = q & 3;
                        CPA16(sBu + nb * 10240u + (uint32_t)(n * 80 + seg * 16),
                              &W1T[(size_t)n * K1 + k0 + seg * 8]);
                    }
                    CPA_COMMIT();
                }
                const __half* cA = sA0 + (it & 1) * 5120;
                const __half* cB = sB0 + (it & 1) * 5120;
#pragma unroll
                for (int kk = 0; kk < 32; kk += 16) {
                    uint32_t afr[4][4], bfr[4][2];
#pragma unroll
                    for (int mt = 0; mt < 4; mt++) {
                        int bm = wm * 64 + mt * 16;
                        afr[mt][0] = hld(&cA[(bm + ar) * 40 + kk + ac * 2]);
                        afr[mt][1] = hld(&cA[(bm + ar + 8) * 40 + kk + ac * 2]);
                        afr[mt][2] = hld(&cA[(bm + ar) * 40 + kk + ac * 2 + 8]);
                        afr[mt][3] = hld(&cA[(bm + ar + 8) * 40 + kk + ac * 2 + 8]);
                    }
#pragma unroll
                    for (int nt = 0; nt < 4; nt++) {
                        int bn = wn * 32 + nt * 8;
                        bfr[nt][0] = hld(&cB[(bn + ar) * 40 + kk + ac * 2]);
                        bfr[nt][1] = hld(&cB[(bn + ar) * 40 + kk + ac * 2 + 8]);
                    }
#pragma unroll
                    for (int mt = 0; mt < 4; mt++)
#pragma unroll
                        for (int nt = 0; nt < 4; nt++)
                            mma_f16(acc[mt][nt], afr[mt], bfr[nt]);
                }
            }
        }

        // epilogue 1: sHb = half(silu(acc + Pi[ii] + Pj[jj] + b1) * HS)
#pragma unroll
        for (int mt = 0; mt < 4; mt++)
#pragma unroll
            for (int h = 0; h < 2; h++) {
                int r = wm * 64 + mt * 16 + ar + 8 * h;
                int row = brow + r;
                int pii = ii[row], pjj = jj[row];
                const float* pi = Pi + (size_t)pii * 128;
                const float* pj = Pj + (size_t)pjj * 128;
#pragma unroll
                for (int nt = 0; nt < 4; nt++) {
                    int c = wn * 32 + nt * 8 + ac * 2;
                    float2 a = *(const float2*)&pi[c];
                    float2 b = *(const float2*)&pj[c];
                    float2 bb = *(const float2*)&b1v[c];
                    float v0 = silu_f(acc[mt][nt][2 * h + 0] + a.x + b.x + bb.x) * HS;
                    float v1 = silu_f(acc[mt][nt][2 * h + 1] + a.y + b.y + bb.y) * HS;
                    *(__half2*)&sHb[r * 136 + c] = __floats2half2_rn(v0, v1);
                }
            }
    }
    __syncthreads();

    // ---- phase 2: out = epi2(hidden @ W2), K=128, cp.async W2 pipeline ----
    {
        constexpr int MW2 = (N2 == 128) ? 2 : 4;
        constexpr int WM2 = 128 / MW2;
        constexpr int WN2 = 32;
        constexpr int MT2 = WM2 / 16;
        constexpr int NT2 = 4;
        constexpr int NCH = N2 / 64;
        const int wm2 = wid % MW2, wn2 = wid / MW2;

#pragma unroll
        for (int i = 0; i < NCH; i++) {
            int q = tid + i * 256, n = q >> 2, seg = q & 3;
            CPA16(sBu + (uint32_t)(n * 80 + seg * 16),
                  &W2T[(size_t)n * 128 + seg * 8]);
        }
        CPA_COMMIT();

        float acc2[MT2][NT2][4];
#pragma unroll
        for (int i = 0; i < MT2; i++)
#pragma unroll
            for (int j = 0; j < NT2; j++)
#pragma unroll
                for (int r = 0; r < 4; r++) acc2[i][j][r] = 0.0f;

        for (int it = 0; it < 4; ++it) {
            CPA_WAIT0();
            __syncthreads();
            if (it < 3) {
                int k0 = (it + 1) * 32;
                uint32_t nb = (uint32_t)((it + 1) & 1);
#pragma unroll
                for (int i = 0; i < NCH; i++) {
                    int q = tid + i * 256, n = q >> 2, seg = q & 3;
                    CPA16(sBu + nb * 10240u + (uint32_t)(n * 80 + seg * 16),
                          &W2T[(size_t)n * 128 + k0 + seg * 8]);
                }
                CPA_COMMIT();
            }
            const __half* cB = sB0 + (it & 1) * 5120;
#pragma unroll
            for (int kk = 0; kk < 32; kk += 16) {
                int k = it * 32 + kk;
                uint32_t afr[MT2][4], bfr[NT2][2];
#pragma unroll
                for (int mt = 0; mt < MT2; mt++) {
                    int bm = wm2 * WM2 + mt * 16;
                    afr[mt][0] = hld(&sHb[(bm + ar) * 136 + k + ac * 2]);
                    afr[mt][1] = hld(&sHb[(bm + ar + 8) * 136 + k + ac * 2]);
                    afr[mt][2] = hld(&sHb[(bm + ar) * 136 + k + ac * 2 + 8]);
                    afr[mt][3] = hld(&sHb[(bm + ar + 8) * 136 + k + ac * 2 + 8]);
                }
#pragma unroll
                for (int nt = 0; nt < NT2; nt++) {
                    int bn = wn2 * WN2 + nt * 8;
                    bfr[nt][0] = hld(&cB[(bn + ar) * 40 + kk + ac * 2]);
                    bfr[nt][1] = hld(&cB[(bn + ar) * 40 + kk + ac * 2 + 8]);
                }
#pragma unroll
                for (int mt = 0; mt < MT2; mt++)
#pragma unroll
                    for (int nt = 0; nt < NT2; nt++)
                        mma_f16(acc2[mt][nt], afr[mt], bfr[nt]);
            }
        }
#pragma unroll
        for (int mt = 0; mt < MT2; mt++)
#pragma unroll
            for (int h = 0; h < 2; h++) {
                int r = wm2 * WM2 + mt * 16 + ar + 8 * h;
                int row = brow + r;
                float cv = (FLAGS2 & FLAG_CUT) ? cut[row] : 1.0f;
#pragma unroll
                for (int nt = 0; nt < NT2; nt++)
#pragma unroll
                    for (int e = 0; e < 2; e++) {
                        int c = wn2 * WN2 + nt * 8 + ac * 2 + e;
                        float v = acc2[mt][nt][2 * h + e];
                        if (b2v) v += b2v[c];
                        if (FLAGS2 & FLAG_SILU) v = silu_f(v);
                        v *= cv;
                        C[(size_t)row * ldc + c] = v;
                    }
            }
    }
}

// ---------------- small kernels ----------------
__global__ void tr_half_kernel(const float* __restrict__ W, __half* __restrict__ WT,
                               int K, int N) {
    int t = blockIdx.x * blockDim.x + threadIdx.x;
    if (t >= K * N) return;
    int k = t / N, n = t % N;
    WT[(size_t)n * K + k] = __float2half(W[t]);
}

// block-1 W1: transpose + fp16, rows k>=32 scaled by 2^13
__global__ void tr_half192s_kernel(const float* __restrict__ W, __half* __restrict__ WT) {
    int t = blockIdx.x * blockDim.x + threadIdx.x;
    if (t >= 192 * 128) return;
    int k = t / 128, n = t % 128;
    float scl = (k >= 32) ? ASCL_UP : 1.0f;
    WT[(size_t)n * 192 + k] = __float2half(W[t] * scl);
}

// block-1 W2: transpose + fp16, scaled by 2^7 (hidden is stored x 2^-7)
__global__ void tr_half_w2s_kernel(const float* __restrict__ W, __half* __restrict__ WT,
                                   int N2) {
    int t = blockIdx.x * blockDim.x + threadIdx.x;
    if (t >= 128 * N2) return;
    int k = t / N2, n = t % N2;
    WT[(size_t)n * 128 + k] = __float2half(W[t] * HSCL_UP);
}

__global__ void copy_s_kernel(const float* __restrict__ features) {
    int t = blockIdx.x * blockDim.x + threadIdx.x;
    if (t < NA * FD) g_s[t] = features[t];
}

__global__ void compute_u_kernel(const float* __restrict__ vectors,
                                 const float* __restrict__ distances) {
    int t = blockIdx.x * blockDim.x + threadIdx.x;
    if (t >= PE * 3) return;
    int p = t / 3;
    g_u[t] = vectors[t] / (distances[p] + 0.001f);
}

__global__ void offsets_kernel(const int* __restrict__ idx_i) {
    int n = blockIdx.x * blockDim.x + threadIdx.x;
    if (n > NA) return;
    int lo = 0, hi = PE;
    while (lo < hi) {
        int mid = (lo + hi) >> 1;
        if (idx_i[mid] < n) lo = mid + 1; else hi = mid;
    }
    g_start[n] = lo;
}

// a-features -> g_xh1 cols 32..191 fp16 scaled 2^-13
__global__ void afeat_h_kernel(const int* __restrict__ idx_i,
                               const int* __restrict__ idx_j) {
    int t = blockIdx.x * blockDim.x + threadIdx.x;
    if (t >= PE * MD) return;
    int p = t / MD, mm = t % MD;
    const float* vi = g_vA + (size_t)idx_i[p] * 96;
    const float* vj = g_vA + (size_t)idx_j[p] * 96;
    float u0 = g_u[p * 3 + 0], u1 = g_u[p * 3 + 1], u2 = g_u[p * 3 + 2];
    float vi0 = vi[mm], vi1 = vi[32 + mm], vi2 = vi[64 + mm];
    float vj0 = vj[mm], vj1 = vj[32 + mm], vj2 = vj[64 + mm];
    __half* x = g_xh1 + (size_t)p * 192 + 32;
    x[mm]       = __float2half((u0 * vi0 + u1 * vi1 + u2 * vi2) * ASCL_DOWN);
    x[32 + mm]  = __float2half((u0 * vj0 + u1 * vj1 + u2 * vj2) * ASCL_DOWN);
    x[64 + mm]  = __float2half((vi0 * vj0 + vi1 * vj1 + vi2 * vj2) * ASCL_DOWN);
    x[96 + mm]  = __float2half((vi0 * vi0 + vi1 * vi1 + vi2 * vi2) * ASCL_DOWN);
    x[128 + mm] = __float2half((vj0 * vj0 + vj1 * vj1 + vj2 * vj2) * ASCL_DOWN);
}

__global__ void segsum_s_kernel() {
    int n = blockIdx.x, f = threadIdx.x;
    int p0 = g_start[n], p1 = g_start[n + 1];
    float acc = 0.0f;
    for (int p = p0; p < p1; p++) acc += g_m[(size_t)p * FD + f];
    g_s[n * FD + f] += acc;
}

__global__ void segsum_v0_kernel(const float* __restrict__ cut) {
    int n = blockIdx.x, t = threadIdx.x;
    int d = t / 32, mm = t % 32;
    int p0 = g_start[n], p1 = g_start[n + 1];
    float acc = 0.0f;
    for (int p = p0; p < p1; p++)
        acc += g_gbuf[(size_t)p * 64 + mm] * g_u[p * 3 + d] * cut[p];
    g_vA[n * 96 + t] = acc;
}

__global__ void segsum_v1_kernel(const float* __restrict__ cut,
                                 const int* __restrict__ idx_j) {
    int n = blockIdx.x, t = threadIdx.x;
    int d = t / 32, mm = t % 32;
    int p0 = g_start[n], p1 = g_start[n + 1];
    float acc = 0.0f;
    for (int p = p0; p < p1; p++) {
        float vjv = g_vA[(size_t)idx_j[p] * 96 + t];
        acc += (g_gbuf[(size_t)p * 64 + mm] * g_u[p * 3 + d]
              + g_gbuf[(size_t)p * 64 + 32 + mm] * vjv) * cut[p];
    }
    g_vB[n * 96 + t] = g_vA[n * 96 + t] + acc;
}

__global__ void copy_weff_kernel(const float* __restrict__ uW1) {
    int t = blockIdx.x * blockDim.x + threadIdx.x;
    if (t < FD * FD) g_weff[t] = uW1[t];
}

__global__ void copy_out_kernel(float* __restrict__ out) {
    int t = blockIdx.x * blockDim.x + threadIdx.x;
    const int SN = NA * FD, VN = NA * 3 * MD;
    if (t < SN) out[t] = g_s[t];
    else if (t < SN + VN) out[t] = g_vB[t - SN];
}

// ---------------- host ----------------
extern "C" void kernel_launch(void* const* d_in, const int* in_sizes, int n_in,
                              void* d_out, int out_size)
{
    const float* features  = (const float*)d_in[0];
    const float* distances = (const float*)d_in[1];
    const float* vectors   = (const float*)d_in[2];
    const float* cutoffs   = (const float*)d_in[3];
    const float* rbfs      = (const float*)d_in[4];
    const int*   idx_i     = (const int*)d_in[5];
    const int*   idx_j     = (const int*)d_in[6];
    const float* Wrbf      = (const float*)d_in[7];
    const float* Wemb      = (const float*)d_in[8];
    const float* eq0_W1    = (const float*)d_in[9];
    const float* eq0_b1    = (const float*)d_in[10];
    const float* eq0_W2    = (const float*)d_in[11];
    const float* eq1_W1    = (const float*)d_in[12];
    const float* eq1_b1    = (const float*)d_in[13];
    const float* eq1_W2    = (const float*)d_in[14];
    const float* inv_W1    = (const float*)d_in[15];
    const float* inv_b1    = (const float*)d_in[16];
    const float* inv_W2    = (const float*)d_in[17];
    const float* inv_b2    = (const float*)d_in[18];
    const float* upd_W1    = (const float*)d_in[19];
    const float* upd_b1    = (const float*)d_in[20];
    const float* upd_W2    = (const float*)d_in[21];
    const float* upd_b2    = (const float*)d_in[22];
    float* out = (float*)d_out;

    static bool attr_done = false;
    if (!attr_done) {
        cudaFuncSetAttribute(mlp_h<32, 64, 0, 0>,
                             cudaFuncAttributeMaxDynamicSharedMemorySize, SMEM_H);
        cudaFuncSetAttribute(mlp_h<32, 128, FLAG_SILU | FLAG_CUT, 0>,
                             cudaFuncAttributeMaxDynamicSharedMemorySize, SMEM_H);
        cudaFuncSetAttribute(mlp_h<192, 64, 0, 7>,
                             cudaFuncAttributeMaxDynamicSharedMemorySize, SMEM_H);
        cudaFuncSetAttribute(mlp_h<192, 128, FLAG_SILU | FLAG_CUT, 7>,
                             cudaFuncAttributeMaxDynamicSharedMemorySize, SMEM_H);
        attr_done = true;
    }

    void* tp;
    float *s, *gb, *m, *Pei, *Pej, *Peqi, *Peqj, *Pinvi, *Pinvj;
    float *weff, *hu;
    __half *xh, *xh1, *tew1, *tew2, *tiw1, *tiw2, *tew1b, *tew2b, *tiw1b, *tiw2b;
    cudaGetSymbolAddress(&tp, g_s);      s      = (float*)tp;
    cudaGetSymbolAddress(&tp, g_gbuf);   gb     = (float*)tp;
    cudaGetSymbolAddress(&tp, g_m);      m      = (float*)tp;
    cudaGetSymbolAddress(&tp, g_Pei);    Pei    = (float*)tp;
    cudaGetSymbolAddress(&tp, g_Pej);    Pej    = (float*)tp;
    cudaGetSymbolAddress(&tp, g_Peqi);   Peqi   = (float*)tp;
    cudaGetSymbolAddress(&tp, g_Peqj);   Peqj   = (float*)tp;
    cudaGetSymbolAddress(&tp, g_Pinvi);  Pinvi  = (float*)tp;
    cudaGetSymbolAddress(&tp, g_Pinvj);  Pinvj  = (float*)tp;
    cudaGetSymbolAddress(&tp, g_weff);   weff   = (float*)tp;
    cudaGetSymbolAddress(&tp, g_hu);     hu     = (float*)tp;
    cudaGetSymbolAddress(&tp, g_xh);     xh     = (__half*)tp;
    cudaGetSymbolAddress(&tp, g_xh1);    xh1    = (__half*)tp;
    cudaGetSymbolAddress(&tp, g_tew1);   tew1   = (__half*)tp;
    cudaGetSymbolAddress(&tp, g_tew2);   tew2   = (__half*)tp;
    cudaGetSymbolAddress(&tp, g_tiw1);   tiw1   = (__half*)tp;
    cudaGetSymbolAddress(&tp, g_tiw2);   tiw2   = (__half*)tp;
    cudaGetSymbolAddress(&tp, g_tew1b);  tew1b  = (__half*)tp;
    cudaGetSymbolAddress(&tp, g_tew2b);  tew2b  = (__half*)tp;
    cudaGetSymbolAddress(&tp, g_tiw1b);  tiw1b  = (__half*)tp;
    cudaGetSymbolAddress(&tp, g_tiw2b);  tiw2b  = (__half*)tp;

    copy_s_kernel<<<(NA * FD + 255) / 256, 256>>>(features);
    compute_u_kernel<<<(PE * 3 + 255) / 256, 256>>>(vectors, distances);
    offsets_kernel<<<(NA + 1 + 255) / 256, 256>>>(idx_i);

    const int gridN = (NA + 63) / 64;
    const int gridE = PE / 128;

    for (int b = 0; b < 2; b++) {
        const float* eqW1 = b ? eq1_W1 : eq0_W1;
        const float* eqb1 = b ? eq1_b1 : eq0_b1;
        const float* eqW2 = b ? eq1_W2 : eq0_W2;
        const int eq_si = b ? 192 : 32;
        const int eq_sj = b ? 320 : 160;
        const float* iW1 = inv_W1 + (size_t)b * 448 * 128;
        const float* ib1 = inv_b1 + b * 128;
        const float* iW2 = inv_W2 + (size_t)b * 128 * 128;
        const float* ib2 = inv_b2 + b * 128;
        const float* uW1 = upd_W1 + (size_t)b * 256 * 128;
        const float* ub1 = upd_b1 + b * 128;
        const float* uW2 = upd_W2 + (size_t)b * 128 * 128;
        const float* ub2 = upd_b2 + b * 128;

        // node projections, batched
        {
            PB4 p2; p2.W[0] = Wrbf + 64 * 32; p2.W[1] = Wrbf + 192 * 32;
            p2.C[0] = Pei; p2.C[1] = Pej;
            gemm_batch<64, 32><<<dim3(gridN, 2), 256>>>(s, FD, p2, 32, 32, NA, FD);

            PB4 p4;
            p4.W[0] = eqW1 + (size_t)eq_si * 128;
            p4.W[1] = eqW1 + (size_t)eq_sj * 128;
            p4.W[2] = iW1 + 192 * 128;
            p4.W[3] = iW1 + 320 * 128;
            p4.C[0] = Peqi; p4.C[1] = Peqj; p4.C[2] = Pinvi; p4.C[3] = Pinvj;
            gemm_batch<64, 128><<<dim3(gridN, 4), 256>>>(s, FD, p4, 128, 128, NA, FD);
        }

        if (b == 0) {
            tr_half_kernel<<<(32 * 128 + 255) / 256, 256>>>(eqW1, tew1, 32, 128);
            tr_half_kernel<<<(128 * 64 + 255) / 256, 256>>>(eqW2, tew2, 128, 64);
            tr_half_kernel<<<(32 * 128 + 255) / 256, 256>>>(iW1, tiw1, 32, 128);
            tr_half_kernel<<<(128 * 128 + 255) / 256, 256>>>(iW2, tiw2, 128, 128);
        } else {
            tr_half192s_kernel<<<(192 * 128 + 255) / 256, 256>>>(eqW1, tew1b);
            tr_half192s_kernel<<<(192 * 128 + 255) / 256, 256>>>(iW1, tiw1b);
            tr_half_w2s_kernel<<<(128 * 64 + 255) / 256, 256>>>(eqW2, tew2b, 64);
            tr_half_w2s_kernel<<<(128 * 128 + 255) / 256, 256>>>(iW2, tiw2b, 128);
        }

        // e = rbfs @ Wrbf[0:64] + Pei[i] + Pej[j]  -> fp16 X directly
        if (b == 0)
            gemm_single<128, 32><<<gridE, 256>>>(rbfs, RD, Wrbf, 32, (float*)xh, 32,
                                                 PE, RD, 0, Pei, Pej, 32,
                                                 idx_i, idx_j, 0, FLAG_F16);
        else
            gemm_single<128, 32><<<gridE, 256>>>(rbfs, RD, Wrbf, 32, (float*)xh1, 192,
                                                 PE, RD, 0, Pei, Pej, 32,
                                                 idx_i, idx_j, 0, FLAG_F16);

        if (b == 0) {
            mlp_h<32, 64, 0, 0><<<gridE, 256, SMEM_H>>>(
                xh, 32, tew1, eqb1, Peqi, Peqj, idx_i, idx_j,
                tew2, (const float*)0, (const float*)0, gb, 64);
            mlp_h<32, 128, FLAG_SILU | FLAG_CUT, 0><<<gridE, 256, SMEM_H>>>(
                xh, 32, tiw1, ib1, Pinvi, Pinvj, idx_i, idx_j,
                tiw2, ib2, cutoffs, m, 128);
        } else {
            afeat_h_kernel<<<(PE * MD + 255) / 256, 256>>>(idx_i, idx_j);
            mlp_h<192, 64, 0, 7><<<gridE, 256, SMEM_H>>>(
                xh1, 192, tew1b, eqb1, Peqi, Peqj, idx_i, idx_j,
                tew2b, (const float*)0, (const float*)0, gb, 64);
            mlp_h<192, 128, FLAG_SILU | FLAG_CUT, 7><<<gridE, 256, SMEM_H>>>(
                xh1, 192, tiw1b, ib1, Pinvi, Pinvj, idx_i, idx_j,
                tiw2b, ib2, cutoffs, m, 128);
        }

        if (b == 0) segsum_v0_kernel<<<NA, 96>>>(cutoffs);
        else        segsum_v1_kernel<<<NA, 96>>>(cutoffs, idx_j);
        segsum_s_kernel<<<NA, FD>>>();

        // node update: Weff = uW1a + Wemb @ uW1b ; s += silu(silu(s@Weff+b1)@uW2+b2)
        copy_weff_kernel<<<(FD * FD + 255) / 256, 256>>>(uW1);
        gemm_single<64, 128><<<2, 256>>>(Wemb, 128, uW1 + 128 * 128, 128, weff, 128,
                                         128, 128, 0, 0, 0, 0, 0, 0, 0, FLAG_RES);
        gemm_single<64, 128><<<gridN, 256>>>(s, FD, weff, 128, hu, 128, NA, FD,
                                             ub1, 0, 0, 0, 0, 0, 0, FLAG_SILU);
        gemm_single<64, 128><<<gridN, 256>>>(hu, FD, uW2, 128, s, 128, NA, FD,
                                             ub2, 0, 0, 0, 0, 0, 0, FLAG_SILU | FLAG_RES);
    }

    int total = NA * FD + NA * 3 * MD;
    copy_out_kernel<<<(total + 255) / 256, 256>>>(out);
}

// round 17
// speedup vs baseline: 1.1727x; 1.0256x over previous
#include <cuda_runtime.h>
#include <cuda_fp16.h>
#include <cstdint>
#include <cstddef>

#define NA 20000
#define PE 320000
#define FD 128
#define RD 64
#define MD 32

enum { FLAG_SILU = 1, FLAG_RES = 2, FLAG_CUT = 4, FLAG_TF32 = 8, FLAG_F16 = 16 };

#define ASCL_DOWN (1.0f / 8192.0f)   // a-feature scale 2^-13
#define ASCL_UP   8192.0f
#define HSCL_UP   128.0f             // hidden scale 2^7 (block-1 W2 pre-scale)

// ---------------- scratch (device globals; no runtime alloc) ----------------
__device__ float g_u[PE * 3];
__device__ float g_s[NA * FD];
__device__ float g_vA[NA * 3 * MD];
__device__ float g_vB[NA * 3 * MD];
__device__ int   g_start[NA + 1];
__device__ float g_gbuf[(size_t)PE * 64];
__device__ float g_m[(size_t)PE * FD];
__device__ float g_Pei[NA * MD];
__device__ float g_Pej[NA * MD];
__device__ float g_Peqi[NA * FD];
__device__ float g_Peqj[NA * FD];
__device__ float g_Pinvi[NA * FD];
__device__ float g_Pinvj[NA * FD];
__device__ float g_weff[FD * FD];
__device__ float g_hu[NA * FD];
// block-0 fp16 data (bounded range)
__device__ __align__(16) __half g_xh[(size_t)PE * 32];
__device__ __align__(16) __half g_tew1[128 * 32];
__device__ __align__(16) __half g_tew2[64 * 128];
__device__ __align__(16) __half g_tiw1[128 * 32];
__device__ __align__(16) __half g_tiw2[128 * 128];
// block-1 fp16 data (a-cols x 2^-13; W1 rows>=32 x 2^13; W2 x 2^7)
__device__ __align__(16) __half g_xh1[(size_t)PE * 192];
__device__ __align__(16) __half g_tew1b[128 * 192];
__device__ __align__(16) __half g_tew2b[64 * 128];
__device__ __align__(16) __half g_tiw1b[128 * 192];
__device__ __align__(16) __half g_tiw2b[128 * 128];

__device__ __forceinline__ float silu_f(float x) { return x / (1.0f + expf(-x)); }

__device__ __forceinline__ float f2tf(float f) {
    uint32_t u;
    asm("cvt.rna.tf32.f32 %0, %1;" : "=r"(u) : "f"(f));
    return __uint_as_float(u);
}

union U32H2 { uint32_t u; __half2 h; };
__device__ __forceinline__ uint32_t hld(const __half* p) {
    U32H2 x; x.h = *(const __half2*)p; return x.u;
}

__device__ __forceinline__ void mma_tf32(float c[4], const uint32_t a[4], const uint32_t b[2]) {
    asm volatile(
        "mma.sync.aligned.m16n8k8.row.col.f32.tf32.tf32.f32 "
        "{%0,%1,%2,%3}, {%4,%5,%6,%7}, {%8,%9}, {%0,%1,%2,%3};\n"
        : "+f"(c[0]), "+f"(c[1]), "+f"(c[2]), "+f"(c[3])
        : "r"(a[0]), "r"(a[1]), "r"(a[2]), "r"(a[3]), "r"(b[0]), "r"(b[1]));
}

__device__ __forceinline__ void mma_f16(float c[4], const uint32_t a[4], const uint32_t b[2]) {
    asm volatile(
        "mma.sync.aligned.m16n8k16.row.col.f32.f16.f16.f32 "
        "{%0,%1,%2,%3}, {%4,%5,%6,%7}, {%8,%9}, {%0,%1,%2,%3};\n"
        : "+f"(c[0]), "+f"(c[1]), "+f"(c[2]), "+f"(c[3])
        : "r"(a[0]), "r"(a[1]), "r"(a[2]), "r"(a[3]), "r"(b[0]), "r"(b[1]));
}

__device__ __forceinline__ uint32_t smem_u32(const void* p) {
    uint32_t a;
    asm("{ .reg .u64 t; cvta.to.shared.u64 t, %1; cvt.u32.u64 %0, t; }" : "=r"(a) : "l"(p));
    return a;
}

#define CPA16(dst, src) \
    asm volatile("cp.async.cg.shared.global [%0], [%1], 16;" :: "r"(dst), "l"(src))
#define CPA_COMMIT() asm volatile("cp.async.commit_group;" ::: "memory")
#define CPA_WAIT0()  asm volatile("cp.async.wait_group 0;" ::: "memory")

// ================= pipelined tf32 legacy GEMM (round 8 + F16 epilogue) =======
template <int BM, int BN>
__device__ __forceinline__ void gemm_body(
    const float* __restrict__ A, int lda,
    const float* __restrict__ W, int ldw,
    float* __restrict__ C, int ldc,
    int Mrows, int K,
    const float* __restrict__ bias,
    const float* __restrict__ Pi,
    const float* __restrict__ Pj, int ldp,
    const int* __restrict__ ii,
    const int* __restrict__ jj,
    const float* __restrict__ cut,
    int flags)
{
    constexpr int BK = 16;
    constexpr int MW = (BN >= 128) ? 2 : (BN == 64 ? 4 : (BM >= 128 ? 8 : 4));
    constexpr int NW = 8 / MW;
    constexpr int WM = BM / MW, WN = BN / NW;
    constexpr int MT = WM / 16, NT = WN / 8;
    constexpr int SAS = BM + 8, SBS = BN + 8;
    constexpr int A4 = (BM * 4) / 256;
    constexpr int B4N = BN / 4;
    constexpr int B4 = (BN * 4 + 255) / 256;
    constexpr bool BG = ((BN * 4) % 256) != 0;

    __shared__ float sA[2][BK][SAS];
    __shared__ float sB[2][BK][SBS];

    const int tid  = threadIdx.x;
    const int lane = tid & 31;
    const int wid  = tid >> 5;
    const int wm   = wid % MW;
    const int wn   = wid / MW;
    const int brow = blockIdx.x * BM;
    const int ar = lane >> 2, ac = lane & 3;

    float acc[MT][NT][4];
#pragma unroll
    for (int i = 0; i < MT; i++)
#pragma unroll
        for (int j = 0; j < NT; j++)
#pragma unroll
            for (int r = 0; r < 4; r++) acc[i][j][r] = 0.0f;

    float4 ra[A4], rb[B4];
    const int nIter = K / BK;

#pragma unroll
    for (int i = 0; i < A4; i++) {
        int q = tid + i * 256, m = q >> 2, kq = q & 3;
        int row = brow + m;
        ra[i] = (row < Mrows) ? *(const float4*)&A[(size_t)row * lda + 4 * kq]
                              : make_float4(0.f, 0.f, 0.f, 0.f);
    }
#pragma unroll
    for (int i = 0; i < B4; i++) {
        int q = tid + i * 256;
        if (!BG || q < BN * 4) {
            int kk = q / B4N, c4 = (q % B4N) * 4;
            rb[i] = *(const float4*)&W[(size_t)kk * ldw + c4];
        }
    }

    for (int it = 0; it < nIter; ++it) {
        int buf = it & 1;
#pragma unroll
        for (int i = 0; i < A4; i++) {
            int q = tid + i * 256, m = q >> 2, kq = q & 3;
            sA[buf][4 * kq + 0][m] = f2tf(ra[i].x);
            sA[buf][4 * kq + 1][m] = f2tf(ra[i].y);
            sA[buf][4 * kq + 2][m] = f2tf(ra[i].z);
            sA[buf][4 * kq + 3][m] = f2tf(ra[i].w);
        }
#pragma unroll
        for (int i = 0; i < B4; i++) {
            int q = tid + i * 256;
            if (!BG || q < BN * 4) {
                int kk = q / B4N, c4 = (q % B4N) * 4;
                float4 v;
                v.x = f2tf(rb[i].x); v.y = f2tf(rb[i].y);
                v.z = f2tf(rb[i].z); v.w = f2tf(rb[i].w);
                *(float4*)&sB[buf][kk][c4] = v;
            }
        }
        __syncthreads();
        if (it + 1 < nIter) {
            int k0 = (it + 1) * BK;
#pragma unroll
            for (int i = 0; i < A4; i++) {
                int q = tid + i * 256, m = q >> 2, kq = q & 3;
                int row = brow + m;
                ra[i] = (row < Mrows) ? *(const float4*)&A[(size_t)row * lda + k0 + 4 * kq]
                                      : make_float4(0.f, 0.f, 0.f, 0.f);
            }
#pragma unroll
            for (int i = 0; i < B4; i++) {
                int q = tid + i * 256;
                if (!BG || q < BN * 4) {
                    int kk = q / B4N, c4 = (q % B4N) * 4;
                    rb[i] = *(const float4*)&W[(size_t)(k0 + kk) * ldw + c4];
                }
            }
        }
#pragma unroll
        for (int kk = 0; kk < BK; kk += 8) {
            uint32_t afr[MT][4], bfr[NT][2];
#pragma unroll
            for (int mt = 0; mt < MT; mt++) {
                int bm = wm * WM + mt * 16;
                afr[mt][0] = __float_as_uint(sA[buf][kk + ac][bm + ar]);
                afr[mt][1] = __float_as_uint(sA[buf][kk + ac][bm + ar + 8]);
                afr[mt][2] = __float_as_uint(sA[buf][kk + ac + 4][bm + ar]);
                afr[mt][3] = __float_as_uint(sA[buf][kk + ac + 4][bm + ar + 8]);
            }
#pragma unroll
            for (int nt = 0; nt < NT; nt++) {
                int bn = wn * WN + nt * 8;
                bfr[nt][0] = __float_as_uint(sB[buf][kk + ac][bn + ar]);
                bfr[nt][1] = __float_as_uint(sB[buf][kk + ac + 4][bn + ar]);
            }
#pragma unroll
            for (int mt = 0; mt < MT; mt++)
#pragma unroll
                for (int nt = 0; nt < NT; nt++)
                    mma_tf32(acc[mt][nt], afr[mt], bfr[nt]);
        }
    }

#pragma unroll
    for (int mt = 0; mt < MT; mt++) {
#pragma unroll
        for (int h = 0; h < 2; h++) {
            int r = wm * WM + mt * 16 + ar + 8 * h;
            int row = brow + r;
            if (row >= Mrows) continue;
            int pii = 0, pjj = 0;
            if (Pi) { pii = ii[row]; pjj = jj[row]; }
            float cv = (flags & FLAG_CUT) ? cut[row] : 1.0f;
#pragma unroll
            for (int nt = 0; nt < NT; nt++) {
                int col = wn * WN + nt * 8 + ac * 2;
#pragma unroll
                for (int e = 0; e < 2; e++) {
                    int c = col + e;
                    float v = acc[mt][nt][2 * h + e];
                    if (bias) v += bias[c];
                    if (Pi) v += Pi[(size_t)pii * ldp + c] + Pj[(size_t)pjj * ldp + c];
                    if (flags & FLAG_SILU) v = silu_f(v);
                    v *= cv;
                    if (flags & FLAG_F16) {
                        ((__half*)C)[(size_t)row * ldc + c] = __float2half(v);
                    } else {
                        if (flags & FLAG_TF32) v = f2tf(v);
                        float* cp = &C[(size_t)row * ldc + c];
                        if (flags & FLAG_RES) *cp += v; else *cp = v;
                    }
                }
            }
        }
    }
}

template <int BM, int BN>
__global__ void __launch_bounds__(256) gemm_single(
    const float* __restrict__ A, int lda, const float* __restrict__ W, int ldw,
    float* __restrict__ C, int ldc, int Mrows, int K,
    const float* __restrict__ bias, const float* __restrict__ Pi,
    const float* __restrict__ Pj, int ldp, const int* __restrict__ ii,
    const int* __restrict__ jj, const float* __restrict__ cut, int flags)
{
    gemm_body<BM, BN>(A, lda, W, ldw, C, ldc, Mrows, K, bias, Pi, Pj, ldp, ii, jj, cut, flags);
}

struct PB4 { const float* W[4]; float* C[4]; };

template <int BM, int BN>
__global__ void __launch_bounds__(256) gemm_batch(
    const float* __restrict__ A, int lda, PB4 p, int ldw, int ldc, int Mrows, int K)
{
    gemm_body<BM, BN>(A, lda, p.W[blockIdx.y], ldw, p.C[blockIdx.y], ldc,
                      Mrows, K, 0, 0, 0, 0, 0, 0, 0, 0);
}

// ================= unified fp16 fused 2-layer edge MLP (BK=64) ===============
// X [PE][K1] fp16; W1T [128][K1] fp16; W2T [N2][128] fp16 (x 2^HSHIFT).
// Chunks of 64 K at stride 72 halves (conflict-free: 36*ar+ac covers 32 banks).
// smem: sA 2x[128][72]h (36864B), sB 2x[128][72]h (36864B), sHb [128][136]h.
#define SMEM_H (36864 + 36864 + 34816)

template <int K1, int N2, int FLAGS2, int HSHIFT>
__global__ void __launch_bounds__(256, 2) mlp_h(
    const __half* __restrict__ X, int ldx,
    const __half* __restrict__ W1T,
    const float* __restrict__ b1v,
    const float* __restrict__ Pi, const float* __restrict__ Pj,
    const int* __restrict__ ii, const int* __restrict__ jj,
    const __half* __restrict__ W2T,
    const float* __restrict__ b2v,
    const float* __restrict__ cut,
    float* __restrict__ C, int ldc)
{
    extern __shared__ char dsmc[];
    __half* sA0 = (__half*)dsmc;                    // 2 x 9216 halves, stride 72
    __half* sB0 = (__half*)(dsmc + 36864);          // 2 x 9216 halves, stride 72
    __half* sHb = (__half*)(dsmc + 73728);          // [128][136] halves

    const int tid = threadIdx.x, lane = tid & 31, wid = tid >> 5;
    const int brow = blockIdx.x * 128;
    const int ar = lane >> 2, ac = lane & 3;
    const uint32_t sAu = smem_u32(sA0);
    const uint32_t sBu = smem_u32(sB0);
    constexpr float HS = 1.0f / (float)(1 << HSHIFT);

    const int wm = wid & 1, wn = wid >> 1;

    // ---- phase 1: hidden = silu(X@W1 + Pi+Pj+b1) ----
    {
        float acc[4][4][4];
#pragma unroll
        for (int i = 0; i < 4; i++)
#pragma unroll
            for (int j = 0; j < 4; j++)
#pragma unroll
                for (int r = 0; r < 4; r++) acc[i][j][r] = 0.0f;

        if (K1 == 32) {
            // single chunk of 32, plain staging (validated round 14; stride 40)
            uint4 ra[2], rb[2];
#pragma unroll
            for (int i = 0; i < 2; i++) {
                int q = tid + i * 256, row = q >> 2, seg = q & 3;
                ra[i] = *(const uint4*)&X[(size_t)(brow + row) * ldx + seg * 8];
            }
#pragma unroll
            for (int i = 0; i < 2; i++) {
                int q = tid + i * 256, n = q >> 2, seg = q & 3;
                rb[i] = *(const uint4*)&W1T[(size_t)n * K1 + seg * 8];
            }
#pragma unroll
            for (int i = 0; i < 2; i++) {
                int q = tid + i * 256, row = q >> 2, seg = q & 3;
                *(uint4*)&sA0[row * 40 + seg * 8] = ra[i];
            }
#pragma unroll
            for (int i = 0; i < 2; i++) {
                int q = tid + i * 256, n = q >> 2, seg = q & 3;
                *(uint4*)&sB0[n * 40 + seg * 8] = rb[i];
            }
            __syncthreads();
#pragma unroll
            for (int kk = 0; kk < 32; kk += 16) {
                uint32_t afr[4][4], bfr[4][2];
#pragma unroll
                for (int mt = 0; mt < 4; mt++) {
                    int bm = wm * 64 + mt * 16;
                    afr[mt][0] = hld(&sA0[(bm + ar) * 40 + kk + ac * 2]);
                    afr[mt][1] = hld(&sA0[(bm + ar + 8) * 40 + kk + ac * 2]);
                    afr[mt][2] = hld(&sA0[(bm + ar) * 40 + kk + ac * 2 + 8]);
                    afr[mt][3] = hld(&sA0[(bm + ar + 8) * 40 + kk + ac * 2 + 8]);
                }
#pragma unroll
                for (int nt = 0; nt < 4; nt++) {
                    int bn = wn * 32 + nt * 8;
                    bfr[nt][0] = hld(&sB0[(bn + ar) * 40 + kk + ac * 2]);
                    bfr[nt][1] = hld(&sB0[(bn + ar) * 40 + kk + ac * 2 + 8]);
                }
#pragma unroll
                for (int mt = 0; mt < 4; mt++)
#pragma unroll
                    for (int nt = 0; nt < 4; nt++)
                        mma_f16(acc[mt][nt], afr[mt], bfr[nt]);
            }
        } else {
            // multi-chunk cp.async pipeline, BK=64 (stride 72)
#pragma unroll
            for (int i = 0; i < 4; i++) {
                int q = tid + i * 256, row = q >> 3, seg = q & 7;
                CPA16(sAu + (uint32_t)(row * 144 + seg * 16),
                      &X[(size_t)(brow + row) * ldx + seg * 8]);
            }
#pragma unroll
            for (int i = 0; i < 4; i++) {
                int q = tid + i * 256, n = q >> 3, seg = q & 7;
                CPA16(sBu + (uint32_t)(n * 144 + seg * 16),
                      &W1T[(size_t)n * K1 + seg * 8]);
            }
            CPA_COMMIT();

            constexpr int nIt1 = K1 / 64;
            for (int it = 0; it < nIt1; ++it) {
                CPA_WAIT0();
                __syncthreads();
                if (it + 1 < nIt1) {
                    int k0 = (it + 1) * 64;
                    uint32_t nb = (uint32_t)((it + 1) & 1);
#pragma unroll
                    for (int i = 0; i < 4; i++) {
                        int q = tid + i * 256, row = q >> 3, seg = q & 7;
                        CPA16(sAu + nb * 18432u + (uint32_t)(row * 144 + seg * 16),
                              &X[(size_t)(brow + row) * ldx + k0 + seg * 8]);
                    }
#pragma unroll
                    for (int i = 0; i < 4; i++) {
                        int q = tid + i * 256, n = q >> 3, seg = q & 7;
                        CPA16(sBu + nb * 18432u + (uint32_t)(n * 144 + seg * 16),
                              &W1T[(size_t)n * K1 + k0 + seg * 8]);
                    }
                    CPA_COMMIT();
                }
                const __half* cA = sA0 + (it & 1) * 9216;
                const __half* cB = sB0 + (it & 1) * 9216;
#pragma unroll
                for (int kk = 0; kk < 64; kk += 16) {
                    uint32_t afr[4][4], bfr[4][2];
#pragma unroll
                    for (int mt = 0; mt < 4; mt++) {
                        int bm = wm * 64 + mt * 16;
                        afr[mt][0] = hld(&cA[(bm + ar) * 72 + kk + ac * 2]);
                        afr[mt][1] = hld(&cA[(bm + ar + 8) * 72 + kk + ac * 2]);
                        afr[mt][2] = hld(&cA[(bm + ar) * 72 + kk + ac * 2 + 8]);
                        afr[mt][3] = hld(&cA[(bm + ar + 8) * 72 + kk + ac * 2 + 8]);
                    }
#pragma unroll
                    for (int nt = 0; nt < 4; nt++) {
                        int bn = wn * 32 + nt * 8;
                        bfr[nt][0] = hld(&cB[(bn + ar) * 72 + kk + ac * 2]);
                        bfr[nt][1] = hld(&cB[(bn + ar) * 72 + kk + ac * 2 + 8]);
                    }
#pragma unroll
                    for (int mt = 0; mt < 4; mt++)
#pragma unroll
                        for (int nt = 0; nt < 4; nt++)
                            mma_f16(acc[mt][nt], afr[mt], bfr[nt]);
                }
            }
        }

        // epilogue 1: sHb = half(silu(acc + Pi[ii] + Pj[jj] + b1) * HS)
#pragma unroll
        for (int mt = 0; mt < 4; mt++)
#pragma unroll
            for (int h = 0; h < 2; h++) {
                int r = wm * 64 + mt * 16 + ar + 8 * h;
                int row = brow + r;
                int pii = ii[row], pjj = jj[row];
                const float* pi = Pi + (size_t)pii * 128;
                const float* pj = Pj + (size_t)pjj * 128;
#pragma unroll
                for (int nt = 0; nt < 4; nt++) {
                    int c = wn * 32 + nt * 8 + ac * 2;
                    float2 a = *(const float2*)&pi[c];
                    float2 b = *(const float2*)&pj[c];
                    float2 bb = *(const float2*)&b1v[c];
                    float v0 = silu_f(acc[mt][nt][2 * h + 0] + a.x + b.x + bb.x) * HS;
                    float v1 = silu_f(acc[mt][nt][2 * h + 1] + a.y + b.y + bb.y) * HS;
                    *(__half2*)&sHb[r * 136 + c] = __floats2half2_rn(v0, v1);
                }
            }
    }
    __syncthreads();

    // ---- phase 2: out = epi2(hidden @ W2), K=128, 2 chunks of 64 ----
    {
        constexpr int MW2 = (N2 == 128) ? 2 : 4;
        constexpr int WM2 = 128 / MW2;
        constexpr int WN2 = 32;
        constexpr int MT2 = WM2 / 16;
        constexpr int NT2 = 4;
        constexpr int NCH = N2 / 32;     // 16B chunks per thread: 4 or 2
        const int wm2 = wid % MW2, wn2 = wid / MW2;

#pragma unroll
        for (int i = 0; i < NCH; i++) {
            int q = tid + i * 256, n = q >> 3, seg = q & 7;
            CPA16(sBu + (uint32_t)(n * 144 + seg * 16),
                  &W2T[(size_t)n * 128 + seg * 8]);
        }
        CPA_COMMIT();

        float acc2[MT2][NT2][4];
#pragma unroll
        for (int i = 0; i < MT2; i++)
#pragma unroll
            for (int j = 0; j < NT2; j++)
#pragma unroll
                for (int r = 0; r < 4; r++) acc2[i][j][r] = 0.0f;

        for (int it = 0; it < 2; ++it) {
            CPA_WAIT0();
            __syncthreads();
            if (it < 1) {
                int k0 = 64;
#pragma unroll
                for (int i = 0; i < NCH; i++) {
                    int q = tid + i * 256, n = q >> 3, seg = q & 7;
                    CPA16(sBu + 18432u + (uint32_t)(n * 144 + seg * 16),
                          &W2T[(size_t)n * 128 + k0 + seg * 8]);
                }
                CPA_COMMIT();
            }
            const __half* cB = sB0 + (it & 1) * 9216;
#pragma unroll
            for (int kk = 0; kk < 64; kk += 16) {
                int k = it * 64 + kk;
                uint32_t afr[MT2][4], bfr[NT2][2];
#pragma unroll
                for (int mt = 0; mt < MT2; mt++) {
                    int bm = wm2 * WM2 + mt * 16;
                    afr[mt][0] = hld(&sHb[(bm + ar) * 136 + k + ac * 2]);
                    afr[mt][1] = hld(&sHb[(bm + ar + 8) * 136 + k + ac * 2]);
                    afr[mt][2] = hld(&sHb[(bm + ar) * 136 + k + ac * 2 + 8]);
                    afr[mt][3] = hld(&sHb[(bm + ar + 8) * 136 + k + ac * 2 + 8]);
                }
#pragma unroll
                for (int nt = 0; nt < NT2; nt++) {
                    int bn = wn2 * WN2 + nt * 8;
                    bfr[nt][0] = hld(&cB[(bn + ar) * 72 + kk + ac * 2]);
                    bfr[nt][1] = hld(&cB[(bn + ar) * 72 + kk + ac * 2 + 8]);
                }
#pragma unroll
                for (int mt = 0; mt < MT2; mt++)
#pragma unroll
                    for (int nt = 0; nt < NT2; nt++)
                        mma_f16(acc2[mt][nt], afr[mt], bfr[nt]);
            }
        }
#pragma unroll
        for (int mt = 0; mt < MT2; mt++)
#pragma unroll
            for (int h = 0; h < 2; h++) {
                int r = wm2 * WM2 + mt * 16 + ar + 8 * h;
                int row = brow + r;
                float cv = (FLAGS2 & FLAG_CUT) ? cut[row] : 1.0f;
#pragma unroll
                for (int nt = 0; nt < NT2; nt++)
#pragma unroll
                    for (int e = 0; e < 2; e++) {
                        int c = wn2 * WN2 + nt * 8 + ac * 2 + e;
                        float v = acc2[mt][nt][2 * h + e];
                        if (b2v) v += b2v[c];
                        if (FLAGS2 & FLAG_SILU) v = silu_f(v);
                        v *= cv;
                        C[(size_t)row * ldc + c] = v;
                    }
            }
    }
}

// ---------------- small kernels ----------------
__global__ void tr_half_kernel(const float* __restrict__ W, __half* __restrict__ WT,
                               int K, int N) {
    int t = blockIdx.x * blockDim.x + threadIdx.x;
    if (t >= K * N) return;
    int k = t / N, n = t % N;
    WT[(size_t)n * K + k] = __float2half(W[t]);
}

// block-1 W1: transpose + fp16, rows k>=32 scaled by 2^13
__global__ void tr_half192s_kernel(const float* __restrict__ W, __half* __restrict__ WT) {
    int t = blockIdx.x * blockDim.x + threadIdx.x;
    if (t >= 192 * 128) return;
    int k = t / 128, n = t % 128;
    float scl = (k >= 32) ? ASCL_UP : 1.0f;
    WT[(size_t)n * 192 + k] = __float2half(W[t] * scl);
}

// block-1 W2: transpose + fp16, scaled by 2^7 (hidden is stored x 2^-7)
__global__ void tr_half_w2s_kernel(const float* __restrict__ W, __half* __restrict__ WT,
                                   int N2) {
    int t = blockIdx.x * blockDim.x + threadIdx.x;
    if (t >= 128 * N2) return;
    int k = t / N2, n = t % N2;
    WT[(size_t)n * 128 + k] = __float2half(W[t] * HSCL_UP);
}

__global__ void copy_s_kernel(const float* __restrict__ features) {
    int t = blockIdx.x * blockDim.x + threadIdx.x;
    if (t < NA * FD) g_s[t] = features[t];
}

__global__ void compute_u_kernel(const float* __restrict__ vectors,
                                 const float* __restrict__ distances) {
    int t = blockIdx.x * blockDim.x + threadIdx.x;
    if (t >= PE * 3) return;
    int p = t / 3;
    g_u[t] = vectors[t] / (distances[p] + 0.001f);
}

__global__ void offsets_kernel(const int* __restrict__ idx_i) {
    int n = blockIdx.x * blockDim.x + threadIdx.x;
    if (n > NA) return;
    int lo = 0, hi = PE;
    while (lo < hi) {
        int mid = (lo + hi) >> 1;
        if (idx_i[mid] < n) lo = mid + 1; else hi = mid;
    }
    g_start[n] = lo;
}

// a-features -> g_xh1 cols 32..191 fp16 scaled 2^-13
__global__ void afeat_h_kernel(const int* __restrict__ idx_i,
                               const int* __restrict__ idx_j) {
    int t = blockIdx.x * blockDim.x + threadIdx.x;
    if (t >= PE * MD) return;
    int p = t / MD, mm = t % MD;
    const float* vi = g_vA + (size_t)idx_i[p] * 96;
    const float* vj = g_vA + (size_t)idx_j[p] * 96;
    float u0 = g_u[p * 3 + 0], u1 = g_u[p * 3 + 1], u2 = g_u[p * 3 + 2];
    float vi0 = vi[mm], vi1 = vi[32 + mm], vi2 = vi[64 + mm];
    float vj0 = vj[mm], vj1 = vj[32 + mm], vj2 = vj[64 + mm];
    __half* x = g_xh1 + (size_t)p * 192 + 32;
    x[mm]       = __float2half((u0 * vi0 + u1 * vi1 + u2 * vi2) * ASCL_DOWN);
    x[32 + mm]  = __float2half((u0 * vj0 + u1 * vj1 + u2 * vj2) * ASCL_DOWN);
    x[64 + mm]  = __float2half((vi0 * vj0 + vi1 * vj1 + vi2 * vj2) * ASCL_DOWN);
    x[96 + mm]  = __float2half((vi0 * vi0 + vi1 * vi1 + vi2 * vi2) * ASCL_DOWN);
    x[128 + mm] = __float2half((vj0 * vj0 + vj1 * vj1 + vj2 * vj2) * ASCL_DOWN);
}

__global__ void segsum_s_kernel() {
    int n = blockIdx.x, f = threadIdx.x;
    int p0 = g_start[n], p1 = g_start[n + 1];
    float acc = 0.0f;
    for (int p = p0; p < p1; p++) acc += g_m[(size_t)p * FD + f];
    g_s[n * FD + f] += acc;
}

__global__ void segsum_v0_kernel(const float* __restrict__ cut) {
    int n = blockIdx.x, t = threadIdx.x;
    int d = t / 32, mm = t % 32;
    int p0 = g_start[n], p1 = g_start[n + 1];
    float acc = 0.0f;
    for (int p = p0; p < p1; p++)
        acc += g_gbuf[(size_t)p * 64 + mm] * g_u[p * 3 + d] * cut[p];
    g_vA[n * 96 + t] = acc;
}

__global__ void segsum_v1_kernel(const float* __restrict__ cut,
                                 const int* __restrict__ idx_j) {
    int n = blockIdx.x, t = threadIdx.x;
    int d = t / 32, mm = t % 32;
    int p0 = g_start[n], p1 = g_start[n + 1];
    float acc = 0.0f;
    for (int p = p0; p < p1; p++) {
        float vjv = g_vA[(size_t)idx_j[p] * 96 + t];
        acc += (g_gbuf[(size_t)p * 64 + mm] * g_u[p * 3 + d]
              + g_gbuf[(size_t)p * 64 + 32 + mm] * vjv) * cut[p];
    }
    g_vB[n * 96 + t] = g_vA[n * 96 + t] + acc;
}

__global__ void copy_weff_kernel(const float* __restrict__ uW1) {
    int t = blockIdx.x * blockDim.x + threadIdx.x;
    if (t < FD * FD) g_weff[t] = uW1[t];
}

__global__ void copy_out_kernel(float* __restrict__ out) {
    int t = blockIdx.x * blockDim.x + threadIdx.x;
    const int SN = NA * FD, VN = NA * 3 * MD;
    if (t < SN) out[t] = g_s[t];
    else if (t < SN + VN) out[t] = g_vB[t - SN];
}

// ---------------- host ----------------
extern "C" void kernel_launch(void* const* d_in, const int* in_sizes, int n_in,
                              void* d_out, int out_size)
{
    const float* features  = (const float*)d_in[0];
    const float* distances = (const float*)d_in[1];
    const float* vectors   = (const float*)d_in[2];
    const float* cutoffs   = (const float*)d_in[3];
    const float* rbfs      = (const float*)d_in[4];
    const int*   idx_i     = (const int*)d_in[5];
    const int*   idx_j     = (const int*)d_in[6];
    const float* Wrbf      = (const float*)d_in[7];
    const float* Wemb      = (const float*)d_in[8];
    const float* eq0_W1    = (const float*)d_in[9];
    const float* eq0_b1    = (const float*)d_in[10];
    const float* eq0_W2    = (const float*)d_in[11];
    const float* eq1_W1    = (const float*)d_in[12];
    const float* eq1_b1    = (const float*)d_in[13];
    const float* eq1_W2    = (const float*)d_in[14];
    const float* inv_W1    = (const float*)d_in[15];
    const float* inv_b1    = (const float*)d_in[16];
    const float* inv_W2    = (const float*)d_in[17];
    const float* inv_b2    = (const float*)d_in[18];
    const float* upd_W1    = (const float*)d_in[19];
    const float* upd_b1    = (const float*)d_in[20];
    const float* upd_W2    = (const float*)d_in[21];
    const float* upd_b2    = (const float*)d_in[22];
    float* out = (float*)d_out;

    static bool attr_done = false;
    if (!attr_done) {
        cudaFuncSetAttribute(mlp_h<32, 64, 0, 0>,
                             cudaFuncAttributeMaxDynamicSharedMemorySize, SMEM_H);
        cudaFuncSetAttribute(mlp_h<32, 128, FLAG_SILU | FLAG_CUT, 0>,
                             cudaFuncAttributeMaxDynamicSharedMemorySize, SMEM_H);
        cudaFuncSetAttribute(mlp_h<192, 64, 0, 7>,
                             cudaFuncAttributeMaxDynamicSharedMemorySize, SMEM_H);
        cudaFuncSetAttribute(mlp_h<192, 128, FLAG_SILU | FLAG_CUT, 7>,
                             cudaFuncAttributeMaxDynamicSharedMemorySize, SMEM_H);
        attr_done = true;
    }

    void* tp;
    float *s, *gb, *m, *Pei, *Pej, *Peqi, *Peqj, *Pinvi, *Pinvj;
    float *weff, *hu;
    __half *xh, *xh1, *tew1, *tew2, *tiw1, *tiw2, *tew1b, *tew2b, *tiw1b, *tiw2b;
    cudaGetSymbolAddress(&tp, g_s);      s      = (float*)tp;
    cudaGetSymbolAddress(&tp, g_gbuf);   gb     = (float*)tp;
    cudaGetSymbolAddress(&tp, g_m);      m      = (float*)tp;
    cudaGetSymbolAddress(&tp, g_Pei);    Pei    = (float*)tp;
    cudaGetSymbolAddress(&tp, g_Pej);    Pej    = (float*)tp;
    cudaGetSymbolAddress(&tp, g_Peqi);   Peqi   = (float*)tp;
    cudaGetSymbolAddress(&tp, g_Peqj);   Peqj   = (float*)tp;
    cudaGetSymbolAddress(&tp, g_Pinvi);  Pinvi  = (float*)tp;
    cudaGetSymbolAddress(&tp, g_Pinvj);  Pinvj  = (float*)tp;
    cudaGetSymbolAddress(&tp, g_weff);   weff   = (float*)tp;
    cudaGetSymbolAddress(&tp, g_hu);     hu     = (float*)tp;
    cudaGetSymbolAddress(&tp, g_xh);     xh     = (__half*)tp;
    cudaGetSymbolAddress(&tp, g_xh1);    xh1    = (__half*)tp;
    cudaGetSymbolAddress(&tp, g_tew1);   tew1   = (__half*)tp;
    cudaGetSymbolAddress(&tp, g_tew2);   tew2   = (__half*)tp;
    cudaGetSymbolAddress(&tp, g_tiw1);   tiw1   = (__half*)tp;
    cudaGetSymbolAddress(&tp, g_tiw2);   tiw2   = (__half*)tp;
    cudaGetSymbolAddress(&tp, g_tew1b);  tew1b  = (__half*)tp;
    cudaGetSymbolAddress(&tp, g_tew2b);  tew2b  = (__half*)tp;
    cudaGetSymbolAddress(&tp, g_tiw1b);  tiw1b  = (__half*)tp;
    cudaGetSymbolAddress(&tp, g_tiw2b);  tiw2b  = (__half*)tp;

    copy_s_kernel<<<(NA * FD + 255) / 256, 256>>>(features);
    compute_u_kernel<<<(PE * 3 + 255) / 256, 256>>>(vectors, distances);
    offsets_kernel<<<(NA + 1 + 255) / 256, 256>>>(idx_i);

    const int gridN = (NA + 63) / 64;
    const int gridE = PE / 128;

    for (int b = 0; b < 2; b++) {
        const float* eqW1 = b ? eq1_W1 : eq0_W1;
        const float* eqb1 = b ? eq1_b1 : eq0_b1;
        const float* eqW2 = b ? eq1_W2 : eq0_W2;
        const int eq_si = b ? 192 : 32;
        const int eq_sj = b ? 320 : 160;
        const float* iW1 = inv_W1 + (size_t)b * 448 * 128;
        const float* ib1 = inv_b1 + b * 128;
        const float* iW2 = inv_W2 + (size_t)b * 128 * 128;
        const float* ib2 = inv_b2 + b * 128;
        const float* uW1 = upd_W1 + (size_t)b * 256 * 128;
        const float* ub1 = upd_b1 + b * 128;
        const float* uW2 = upd_W2 + (size_t)b * 128 * 128;
        const float* ub2 = upd_b2 + b * 128;

        // node projections, batched
        {
            PB4 p2; p2.W[0] = Wrbf + 64 * 32; p2.W[1] = Wrbf + 192 * 32;
            p2.C[0] = Pei; p2.C[1] = Pej;
            gemm_batch<64, 32><<<dim3(gridN, 2), 256>>>(s, FD, p2, 32, 32, NA, FD);

            PB4 p4;
            p4.W[0] = eqW1 + (size_t)eq_si * 128;
            p4.W[1] = eqW1 + (size_t)eq_sj * 128;
            p4.W[2] = iW1 + 192 * 128;
            p4.W[3] = iW1 + 320 * 128;
            p4.C[0] = Peqi; p4.C[1] = Peqj; p4.C[2] = Pinvi; p4.C[3] = Pinvj;
            gemm_batch<64, 128><<<dim3(gridN, 4), 256>>>(s, FD, p4, 128, 128, NA, FD);
        }

        if (b == 0) {
            tr_half_kernel<<<(32 * 128 + 255) / 256, 256>>>(eqW1, tew1, 32, 128);
            tr_half_kernel<<<(128 * 64 + 255) / 256, 256>>>(eqW2, tew2, 128, 64);
            tr_half_kernel<<<(32 * 128 + 255) / 256, 256>>>(iW1, tiw1, 32, 128);
            tr_half_kernel<<<(128 * 128 + 255) / 256, 256>>>(iW2, tiw2, 128, 128);
        } else {
            tr_half192s_kernel<<<(192 * 128 + 255) / 256, 256>>>(eqW1, tew1b);
            tr_half192s_kernel<<<(192 * 128 + 255) / 256, 256>>>(iW1, tiw1b);
            tr_half_w2s_kernel<<<(128 * 64 + 255) / 256, 256>>>(eqW2, tew2b, 64);
            tr_half_w2s_kernel<<<(128 * 128 + 255) / 256, 256>>>(iW2, tiw2b, 128);
        }

        // e = rbfs @ Wrbf[0:64] + Pei[i] + Pej[j]  -> fp16 X directly
        if (b == 0)
            gemm_single<128, 32><<<gridE, 256>>>(rbfs, RD, Wrbf, 32, (float*)xh, 32,
                                                 PE, RD, 0, Pei, Pej, 32,
                                                 idx_i, idx_j, 0, FLAG_F16);
        else
            gemm_single<128, 32><<<gridE, 256>>>(rbfs, RD, Wrbf, 32, (float*)xh1, 192,
                                                 PE, RD, 0, Pei, Pej, 32,
                                                 idx_i, idx_j, 0, FLAG_F16);

        if (b == 0) {
            mlp_h<32, 64, 0, 0><<<gridE, 256, SMEM_H>>>(
                xh, 32, tew1, eqb1, Peqi, Peqj, idx_i, idx_j,
                tew2, (const float*)0, (const float*)0, gb, 64);
            mlp_h<32, 128, FLAG_SILU | FLAG_CUT, 0><<<gridE, 256, SMEM_H>>>(
                xh, 32, tiw1, ib1, Pinvi, Pinvj, idx_i, idx_j,
                tiw2, ib2, cutoffs, m, 128);
        } else {
            afeat_h_kernel<<<(PE * MD + 255) / 256, 256>>>(idx_i, idx_j);
            mlp_h<192, 64, 0, 7><<<gridE, 256, SMEM_H>>>(
                xh1, 192, tew1b, eqb1, Peqi, Peqj, idx_i, idx_j,
                tew2b, (const float*)0, (const float*)0, gb, 64);
            mlp_h<192, 128, FLAG_SILU | FLAG_CUT, 7><<<gridE, 256, SMEM_H>>>(
                xh1, 192, tiw1b, ib1, Pinvi, Pinvj, idx_i, idx_j,
                tiw2b, ib2, cutoffs, m, 128);
        }

        if (b == 0) segsum_v0_kernel<<<NA, 96>>>(cutoffs);
        else        segsum_v1_kernel<<<NA, 96>>>(cutoffs, idx_j);
        segsum_s_kernel<<<NA, FD>>>();

        // node update: Weff = uW1a + Wemb @ uW1b ; s += silu(silu(s@Weff+b1)@uW2+b2)
        copy_weff_kernel<<<(FD * FD + 255) / 256, 256>>>(uW1);
        gemm_single<64, 128><<<2, 256>>>(Wemb, 128, uW1 + 128 * 128, 128, weff, 128,
                                         128, 128, 0, 0, 0, 0, 0, 0, 0, FLAG_RES);
        gemm_single<64, 128><<<gridN, 256>>>(s, FD, weff, 128, hu, 128, NA, FD,
                                             ub1, 0, 0, 0, 0, 0, 0, FLAG_SILU);
        gemm_single<64, 128><<<gridN, 256>>>(hu, FD, uW2, 128, s, 128, NA, FD,
                                             ub2, 0, 0, 0, 0, 0, 0, FLAG_SILU | FLAG_RES);
    }

    int total = NA * FD + NA * 3 * MD;
    copy_out_kernel<<<(total + 255) / 256, 256>>>(out);
}